// round 1
// baseline (speedup 1.0000x reference)
#include <cuda_runtime.h>
#include <math.h>

#define D 1024
#define T_SEQ 1024
#define BATCH 4
#define NMEM 16
#define NHEADS 64
#define HD 16
#define ROWS (BATCH*T_SEQ)   // 4096

// ---------------- scratch (device globals; no runtime allocation) ----------------
__device__ float g_h[ROWS*D];            // LN outputs (reused 3x)
__device__ float g_qkv[ROWS*3*D];        // qkv, later reused for Q of cross-attn
__device__ float g_ao[ROWS*D];           // attention outputs / cross-attn ctx
__device__ float g_ffn[ROWS*4*D];        // FFN hidden
__device__ float g_meanh[BATCH*D];
__device__ float g_cat[BATCH*NMEM*2*D];
__device__ float g_catr[BATCH*NMEM*2*D];
__device__ float g_zpre[BATCH*NMEM*D];
__device__ float g_rpre[BATCH*NMEM*D];
__device__ float g_cpre[BATCH*NMEM*D];
__device__ float g_K[BATCH*NMEM*D];
__device__ float g_V[BATCH*NMEM*D];

// ---------------- utility kernels ----------------
__global__ void copy_kernel(const float* __restrict__ src, float* __restrict__ dst, int n4) {
    int i = blockIdx.x*blockDim.x + threadIdx.x;
    if (i < n4) ((float4*)dst)[i] = ((const float4*)src)[i];
}

__global__ __launch_bounds__(256) void ln_kernel(
    const float* __restrict__ x, const float* __restrict__ g,
    const float* __restrict__ b, float* __restrict__ y)
{
    __shared__ float s1[256], s2[256];
    int row = blockIdx.x;
    const float4* xr = (const float4*)(x + (size_t)row*D);
    float4 v = xr[threadIdx.x];
    float sum = v.x+v.y+v.z+v.w;
    float sq  = v.x*v.x + v.y*v.y + v.z*v.z + v.w*v.w;
    s1[threadIdx.x]=sum; s2[threadIdx.x]=sq;
    __syncthreads();
    for (int off=128; off; off>>=1) {
        if (threadIdx.x < off) {
            s1[threadIdx.x]+=s1[threadIdx.x+off];
            s2[threadIdx.x]+=s2[threadIdx.x+off];
        }
        __syncthreads();
    }
    float mean = s1[0]*(1.0f/D);
    float var  = s2[0]*(1.0f/D) - mean*mean;
    float rstd = rsqrtf(var + 1e-5f);
    int c = threadIdx.x*4;
    float4 gg = *(const float4*)(g+c);
    float4 bb = *(const float4*)(b+c);
    float4 o;
    o.x = (v.x-mean)*rstd*gg.x + bb.x;
    o.y = (v.y-mean)*rstd*gg.y + bb.y;
    o.z = (v.z-mean)*rstd*gg.z + bb.z;
    o.w = (v.w-mean)*rstd*gg.w + bb.w;
    ((float4*)(y + (size_t)row*D))[threadIdx.x] = o;
}

// ---------------- tiled SGEMM: C(M,N) = A(M,K) @ B(N,K)^T [+bias][act][+res] ----
// ACT: 0=none, 1=exact GELU
template<int ACT, int BIASF, int RESF>
__global__ __launch_bounds__(256) void gemm_nt(
    const float* __restrict__ A, const float* __restrict__ B,
    const float* __restrict__ bias, const float* __restrict__ res,
    float* __restrict__ C, int M, int N, int K)
{
    __shared__ float As[8][128];
    __shared__ float Bs[8][128];
    const int tid = threadIdx.x;
    const int bm = blockIdx.y * 128;
    const int bn = blockIdx.x * 128;
    const int tx = tid & 15;
    const int ty = tid >> 4;
    const int lr = tid >> 1;
    const int lc = (tid & 1) << 2;

    float acc[8][8];
    #pragma unroll
    for (int i=0;i<8;i++)
        #pragma unroll
        for (int j=0;j<8;j++) acc[i][j]=0.f;

    for (int k0=0;k0<K;k0+=8) {
        int ar = bm + lr;
        float4 av = make_float4(0.f,0.f,0.f,0.f);
        if (ar < M) av = *(const float4*)(A + (size_t)ar*K + k0 + lc);
        As[lc+0][lr]=av.x; As[lc+1][lr]=av.y; As[lc+2][lr]=av.z; As[lc+3][lr]=av.w;
        int br = bn + lr;
        float4 bv = make_float4(0.f,0.f,0.f,0.f);
        if (br < N) bv = *(const float4*)(B + (size_t)br*K + k0 + lc);
        Bs[lc+0][lr]=bv.x; Bs[lc+1][lr]=bv.y; Bs[lc+2][lr]=bv.z; Bs[lc+3][lr]=bv.w;
        __syncthreads();
        #pragma unroll
        for (int kk=0;kk<8;kk++) {
            float a[8], bb[8];
            #pragma unroll
            for (int i=0;i<8;i++) a[i]=As[kk][ty*8+i];
            #pragma unroll
            for (int j=0;j<8;j++) bb[j]=Bs[kk][tx*8+j];
            #pragma unroll
            for (int i=0;i<8;i++)
                #pragma unroll
                for (int j=0;j<8;j++)
                    acc[i][j] += a[i]*bb[j];
        }
        __syncthreads();
    }
    #pragma unroll
    for (int i=0;i<8;i++) {
        int row = bm + ty*8 + i;
        if (row >= M) continue;
        #pragma unroll
        for (int j=0;j<8;j++) {
            int col = bn + tx*8 + j;
            float v = acc[i][j];
            if (BIASF) v += bias[col];
            if (ACT==1) v = 0.5f*v*(1.f + erff(v*0.70710678118654752f));
            if (RESF) v += res[(size_t)row*N + col];
            C[(size_t)row*N + col] = v;
        }
    }
}

// ---------------- self-attention: block = (b,h), thread = query row ------------
__global__ __launch_bounds__(1024) void self_attn_kernel(
    const float* __restrict__ qkv, float* __restrict__ ao)
{
    extern __shared__ float smem[];
    float* Ks = smem;                 // [T_SEQ*HD]
    float* Vs = smem + T_SEQ*HD;
    int b = blockIdx.x >> 6;
    int h = blockIdx.x & 63;
    int t = threadIdx.x;
    const float* base = qkv + (size_t)b*T_SEQ*3*D;
    const float4* krow = (const float4*)(base + (size_t)t*3*D + D   + h*HD);
    const float4* vrow = (const float4*)(base + (size_t)t*3*D + 2*D + h*HD);
    #pragma unroll
    for (int i=0;i<4;i++) {
        ((float4*)(Ks + t*HD))[i] = krow[i];
        ((float4*)(Vs + t*HD))[i] = vrow[i];
    }
    float q[16];
    const float4* qrow = (const float4*)(base + (size_t)t*3*D + h*HD);
    #pragma unroll
    for (int i=0;i<4;i++) ((float4*)q)[i] = qrow[i];
    __syncthreads();

    float m = -1e30f, l = 0.f, acc[16];
    #pragma unroll
    for (int i=0;i<16;i++) acc[i]=0.f;

    for (int j=0;j<T_SEQ;j++) {
        const float* kj = Ks + j*HD;
        float s = 0.f;
        #pragma unroll
        for (int i=0;i<16;i++) s += q[i]*kj[i];
        s *= 0.25f;  // HD^-0.5
        const float* vj = Vs + j*HD;
        if (s <= m) {
            float p = __expf(s - m);
            l += p;
            #pragma unroll
            for (int i=0;i<16;i++) acc[i] += p*vj[i];
        } else {
            float corr = __expf(m - s);
            l = l*corr + 1.f;
            #pragma unroll
            for (int i=0;i<16;i++) acc[i] = acc[i]*corr + vj[i];
            m = s;
        }
    }
    float inv = 1.f/l;
    float* orow = ao + ((size_t)b*T_SEQ + t)*D + h*HD;
    #pragma unroll
    for (int i=0;i<16;i++) orow[i] = acc[i]*inv;
}

// ---------------- cross-attention to memory (single head) ---------------------
__global__ __launch_bounds__(256) void cross_attn_kernel(
    const float* __restrict__ Q, const float* __restrict__ Km,
    const float* __restrict__ Vm, float* __restrict__ ctx)
{
    extern __shared__ float smem[];
    float* Ks = smem;             // [NMEM*D]
    float* Vs = smem + NMEM*D;
    int b = blockIdx.x >> 2;
    int chunk = blockIdx.x & 3;
    for (int i=threadIdx.x; i<NMEM*D; i+=256) {
        Ks[i] = Km[(size_t)b*NMEM*D + i];
        Vs[i] = Vm[(size_t)b*NMEM*D + i];
    }
    __syncthreads();
    int t = chunk*256 + threadIdx.x;
    const float4* qrow = (const float4*)(Q + ((size_t)b*T_SEQ + t)*D);
    float s[16];
    #pragma unroll
    for (int mm=0;mm<16;mm++) s[mm]=0.f;
    for (int k4=0;k4<D/4;k4++) {
        float4 qv = qrow[k4];
        #pragma unroll
        for (int mm=0;mm<16;mm++) {
            const float* kr = Ks + mm*D + k4*4;
            s[mm] += qv.x*kr[0] + qv.y*kr[1] + qv.z*kr[2] + qv.w*kr[3];
        }
    }
    float mx = -1e30f;
    #pragma unroll
    for (int mm=0;mm<16;mm++) { s[mm] *= 0.03125f; mx = fmaxf(mx, s[mm]); }
    float sum = 0.f;
    #pragma unroll
    for (int mm=0;mm<16;mm++) { s[mm] = __expf(s[mm]-mx); sum += s[mm]; }
    float inv = 1.f/sum;
    #pragma unroll
    for (int mm=0;mm<16;mm++) s[mm] *= inv;
    float* crow = ctx + ((size_t)b*T_SEQ + t)*D;
    for (int c=0;c<D;c+=4) {
        float4 o = make_float4(0.f,0.f,0.f,0.f);
        #pragma unroll
        for (int mm=0;mm<16;mm++) {
            const float* vr = Vs + mm*D + c;
            o.x += s[mm]*vr[0]; o.y += s[mm]*vr[1];
            o.z += s[mm]*vr[2]; o.w += s[mm]*vr[3];
        }
        *(float4*)(crow + c) = o;
    }
}

// ---------------- memory-update helpers ----------------------------------------
__global__ void mean_kernel(const float* __restrict__ x) {
    int idx = blockIdx.x*blockDim.x + threadIdx.x;   // 0..4095
    int b = idx >> 10, c = idx & 1023;
    const float* p = x + (size_t)b*T_SEQ*D + c;
    float s = 0.f;
    for (int t=0;t<T_SEQ;t++) s += p[(size_t)t*D];
    g_meanh[idx] = s * (1.f/T_SEQ);
}

__global__ void cat_kernel(const float* __restrict__ memory) {
    int idx = blockIdx.x*blockDim.x + threadIdx.x;   // 0..131071
    int b = idx >> 15;
    int rem = idx & 32767;
    int mm = rem >> 11;
    int j = rem & 2047;
    float v;
    if (j < D) v = g_meanh[b*D + j];
    else       v = memory[((size_t)b*NMEM + mm)*D + (j-D)];
    g_cat[idx] = v;
}

__global__ void catr_kernel(const float* __restrict__ memory) {
    int idx = blockIdx.x*blockDim.x + threadIdx.x;
    int b = idx >> 15;
    int rem = idx & 32767;
    int mm = rem >> 11;
    int j = rem & 2047;
    float v;
    if (j < D) v = g_meanh[b*D + j];
    else {
        int mi = ((b*NMEM + mm))*D + (j-D);
        float r = 1.f/(1.f + __expf(-g_rpre[mi]));
        v = r * memory[mi];
    }
    g_catr[idx] = v;
}

__global__ void gates_kernel(const float* __restrict__ memory, float* __restrict__ newmem) {
    int idx = blockIdx.x*blockDim.x + threadIdx.x;   // 0..65535
    float z = 1.f/(1.f + __expf(-g_zpre[idx]));
    float c = tanhf(g_cpre[idx]);
    newmem[idx] = (1.f - z)*memory[idx] + z*c;
}

// ---------------- host launcher -------------------------------------------------
extern "C" void kernel_launch(void* const* d_in, const int* in_sizes, int n_in,
                              void* d_out, int out_size)
{
    const float* x          = (const float*)d_in[0];
    const float* memory     = (const float*)d_in[1];
    const float* ln1_g      = (const float*)d_in[2];
    const float* ln1_b      = (const float*)d_in[3];
    const float* ln2_g      = (const float*)d_in[4];
    const float* ln2_b      = (const float*)d_in[5];
    const float* ln3_g      = (const float*)d_in[6];
    const float* ln3_b      = (const float*)d_in[7];
    const float* in_proj_w  = (const float*)d_in[8];
    const float* in_proj_b  = (const float*)d_in[9];
    const float* attn_out_w = (const float*)d_in[10];
    const float* attn_out_b = (const float*)d_in[11];
    const float* Wz_w       = (const float*)d_in[12];
    const float* Wz_b       = (const float*)d_in[13];
    const float* Wr_w       = (const float*)d_in[14];
    const float* Wr_b       = (const float*)d_in[15];
    const float* Wc_w       = (const float*)d_in[16];
    const float* Wc_b       = (const float*)d_in[17];
    const float* mq_w       = (const float*)d_in[18];
    const float* mk_w       = (const float*)d_in[19];
    const float* mv_w       = (const float*)d_in[20];
    const float* mo_w       = (const float*)d_in[21];
    const float* W1         = (const float*)d_in[22];
    const float* b1         = (const float*)d_in[23];
    const float* W2         = (const float*)d_in[24];
    const float* b2         = (const float*)d_in[25];

    float* xo = (float*)d_out;                     // running residual stream (4096x1024)
    float* newmem = xo + (size_t)ROWS*D;           // new_memory (4x16x1024)

    float *p_h, *p_qkv, *p_ao, *p_ffn, *p_cat, *p_catr, *p_z, *p_r, *p_c, *p_K, *p_V;
    cudaGetSymbolAddress((void**)&p_h,    g_h);
    cudaGetSymbolAddress((void**)&p_qkv,  g_qkv);
    cudaGetSymbolAddress((void**)&p_ao,   g_ao);
    cudaGetSymbolAddress((void**)&p_ffn,  g_ffn);
    cudaGetSymbolAddress((void**)&p_cat,  g_cat);
    cudaGetSymbolAddress((void**)&p_catr, g_catr);
    cudaGetSymbolAddress((void**)&p_z,    g_zpre);
    cudaGetSymbolAddress((void**)&p_r,    g_rpre);
    cudaGetSymbolAddress((void**)&p_c,    g_cpre);
    cudaGetSymbolAddress((void**)&p_K,    g_K);
    cudaGetSymbolAddress((void**)&p_V,    g_V);

    cudaFuncSetAttribute(self_attn_kernel,  cudaFuncAttributeMaxDynamicSharedMemorySize, 131072);
    cudaFuncSetAttribute(cross_attn_kernel, cudaFuncAttributeMaxDynamicSharedMemorySize, 131072);

    // 1. residual stream <- x
    copy_kernel<<<(ROWS*D/4 + 255)/256, 256>>>(x, xo, ROWS*D/4);

    // 2. h = LN1(x)
    ln_kernel<<<ROWS, 256>>>(xo, ln1_g, ln1_b, p_h);

    // 3. qkv = h @ in_proj^T + b
    gemm_nt<0,1,0><<<dim3(3*D/128, ROWS/128), 256>>>(p_h, in_proj_w, in_proj_b, nullptr, p_qkv, ROWS, 3*D, D);

    // 4. self-attention
    self_attn_kernel<<<BATCH*NHEADS, 1024, 131072>>>(p_qkv, p_ao);

    // 5. x += ao @ attn_out^T + b
    gemm_nt<0,1,1><<<dim3(D/128, ROWS/128), 256>>>(p_ao, attn_out_w, attn_out_b, xo, xo, ROWS, D, D);

    // 6-11. gated memory update
    mean_kernel<<<16, 256>>>(xo);
    cat_kernel<<<BATCH*NMEM*2*D/256, 256>>>(memory);
    gemm_nt<0,1,0><<<dim3(D/128, 1), 256>>>(p_cat,  Wz_w, Wz_b, nullptr, p_z, BATCH*NMEM, D, 2*D);
    gemm_nt<0,1,0><<<dim3(D/128, 1), 256>>>(p_cat,  Wr_w, Wr_b, nullptr, p_r, BATCH*NMEM, D, 2*D);
    catr_kernel<<<BATCH*NMEM*2*D/256, 256>>>(memory);
    gemm_nt<0,1,0><<<dim3(D/128, 1), 256>>>(p_catr, Wc_w, Wc_b, nullptr, p_c, BATCH*NMEM, D, 2*D);
    gates_kernel<<<BATCH*NMEM*D/256, 256>>>(memory, newmem);

    // 12-16. cross-attention to memory
    ln_kernel<<<ROWS, 256>>>(xo, ln2_g, ln2_b, p_h);
    gemm_nt<0,0,0><<<dim3(D/128, ROWS/128), 256>>>(p_h, mq_w, nullptr, nullptr, p_qkv, ROWS, D, D);
    gemm_nt<0,0,0><<<dim3(D/128, 1), 256>>>(newmem, mk_w, nullptr, nullptr, p_K, BATCH*NMEM, D, D);
    gemm_nt<0,0,0><<<dim3(D/128, 1), 256>>>(newmem, mv_w, nullptr, nullptr, p_V, BATCH*NMEM, D, D);
    cross_attn_kernel<<<BATCH*4, 256, 131072>>>(p_qkv, p_K, p_V, p_ao);
    gemm_nt<0,0,1><<<dim3(D/128, ROWS/128), 256>>>(p_ao, mo_w, nullptr, xo, xo, ROWS, D, D);

    // 17-19. FFN
    ln_kernel<<<ROWS, 256>>>(xo, ln3_g, ln3_b, p_h);
    gemm_nt<1,1,0><<<dim3(4*D/128, ROWS/128), 256>>>(p_h, W1, b1, nullptr, p_ffn, ROWS, 4*D, D);
    gemm_nt<0,1,1><<<dim3(D/128, ROWS/128), 256>>>(p_ffn, W2, b2, xo, xo, ROWS, D, 4*D);
}

// round 2
// speedup vs baseline: 1.7549x; 1.7549x over previous
#include <cuda_runtime.h>
#include <math.h>
#include <stdint.h>

#define D 1024
#define T_SEQ 1024
#define BATCH 4
#define NMEM 16
#define NHEADS 64
#define HD 16
#define ROWS (BATCH*T_SEQ)   // 4096

// ---------------- scratch (device globals; no runtime allocation) ----------------
__device__ float g_h[ROWS*D];            // LN outputs (tf32-rounded)
__device__ float g_qkv[ROWS*3*D];        // qkv, later reused for Q of cross-attn
__device__ float g_ao[ROWS*D];           // attention outputs / cross-attn ctx (tf32-rounded)
__device__ float g_ffn[ROWS*4*D];        // FFN hidden (tf32-rounded)
__device__ float g_meanh[BATCH*D];
__device__ float g_cat[BATCH*NMEM*2*D];
__device__ float g_catr[BATCH*NMEM*2*D];
__device__ float g_zpre[BATCH*NMEM*D];
__device__ float g_rpre[BATCH*NMEM*D];
__device__ float g_cpre[BATCH*NMEM*D];
__device__ float g_K[BATCH*NMEM*D];
__device__ float g_V[BATCH*NMEM*D];
__device__ float g_w[14*1024*1024];      // tf32-rounded weight copies

// in g_w: in_proj @0 (3M), attn_out @3M (1M), mq @4M (1M), mo @5M (1M), W1 @6M (4M), W2 @10M (4M)
#define OFF_INP   0
#define OFF_AOUT  (3*1024*1024)
#define OFF_MQ    (4*1024*1024)
#define OFF_MO    (5*1024*1024)
#define OFF_W1    (6*1024*1024)
#define OFF_W2    (10*1024*1024)

__device__ __forceinline__ float to_tf32(float v) {
    uint32_t r;
    asm("cvt.rna.tf32.f32 %0, %1;" : "=r"(r) : "f"(v));
    return __uint_as_float(r);
}

// ---------------- utility kernels ----------------
__global__ void copy_kernel(const float* __restrict__ src, float* __restrict__ dst, int n4) {
    int i = blockIdx.x*blockDim.x + threadIdx.x;
    if (i < n4) ((float4*)dst)[i] = ((const float4*)src)[i];
}

__global__ void cvt_tf32_kernel(const float* __restrict__ src, float* __restrict__ dst, int n4) {
    int i = blockIdx.x*blockDim.x + threadIdx.x;
    if (i < n4) {
        float4 v = ((const float4*)src)[i];
        v.x = to_tf32(v.x); v.y = to_tf32(v.y); v.z = to_tf32(v.z); v.w = to_tf32(v.w);
        ((float4*)dst)[i] = v;
    }
}

// LN with tf32-rounded output (output only feeds tf32 GEMMs)
__global__ __launch_bounds__(256) void ln_kernel(
    const float* __restrict__ x, const float* __restrict__ g,
    const float* __restrict__ b, float* __restrict__ y)
{
    __shared__ float s1[256], s2[256];
    int row = blockIdx.x;
    const float4* xr = (const float4*)(x + (size_t)row*D);
    float4 v = xr[threadIdx.x];
    float sum = v.x+v.y+v.z+v.w;
    float sq  = v.x*v.x + v.y*v.y + v.z*v.z + v.w*v.w;
    s1[threadIdx.x]=sum; s2[threadIdx.x]=sq;
    __syncthreads();
    for (int off=128; off; off>>=1) {
        if (threadIdx.x < off) {
            s1[threadIdx.x]+=s1[threadIdx.x+off];
            s2[threadIdx.x]+=s2[threadIdx.x+off];
        }
        __syncthreads();
    }
    float mean = s1[0]*(1.0f/D);
    float var  = s2[0]*(1.0f/D) - mean*mean;
    float rstd = rsqrtf(var + 1e-5f);
    int c = threadIdx.x*4;
    float4 gg = *(const float4*)(g+c);
    float4 bb = *(const float4*)(b+c);
    float4 o;
    o.x = to_tf32((v.x-mean)*rstd*gg.x + bb.x);
    o.y = to_tf32((v.y-mean)*rstd*gg.y + bb.y);
    o.z = to_tf32((v.z-mean)*rstd*gg.z + bb.z);
    o.w = to_tf32((v.w-mean)*rstd*gg.w + bb.w);
    ((float4*)(y + (size_t)row*D))[threadIdx.x] = o;
}

// ---------------- tf32 tensor-core GEMM: C(M,N) = A(M,K) @ B(N,K)^T -------------
// Inputs A,B must be pre-rounded to tf32. BM=BN=128, BK=32, 256 thr, cp.async x2 buf.
// ACT: 0 none, 1 exact GELU. TF32OUT: round the stored output to tf32.
#define SMEM_FLOATS (4*4608)
#define A_OFFS(buf) ((buf)*4608)
#define B_OFFS(buf) (9216 + (buf)*4608)

__device__ __forceinline__ void cp16(uint32_t dst, const void* src) {
    asm volatile("cp.async.cg.shared.global [%0], [%1], 16;" :: "r"(dst), "l"(src));
}

template<int ACT, int BIASF, int RESF, int TF32OUT>
__global__ __launch_bounds__(256, 2) void gemm_tf32(
    const float* __restrict__ A, const float* __restrict__ B,
    const float* __restrict__ bias, const float* __restrict__ res,
    float* __restrict__ C, int M, int N, int K)
{
    extern __shared__ float sm[];
    const int tid = threadIdx.x;
    const int bm = blockIdx.y * 128;
    const int bn = blockIdx.x * 128;
    const int lane = tid & 31;
    const int warp = tid >> 5;
    const int wm64 = (warp & 1) * 64;
    const int wn32 = (warp >> 1) * 32;
    const int qr = lane >> 2;     // 0..7
    const int qc = lane & 3;      // 0..3

    uint32_t smem_u32 = (uint32_t)__cvta_generic_to_shared(sm);

    const int lrow = tid >> 3;          // 0..31
    const int lkq  = (tid & 7) * 4;     // k offset 0,4,...,28

    float acc[4][4][4];
    #pragma unroll
    for (int i=0;i<4;i++)
        #pragma unroll
        for (int j=0;j<4;j++)
            #pragma unroll
            for (int e=0;e<4;e++) acc[i][j][e] = 0.f;

    const int NT = K >> 5;

    // prologue: load tile 0 into buf 0
    {
        const float* Ab = A + (size_t)bm*K;
        const float* Bb = B + (size_t)bn*K;
        #pragma unroll
        for (int rep=0; rep<4; rep++) {
            int row = rep*32 + lrow;
            cp16(smem_u32 + (A_OFFS(0) + row*36 + lkq)*4, Ab + (size_t)row*K + lkq);
            cp16(smem_u32 + (B_OFFS(0) + row*36 + lkq)*4, Bb + (size_t)row*K + lkq);
        }
        asm volatile("cp.async.commit_group;");
    }

    for (int t = 0; t < NT; t++) {
        if (t + 1 < NT) {
            int buf = (t+1) & 1;
            int kb = (t+1) << 5;
            const float* Ab = A + (size_t)bm*K + kb;
            const float* Bb = B + (size_t)bn*K + kb;
            #pragma unroll
            for (int rep=0; rep<4; rep++) {
                int row = rep*32 + lrow;
                cp16(smem_u32 + (A_OFFS(buf) + row*36 + lkq)*4, Ab + (size_t)row*K + lkq);
                cp16(smem_u32 + (B_OFFS(buf) + row*36 + lkq)*4, Bb + (size_t)row*K + lkq);
            }
            asm volatile("cp.async.commit_group;");
            asm volatile("cp.async.wait_group 1;");
        } else {
            asm volatile("cp.async.wait_group 0;");
        }
        __syncthreads();

        const float* sA = sm + A_OFFS(t & 1);
        const float* sB = sm + B_OFFS(t & 1);

        #pragma unroll
        for (int ks = 0; ks < 4; ks++) {
            const int k0 = ks * 8;
            uint32_t a[4][4], b[4][2];
            #pragma unroll
            for (int i=0;i<4;i++) {
                int r = wm64 + i*16 + qr;
                a[i][0] = __float_as_uint(sA[r*36 + k0 + qc]);
                a[i][1] = __float_as_uint(sA[(r+8)*36 + k0 + qc]);
                a[i][2] = __float_as_uint(sA[r*36 + k0 + qc + 4]);
                a[i][3] = __float_as_uint(sA[(r+8)*36 + k0 + qc + 4]);
            }
            #pragma unroll
            for (int j=0;j<4;j++) {
                int n = wn32 + j*8 + qr;
                b[j][0] = __float_as_uint(sB[n*36 + k0 + qc]);
                b[j][1] = __float_as_uint(sB[n*36 + k0 + qc + 4]);
            }
            #pragma unroll
            for (int i=0;i<4;i++)
                #pragma unroll
                for (int j=0;j<4;j++) {
                    asm volatile(
                        "mma.sync.aligned.m16n8k8.row.col.f32.tf32.tf32.f32 "
                        "{%0,%1,%2,%3}, {%4,%5,%6,%7}, {%8,%9}, {%0,%1,%2,%3};"
                        : "+f"(acc[i][j][0]), "+f"(acc[i][j][1]),
                          "+f"(acc[i][j][2]), "+f"(acc[i][j][3])
                        : "r"(a[i][0]), "r"(a[i][1]), "r"(a[i][2]), "r"(a[i][3]),
                          "r"(b[j][0]), "r"(b[j][1]));
                }
        }
        __syncthreads();
    }

    // epilogue
    #pragma unroll
    for (int i=0;i<4;i++) {
        int row0 = bm + wm64 + i*16 + qr;
        #pragma unroll
        for (int j=0;j<4;j++) {
            int col0 = bn + wn32 + j*8 + qc*2;
            float v0 = acc[i][j][0], v1 = acc[i][j][1];
            float v2 = acc[i][j][2], v3 = acc[i][j][3];
            if (BIASF) {
                float b0 = bias[col0], b1 = bias[col0+1];
                v0 += b0; v1 += b1; v2 += b0; v3 += b1;
            }
            if (ACT == 1) {
                v0 = 0.5f*v0*(1.f + erff(v0*0.70710678118654752f));
                v1 = 0.5f*v1*(1.f + erff(v1*0.70710678118654752f));
                v2 = 0.5f*v2*(1.f + erff(v2*0.70710678118654752f));
                v3 = 0.5f*v3*(1.f + erff(v3*0.70710678118654752f));
            }
            if (RESF) {
                v0 += res[(size_t)row0*N + col0];
                v1 += res[(size_t)row0*N + col0 + 1];
                v2 += res[(size_t)(row0+8)*N + col0];
                v3 += res[(size_t)(row0+8)*N + col0 + 1];
            }
            if (TF32OUT) {
                v0 = to_tf32(v0); v1 = to_tf32(v1);
                v2 = to_tf32(v2); v3 = to_tf32(v3);
            }
            *(float2*)(C + (size_t)row0*N + col0)     = make_float2(v0, v1);
            *(float2*)(C + (size_t)(row0+8)*N + col0) = make_float2(v2, v3);
        }
    }
}

// ---------------- exact fp32 tiled SGEMM for the small (M=64) memory GEMMs ------
template<int ACT, int BIASF, int RESF>
__global__ __launch_bounds__(256) void gemm_nt(
    const float* __restrict__ A, const float* __restrict__ B,
    const float* __restrict__ bias, const float* __restrict__ res,
    float* __restrict__ C, int M, int N, int K)
{
    __shared__ float As[8][128];
    __shared__ float Bs[8][128];
    const int tid = threadIdx.x;
    const int bm = blockIdx.y * 128;
    const int bn = blockIdx.x * 128;
    const int tx = tid & 15;
    const int ty = tid >> 4;
    const int lr = tid >> 1;
    const int lc = (tid & 1) << 2;

    float acc[8][8];
    #pragma unroll
    for (int i=0;i<8;i++)
        #pragma unroll
        for (int j=0;j<8;j++) acc[i][j]=0.f;

    for (int k0=0;k0<K;k0+=8) {
        int ar = bm + lr;
        float4 av = make_float4(0.f,0.f,0.f,0.f);
        if (ar < M) av = *(const float4*)(A + (size_t)ar*K + k0 + lc);
        As[lc+0][lr]=av.x; As[lc+1][lr]=av.y; As[lc+2][lr]=av.z; As[lc+3][lr]=av.w;
        int br = bn + lr;
        float4 bv = make_float4(0.f,0.f,0.f,0.f);
        if (br < N) bv = *(const float4*)(B + (size_t)br*K + k0 + lc);
        Bs[lc+0][lr]=bv.x; Bs[lc+1][lr]=bv.y; Bs[lc+2][lr]=bv.z; Bs[lc+3][lr]=bv.w;
        __syncthreads();
        #pragma unroll
        for (int kk=0;kk<8;kk++) {
            float a[8], bb[8];
            #pragma unroll
            for (int i=0;i<8;i++) a[i]=As[kk][ty*8+i];
            #pragma unroll
            for (int j=0;j<8;j++) bb[j]=Bs[kk][tx*8+j];
            #pragma unroll
            for (int i=0;i<8;i++)
                #pragma unroll
                for (int j=0;j<8;j++)
                    acc[i][j] += a[i]*bb[j];
        }
        __syncthreads();
    }
    #pragma unroll
    for (int i=0;i<8;i++) {
        int row = bm + ty*8 + i;
        if (row >= M) continue;
        #pragma unroll
        for (int j=0;j<8;j++) {
            int col = bn + tx*8 + j;
            float v = acc[i][j];
            if (BIASF) v += bias[col];
            if (ACT==1) v = 0.5f*v*(1.f + erff(v*0.70710678118654752f));
            if (RESF) v += res[(size_t)row*N + col];
            C[(size_t)row*N + col] = v;
        }
    }
}

// ---------------- self-attention: block = (b,h), thread = query row ------------
__global__ __launch_bounds__(1024) void self_attn_kernel(
    const float* __restrict__ qkv, float* __restrict__ ao)
{
    extern __shared__ float smem[];
    float* Ks = smem;                 // [T_SEQ*HD]
    float* Vs = smem + T_SEQ*HD;
    int b = blockIdx.x >> 6;
    int h = blockIdx.x & 63;
    int t = threadIdx.x;
    const float* base = qkv + (size_t)b*T_SEQ*3*D;
    const float4* krow = (const float4*)(base + (size_t)t*3*D + D   + h*HD);
    const float4* vrow = (const float4*)(base + (size_t)t*3*D + 2*D + h*HD);
    #pragma unroll
    for (int i=0;i<4;i++) {
        ((float4*)(Ks + t*HD))[i] = krow[i];
        ((float4*)(Vs + t*HD))[i] = vrow[i];
    }
    float q[16];
    const float4* qrow = (const float4*)(base + (size_t)t*3*D + h*HD);
    #pragma unroll
    for (int i=0;i<4;i++) ((float4*)q)[i] = qrow[i];
    __syncthreads();

    float m = -1e30f, l = 0.f, acc[16];
    #pragma unroll
    for (int i=0;i<16;i++) acc[i]=0.f;

    for (int j=0;j<T_SEQ;j++) {
        const float* kj = Ks + j*HD;
        float s = 0.f;
        #pragma unroll
        for (int i=0;i<16;i++) s += q[i]*kj[i];
        s *= 0.25f;  // HD^-0.5
        const float* vj = Vs + j*HD;
        if (s <= m) {
            float p = __expf(s - m);
            l += p;
            #pragma unroll
            for (int i=0;i<16;i++) acc[i] += p*vj[i];
        } else {
            float corr = __expf(m - s);
            l = l*corr + 1.f;
            #pragma unroll
            for (int i=0;i<16;i++) acc[i] = acc[i]*corr + vj[i];
            m = s;
        }
    }
    float inv = 1.f/l;
    float* orow = ao + ((size_t)b*T_SEQ + t)*D + h*HD;
    #pragma unroll
    for (int i=0;i<16;i++) orow[i] = to_tf32(acc[i]*inv);  // rounded: feeds tf32 GEMM
}

// ---------------- cross-attention to memory (single head) ---------------------
__global__ __launch_bounds__(256) void cross_attn_kernel(
    const float* __restrict__ Q, const float* __restrict__ Km,
    const float* __restrict__ Vm, float* __restrict__ ctx)
{
    extern __shared__ float smem[];
    float* Ks = smem;             // [NMEM*D]
    float* Vs = smem + NMEM*D;
    int b = blockIdx.x >> 2;
    int chunk = blockIdx.x & 3;
    for (int i=threadIdx.x; i<NMEM*D; i+=256) {
        Ks[i] = Km[(size_t)b*NMEM*D + i];
        Vs[i] = Vm[(size_t)b*NMEM*D + i];
    }
    __syncthreads();
    int t = chunk*256 + threadIdx.x;
    const float4* qrow = (const float4*)(Q + ((size_t)b*T_SEQ + t)*D);
    float s[16];
    #pragma unroll
    for (int mm=0;mm<16;mm++) s[mm]=0.f;
    for (int k4=0;k4<D/4;k4++) {
        float4 qv = qrow[k4];
        #pragma unroll
        for (int mm=0;mm<16;mm++) {
            const float* kr = Ks + mm*D + k4*4;
            s[mm] += qv.x*kr[0] + qv.y*kr[1] + qv.z*kr[2] + qv.w*kr[3];
        }
    }
    float mx = -1e30f;
    #pragma unroll
    for (int mm=0;mm<16;mm++) { s[mm] *= 0.03125f; mx = fmaxf(mx, s[mm]); }
    float sum = 0.f;
    #pragma unroll
    for (int mm=0;mm<16;mm++) { s[mm] = __expf(s[mm]-mx); sum += s[mm]; }
    float inv = 1.f/sum;
    #pragma unroll
    for (int mm=0;mm<16;mm++) s[mm] *= inv;
    float* crow = ctx + ((size_t)b*T_SEQ + t)*D;
    for (int c=0;c<D;c+=4) {
        float4 o = make_float4(0.f,0.f,0.f,0.f);
        #pragma unroll
        for (int mm=0;mm<16;mm++) {
            const float* vr = Vs + mm*D + c;
            o.x += s[mm]*vr[0]; o.y += s[mm]*vr[1];
            o.z += s[mm]*vr[2]; o.w += s[mm]*vr[3];
        }
        o.x = to_tf32(o.x); o.y = to_tf32(o.y);   // rounded: feeds tf32 GEMM
        o.z = to_tf32(o.z); o.w = to_tf32(o.w);
        *(float4*)(crow + c) = o;
    }
}

// ---------------- memory-update helpers ----------------------------------------
__global__ void mean_kernel(const float* __restrict__ x) {
    int idx = blockIdx.x*blockDim.x + threadIdx.x;   // 0..4095
    int b = idx >> 10, c = idx & 1023;
    const float* p = x + (size_t)b*T_SEQ*D + c;
    float s = 0.f;
    for (int t=0;t<T_SEQ;t++) s += p[(size_t)t*D];
    g_meanh[idx] = s * (1.f/T_SEQ);
}

__global__ void cat_kernel(const float* __restrict__ memory) {
    int idx = blockIdx.x*blockDim.x + threadIdx.x;   // 0..131071
    int b = idx >> 15;
    int rem = idx & 32767;
    int mm = rem >> 11;
    int j = rem & 2047;
    float v;
    if (j < D) v = g_meanh[b*D + j];
    else       v = memory[((size_t)b*NMEM + mm)*D + (j-D)];
    g_cat[idx] = v;
}

__global__ void catr_kernel(const float* __restrict__ memory) {
    int idx = blockIdx.x*blockDim.x + threadIdx.x;
    int b = idx >> 15;
    int rem = idx & 32767;
    int mm = rem >> 11;
    int j = rem & 2047;
    float v;
    if (j < D) v = g_meanh[b*D + j];
    else {
        int mi = ((b*NMEM + mm))*D + (j-D);
        float r = 1.f/(1.f + __expf(-g_rpre[mi]));
        v = r * memory[mi];
    }
    g_catr[idx] = v;
}

__global__ void gates_kernel(const float* __restrict__ memory, float* __restrict__ newmem) {
    int idx = blockIdx.x*blockDim.x + threadIdx.x;   // 0..65535
    float z = 1.f/(1.f + __expf(-g_zpre[idx]));
    float c = tanhf(g_cpre[idx]);
    newmem[idx] = (1.f - z)*memory[idx] + z*c;
}

// ---------------- host launcher -------------------------------------------------
extern "C" void kernel_launch(void* const* d_in, const int* in_sizes, int n_in,
                              void* d_out, int out_size)
{
    const float* x          = (const float*)d_in[0];
    const float* memory     = (const float*)d_in[1];
    const float* ln1_g      = (const float*)d_in[2];
    const float* ln1_b      = (const float*)d_in[3];
    const float* ln2_g      = (const float*)d_in[4];
    const float* ln2_b      = (const float*)d_in[5];
    const float* ln3_g      = (const float*)d_in[6];
    const float* ln3_b      = (const float*)d_in[7];
    const float* in_proj_w  = (const float*)d_in[8];
    const float* in_proj_b  = (const float*)d_in[9];
    const float* attn_out_w = (const float*)d_in[10];
    const float* attn_out_b = (const float*)d_in[11];
    const float* Wz_w       = (const float*)d_in[12];
    const float* Wz_b       = (const float*)d_in[13];
    const float* Wr_w       = (const float*)d_in[14];
    const float* Wr_b       = (const float*)d_in[15];
    const float* Wc_w       = (const float*)d_in[16];
    const float* Wc_b       = (const float*)d_in[17];
    const float* mq_w       = (const float*)d_in[18];
    const float* mk_w       = (const float*)d_in[19];
    const float* mv_w       = (const float*)d_in[20];
    const float* mo_w       = (const float*)d_in[21];
    const float* W1         = (const float*)d_in[22];
    const float* b1         = (const float*)d_in[23];
    const float* W2         = (const float*)d_in[24];
    const float* b2         = (const float*)d_in[25];

    float* xo = (float*)d_out;                     // running residual stream (4096x1024)
    float* newmem = xo + (size_t)ROWS*D;           // new_memory (4x16x1024)

    float *p_h, *p_qkv, *p_ao, *p_ffn, *p_cat, *p_catr, *p_z, *p_r, *p_c, *p_K, *p_V, *p_w;
    cudaGetSymbolAddress((void**)&p_h,    g_h);
    cudaGetSymbolAddress((void**)&p_qkv,  g_qkv);
    cudaGetSymbolAddress((void**)&p_ao,   g_ao);
    cudaGetSymbolAddress((void**)&p_ffn,  g_ffn);
    cudaGetSymbolAddress((void**)&p_cat,  g_cat);
    cudaGetSymbolAddress((void**)&p_catr, g_catr);
    cudaGetSymbolAddress((void**)&p_z,    g_zpre);
    cudaGetSymbolAddress((void**)&p_r,    g_rpre);
    cudaGetSymbolAddress((void**)&p_c,    g_cpre);
    cudaGetSymbolAddress((void**)&p_K,    g_K);
    cudaGetSymbolAddress((void**)&p_V,    g_V);
    cudaGetSymbolAddress((void**)&p_w,    g_w);

    cudaFuncSetAttribute(self_attn_kernel,  cudaFuncAttributeMaxDynamicSharedMemorySize, 131072);
    cudaFuncSetAttribute(cross_attn_kernel, cudaFuncAttributeMaxDynamicSharedMemorySize, 131072);
    const int GSM = SMEM_FLOATS * 4;  // 73728 bytes
    cudaFuncSetAttribute(gemm_tf32<0,1,0,0>, cudaFuncAttributeMaxDynamicSharedMemorySize, GSM);
    cudaFuncSetAttribute(gemm_tf32<0,1,1,0>, cudaFuncAttributeMaxDynamicSharedMemorySize, GSM);
    cudaFuncSetAttribute(gemm_tf32<0,0,0,0>, cudaFuncAttributeMaxDynamicSharedMemorySize, GSM);
    cudaFuncSetAttribute(gemm_tf32<0,0,1,0>, cudaFuncAttributeMaxDynamicSharedMemorySize, GSM);
    cudaFuncSetAttribute(gemm_tf32<1,1,0,1>, cudaFuncAttributeMaxDynamicSharedMemorySize, GSM);

    // 0. convert weights to tf32 copies
    cvt_tf32_kernel<<<(3*1024*1024/4 + 255)/256, 256>>>(in_proj_w,  p_w + OFF_INP,  3*1024*1024/4);
    cvt_tf32_kernel<<<(1024*1024/4 + 255)/256, 256>>>(attn_out_w,   p_w + OFF_AOUT, 1024*1024/4);
    cvt_tf32_kernel<<<(1024*1024/4 + 255)/256, 256>>>(mq_w,         p_w + OFF_MQ,   1024*1024/4);
    cvt_tf32_kernel<<<(1024*1024/4 + 255)/256, 256>>>(mo_w,         p_w + OFF_MO,   1024*1024/4);
    cvt_tf32_kernel<<<(4*1024*1024/4 + 255)/256, 256>>>(W1,         p_w + OFF_W1,   4*1024*1024/4);
    cvt_tf32_kernel<<<(4*1024*1024/4 + 255)/256, 256>>>(W2,         p_w + OFF_W2,   4*1024*1024/4);

    // 1. residual stream <- x
    copy_kernel<<<(ROWS*D/4 + 255)/256, 256>>>(x, xo, ROWS*D/4);

    // 2. h = LN1(x)  (tf32-rounded output)
    ln_kernel<<<ROWS, 256>>>(xo, ln1_g, ln1_b, p_h);

    // 3. qkv = h @ in_proj^T + b
    gemm_tf32<0,1,0,0><<<dim3(3*D/128, ROWS/128), 256, GSM>>>(p_h, p_w + OFF_INP, in_proj_b, nullptr, p_qkv, ROWS, 3*D, D);

    // 4. self-attention
    self_attn_kernel<<<BATCH*NHEADS, 1024, 131072>>>(p_qkv, p_ao);

    // 5. x += ao @ attn_out^T + b
    gemm_tf32<0,1,1,0><<<dim3(D/128, ROWS/128), 256, GSM>>>(p_ao, p_w + OFF_AOUT, attn_out_b, xo, xo, ROWS, D, D);

    // 6-11. gated memory update (exact fp32 path)
    mean_kernel<<<16, 256>>>(xo);
    cat_kernel<<<BATCH*NMEM*2*D/256, 256>>>(memory);
    gemm_nt<0,1,0><<<dim3(D/128, 1), 256>>>(p_cat,  Wz_w, Wz_b, nullptr, p_z, BATCH*NMEM, D, 2*D);
    gemm_nt<0,1,0><<<dim3(D/128, 1), 256>>>(p_cat,  Wr_w, Wr_b, nullptr, p_r, BATCH*NMEM, D, 2*D);
    catr_kernel<<<BATCH*NMEM*2*D/256, 256>>>(memory);
    gemm_nt<0,1,0><<<dim3(D/128, 1), 256>>>(p_catr, Wc_w, Wc_b, nullptr, p_c, BATCH*NMEM, D, 2*D);
    gates_kernel<<<BATCH*NMEM*D/256, 256>>>(memory, newmem);

    // 12-16. cross-attention to memory
    ln_kernel<<<ROWS, 256>>>(xo, ln2_g, ln2_b, p_h);
    gemm_tf32<0,0,0,0><<<dim3(D/128, ROWS/128), 256, GSM>>>(p_h, p_w + OFF_MQ, nullptr, nullptr, p_qkv, ROWS, D, D);
    gemm_nt<0,0,0><<<dim3(D/128, 1), 256>>>(newmem, mk_w, nullptr, nullptr, p_K, BATCH*NMEM, D, D);
    gemm_nt<0,0,0><<<dim3(D/128, 1), 256>>>(newmem, mv_w, nullptr, nullptr, p_V, BATCH*NMEM, D, D);
    cross_attn_kernel<<<BATCH*4, 256, 131072>>>(p_qkv, p_K, p_V, p_ao);
    gemm_tf32<0,0,1,0><<<dim3(D/128, ROWS/128), 256, GSM>>>(p_ao, p_w + OFF_MO, nullptr, xo, xo, ROWS, D, D);

    // 17-19. FFN
    ln_kernel<<<ROWS, 256>>>(xo, ln3_g, ln3_b, p_h);
    gemm_tf32<1,1,0,1><<<dim3(4*D/128, ROWS/128), 256, GSM>>>(p_h, p_w + OFF_W1, b1, nullptr, p_ffn, ROWS, 4*D, D);
    gemm_tf32<0,1,1,0><<<dim3(D/128, ROWS/128), 256, GSM>>>(p_ffn, p_w + OFF_W2, b2, xo, xo, ROWS, D, 4*D);
}

// round 5
// speedup vs baseline: 2.8996x; 1.6523x over previous
#include <cuda_runtime.h>
#include <math.h>
#include <stdint.h>

#define D 1024
#define T_SEQ 1024
#define BATCH 4
#define NMEM 16
#define NHEADS 64
#define HD 16
#define ROWS (BATCH*T_SEQ)   // 4096

// ---------------- scratch (device globals; no runtime allocation) ----------------
__device__ float g_h[ROWS*D];            // LN outputs (tf32-rounded)
__device__ float g_qkv[ROWS*3*D];        // qkv, later reused for Q of cross-attn
__device__ float g_ao[ROWS*D];           // attention outputs / cross-attn ctx (tf32-rounded)
__device__ float g_ffn[ROWS*4*D];        // FFN hidden (tf32-rounded)
__device__ float g_meanh[BATCH*D];
__device__ float g_base[3*BATCH*D];      // meanh @ W[:, :1024]^T + bias, per gate
__device__ float g_z[BATCH*NMEM*D];      // sigmoid(zpre)
__device__ float g_rm[BATCH*NMEM*D];     // sigmoid(rpre) * memory
__device__ float g_K[BATCH*NMEM*D];
__device__ float g_V[BATCH*NMEM*D];
__device__ float g_w[14*1024*1024];      // tf32-rounded weight copies

#define OFF_INP   0
#define OFF_AOUT  (3*1024*1024)
#define OFF_MQ    (4*1024*1024)
#define OFF_MO    (5*1024*1024)
#define OFF_W1    (6*1024*1024)
#define OFF_W2    (10*1024*1024)

__device__ __forceinline__ float to_tf32(float v) {
    uint32_t r;
    asm("cvt.rna.tf32.f32 %0, %1;" : "=r"(r) : "f"(v));
    return __uint_as_float(r);
}

// ---------------- utility kernels ----------------
__global__ void cvt_tf32_kernel(const float* __restrict__ src, float* __restrict__ dst, int n4) {
    int i = blockIdx.x*blockDim.x + threadIdx.x;
    if (i < n4) {
        float4 v = ((const float4*)src)[i];
        v.x = to_tf32(v.x); v.y = to_tf32(v.y); v.z = to_tf32(v.z); v.w = to_tf32(v.w);
        ((float4*)dst)[i] = v;
    }
}

__global__ __launch_bounds__(256) void ln_kernel(
    const float* __restrict__ x, const float* __restrict__ g,
    const float* __restrict__ b, float* __restrict__ y)
{
    __shared__ float s1[256], s2[256];
    int row = blockIdx.x;
    const float4* xr = (const float4*)(x + (size_t)row*D);
    float4 v = xr[threadIdx.x];
    float sum = v.x+v.y+v.z+v.w;
    float sq  = v.x*v.x + v.y*v.y + v.z*v.z + v.w*v.w;
    s1[threadIdx.x]=sum; s2[threadIdx.x]=sq;
    __syncthreads();
    for (int off=128; off; off>>=1) {
        if (threadIdx.x < off) {
            s1[threadIdx.x]+=s1[threadIdx.x+off];
            s2[threadIdx.x]+=s2[threadIdx.x+off];
        }
        __syncthreads();
    }
    float mean = s1[0]*(1.0f/D);
    float var  = s2[0]*(1.0f/D) - mean*mean;
    float rstd = rsqrtf(var + 1e-5f);
    int c = threadIdx.x*4;
    float4 gg = *(const float4*)(g+c);
    float4 bb = *(const float4*)(b+c);
    float4 o;
    o.x = to_tf32((v.x-mean)*rstd*gg.x + bb.x);
    o.y = to_tf32((v.y-mean)*rstd*gg.y + bb.y);
    o.z = to_tf32((v.z-mean)*rstd*gg.z + bb.z);
    o.w = to_tf32((v.w-mean)*rstd*gg.w + bb.w);
    ((float4*)(y + (size_t)row*D))[threadIdx.x] = o;
}

// ---------------- tf32 tensor-core GEMM: C(M,N) = A(M,K) @ B(N,K)^T -------------
#define SMEM_FLOATS (4*4608)
#define A_OFFS(buf) ((buf)*4608)
#define B_OFFS(buf) (9216 + (buf)*4608)

__device__ __forceinline__ void cp16(uint32_t dst, const void* src) {
    asm volatile("cp.async.cg.shared.global [%0], [%1], 16;" :: "r"(dst), "l"(src));
}

template<int ACT, int BIASF, int RESF, int TF32OUT>
__global__ __launch_bounds__(256, 2) void gemm_tf32(
    const float* __restrict__ A, const float* __restrict__ B,
    const float* __restrict__ bias, const float* __restrict__ res,
    float* __restrict__ C, int M, int N, int K)
{
    extern __shared__ float sm[];
    const int tid = threadIdx.x;
    const int bm = blockIdx.y * 128;
    const int bn = blockIdx.x * 128;
    const int lane = tid & 31;
    const int warp = tid >> 5;
    const int wm64 = (warp & 1) * 64;
    const int wn32 = (warp >> 1) * 32;
    const int qr = lane >> 2;
    const int qc = lane & 3;

    uint32_t smem_u32 = (uint32_t)__cvta_generic_to_shared(sm);

    const int lrow = tid >> 3;
    const int lkq  = (tid & 7) * 4;

    float acc[4][4][4];
    #pragma unroll
    for (int i=0;i<4;i++)
        #pragma unroll
        for (int j=0;j<4;j++)
            #pragma unroll
            for (int e=0;e<4;e++) acc[i][j][e] = 0.f;

    const int NT = K >> 5;

    {
        const float* Ab = A + (size_t)bm*K;
        const float* Bb = B + (size_t)bn*K;
        #pragma unroll
        for (int rep=0; rep<4; rep++) {
            int row = rep*32 + lrow;
            cp16(smem_u32 + (A_OFFS(0) + row*36 + lkq)*4, Ab + (size_t)row*K + lkq);
            cp16(smem_u32 + (B_OFFS(0) + row*36 + lkq)*4, Bb + (size_t)row*K + lkq);
        }
        asm volatile("cp.async.commit_group;");
    }

    for (int t = 0; t < NT; t++) {
        if (t + 1 < NT) {
            int buf = (t+1) & 1;
            int kb = (t+1) << 5;
            const float* Ab = A + (size_t)bm*K + kb;
            const float* Bb = B + (size_t)bn*K + kb;
            #pragma unroll
            for (int rep=0; rep<4; rep++) {
                int row = rep*32 + lrow;
                cp16(smem_u32 + (A_OFFS(buf) + row*36 + lkq)*4, Ab + (size_t)row*K + lkq);
                cp16(smem_u32 + (B_OFFS(buf) + row*36 + lkq)*4, Bb + (size_t)row*K + lkq);
            }
            asm volatile("cp.async.commit_group;");
            asm volatile("cp.async.wait_group 1;");
        } else {
            asm volatile("cp.async.wait_group 0;");
        }
        __syncthreads();

        const float* sA = sm + A_OFFS(t & 1);
        const float* sB = sm + B_OFFS(t & 1);

        #pragma unroll
        for (int ks = 0; ks < 4; ks++) {
            const int k0 = ks * 8;
            uint32_t a[4][4], b[4][2];
            #pragma unroll
            for (int i=0;i<4;i++) {
                int r = wm64 + i*16 + qr;
                a[i][0] = __float_as_uint(sA[r*36 + k0 + qc]);
                a[i][1] = __float_as_uint(sA[(r+8)*36 + k0 + qc]);
                a[i][2] = __float_as_uint(sA[r*36 + k0 + qc + 4]);
                a[i][3] = __float_as_uint(sA[(r+8)*36 + k0 + qc + 4]);
            }
            #pragma unroll
            for (int j=0;j<4;j++) {
                int n = wn32 + j*8 + qr;
                b[j][0] = __float_as_uint(sB[n*36 + k0 + qc]);
                b[j][1] = __float_as_uint(sB[n*36 + k0 + qc + 4]);
            }
            #pragma unroll
            for (int i=0;i<4;i++)
                #pragma unroll
                for (int j=0;j<4;j++) {
                    asm volatile(
                        "mma.sync.aligned.m16n8k8.row.col.f32.tf32.tf32.f32 "
                        "{%0,%1,%2,%3}, {%4,%5,%6,%7}, {%8,%9}, {%0,%1,%2,%3};"
                        : "+f"(acc[i][j][0]), "+f"(acc[i][j][1]),
                          "+f"(acc[i][j][2]), "+f"(acc[i][j][3])
                        : "r"(a[i][0]), "r"(a[i][1]), "r"(a[i][2]), "r"(a[i][3]),
                          "r"(b[j][0]), "r"(b[j][1]));
                }
        }
        __syncthreads();
    }

    #pragma unroll
    for (int i=0;i<4;i++) {
        int row0 = bm + wm64 + i*16 + qr;
        #pragma unroll
        for (int j=0;j<4;j++) {
            int col0 = bn + wn32 + j*8 + qc*2;
            float v0 = acc[i][j][0], v1 = acc[i][j][1];
            float v2 = acc[i][j][2], v3 = acc[i][j][3];
            if (BIASF) {
                float b0 = bias[col0], b1 = bias[col0+1];
                v0 += b0; v1 += b1; v2 += b0; v3 += b1;
            }
            if (ACT == 1) {
                v0 = 0.5f*v0*(1.f + erff(v0*0.70710678118654752f));
                v1 = 0.5f*v1*(1.f + erff(v1*0.70710678118654752f));
                v2 = 0.5f*v2*(1.f + erff(v2*0.70710678118654752f));
                v3 = 0.5f*v3*(1.f + erff(v3*0.70710678118654752f));
            }
            if (RESF) {
                v0 += res[(size_t)row0*N + col0];
                v1 += res[(size_t)row0*N + col0 + 1];
                v2 += res[(size_t)(row0+8)*N + col0];
                v3 += res[(size_t)(row0+8)*N + col0 + 1];
            }
            if (TF32OUT) {
                v0 = to_tf32(v0); v1 = to_tf32(v1);
                v2 = to_tf32(v2); v3 = to_tf32(v3);
            }
            *(float2*)(C + (size_t)row0*N + col0)     = make_float2(v0, v1);
            *(float2*)(C + (size_t)(row0+8)*N + col0) = make_float2(v2, v3);
        }
    }
}

// ---------------- self-attention: block = (b,h), thread = query row ------------
__global__ __launch_bounds__(1024) void self_attn_kernel(
    const float* __restrict__ qkv, float* __restrict__ ao)
{
    extern __shared__ float smem[];
    float* Ks = smem;
    float* Vs = smem + T_SEQ*HD;
    int b = blockIdx.x >> 6;
    int h = blockIdx.x & 63;
    int t = threadIdx.x;
    const float* base = qkv + (size_t)b*T_SEQ*3*D;
    const float4* krow = (const float4*)(base + (size_t)t*3*D + D   + h*HD);
    const float4* vrow = (const float4*)(base + (size_t)t*3*D + 2*D + h*HD);
    #pragma unroll
    for (int i=0;i<4;i++) {
        ((float4*)(Ks + t*HD))[i] = krow[i];
        ((float4*)(Vs + t*HD))[i] = vrow[i];
    }
    float q[16];
    const float4* qrow = (const float4*)(base + (size_t)t*3*D + h*HD);
    #pragma unroll
    for (int i=0;i<4;i++) ((float4*)q)[i] = qrow[i];
    #pragma unroll
    for (int i=0;i<16;i++) q[i] *= 0.25f;   // fold HD^-0.5
    __syncthreads();

    float m = -1e30f, l = 0.f, acc[16];
    #pragma unroll
    for (int i=0;i<16;i++) acc[i]=0.f;

    for (int j=0;j<T_SEQ;j+=4) {
        const float* k0p = Ks + (j+0)*HD;
        const float* k1p = Ks + (j+1)*HD;
        const float* k2p = Ks + (j+2)*HD;
        const float* k3p = Ks + (j+3)*HD;
        float s0=0.f, s1=0.f, s2=0.f, s3=0.f;
        #pragma unroll
        for (int i=0;i<16;i++) {
            float qi = q[i];
            s0 += qi*k0p[i]; s1 += qi*k1p[i];
            s2 += qi*k2p[i]; s3 += qi*k3p[i];
        }
        float mx = fmaxf(fmaxf(s0,s1), fmaxf(s2,s3));
        if (mx > m) {
            float corr = __expf(m - mx);
            l *= corr;
            #pragma unroll
            for (int i=0;i<16;i++) acc[i] *= corr;
            m = mx;
        }
        float p0 = __expf(s0-m), p1 = __expf(s1-m);
        float p2 = __expf(s2-m), p3 = __expf(s3-m);
        l += (p0+p1) + (p2+p3);
        const float* v0 = Vs + (j+0)*HD;
        const float* v1 = Vs + (j+1)*HD;
        const float* v2 = Vs + (j+2)*HD;
        const float* v3 = Vs + (j+3)*HD;
        #pragma unroll
        for (int i=0;i<16;i++)
            acc[i] += p0*v0[i] + p1*v1[i] + p2*v2[i] + p3*v3[i];
    }
    float inv = 1.f/l;
    float* orow = ao + ((size_t)b*T_SEQ + t)*D + h*HD;
    #pragma unroll
    for (int i=0;i<16;i++) orow[i] = to_tf32(acc[i]*inv);
}

// ---------------- cross-attention to memory (single head) ---------------------
__global__ __launch_bounds__(256) void cross_attn_kernel(
    const float* __restrict__ Q, const float* __restrict__ Km,
    const float* __restrict__ Vm, float* __restrict__ ctx)
{
    extern __shared__ float smem[];
    float* Ks = smem;
    float* Vs = smem + NMEM*D;
    int b = blockIdx.x >> 2;
    int chunk = blockIdx.x & 3;
    for (int i=threadIdx.x; i<NMEM*D; i+=256) {
        Ks[i] = Km[(size_t)b*NMEM*D + i];
        Vs[i] = Vm[(size_t)b*NMEM*D + i];
    }
    __syncthreads();
    int t = chunk*256 + threadIdx.x;
    const float4* qrow = (const float4*)(Q + ((size_t)b*T_SEQ + t)*D);
    float s[16];
    #pragma unroll
    for (int mm=0;mm<16;mm++) s[mm]=0.f;
    for (int k4=0;k4<D/4;k4++) {
        float4 qv = qrow[k4];
        #pragma unroll
        for (int mm=0;mm<16;mm++) {
            const float* kr = Ks + mm*D + k4*4;
            s[mm] += qv.x*kr[0] + qv.y*kr[1] + qv.z*kr[2] + qv.w*kr[3];
        }
    }
    float mx = -1e30f;
    #pragma unroll
    for (int mm=0;mm<16;mm++) { s[mm] *= 0.03125f; mx = fmaxf(mx, s[mm]); }
    float sum = 0.f;
    #pragma unroll
    for (int mm=0;mm<16;mm++) { s[mm] = __expf(s[mm]-mx); sum += s[mm]; }
    float inv = 1.f/sum;
    #pragma unroll
    for (int mm=0;mm<16;mm++) s[mm] *= inv;
    float* crow = ctx + ((size_t)b*T_SEQ + t)*D;
    for (int c=0;c<D;c+=4) {
        float4 o = make_float4(0.f,0.f,0.f,0.f);
        #pragma unroll
        for (int mm=0;mm<16;mm++) {
            const float* vr = Vs + mm*D + c;
            o.x += s[mm]*vr[0]; o.y += s[mm]*vr[1];
            o.z += s[mm]*vr[2]; o.w += s[mm]*vr[3];
        }
        o.x = to_tf32(o.x); o.y = to_tf32(o.y);
        o.z = to_tf32(o.z); o.w = to_tf32(o.w);
        *(float4*)(crow + c) = o;
    }
}

// ---------------- memory path -------------------------------------------------
__global__ __launch_bounds__(256) void mean_kernel(const float* __restrict__ x,
                                                   float* __restrict__ mh) {
    __shared__ float sred[256];
    int b = blockIdx.x, cb = blockIdx.y*128;
    int c = threadIdx.x & 127, half = threadIdx.x >> 7;
    const float* p = x + (size_t)b*T_SEQ*D + (size_t)half*512*D + cb + c;
    float s = 0.f;
    #pragma unroll 4
    for (int t=0;t<512;t++) s += p[(size_t)t*D];
    sred[threadIdx.x] = s;
    __syncthreads();
    if (half == 0)
        mh[b*D + cb + c] = (sred[threadIdx.x] + sred[threadIdx.x+128]) * (1.f/T_SEQ);
}

__global__ __launch_bounds__(256) void base_gemv(
    const float* __restrict__ Wz, const float* __restrict__ Wr, const float* __restrict__ Wc,
    const float* __restrict__ bz, const float* __restrict__ br, const float* __restrict__ bc)
{
    int gid = blockIdx.x*8 + (threadIdx.x >> 5);
    int lane = threadIdx.x & 31;
    int g = gid >> 12;
    int rem = gid & 4095;
    int b = rem >> 10;
    int col = rem & 1023;
    const float* W    = (g==0) ? Wz : ((g==1) ? Wr : Wc);
    const float* bias = (g==0) ? bz : ((g==1) ? br : bc);
    const float* wrow = W + (size_t)col*2048;
    const float* mrow = g_meanh + b*D;
    float acc = 0.f;
    #pragma unroll
    for (int k0=0;k0<1024;k0+=128) {
        float4 w = *(const float4*)(wrow + k0 + lane*4);
        float4 m = *(const float4*)(mrow + k0 + lane*4);
        acc += w.x*m.x + w.y*m.y + w.z*m.z + w.w*m.w;
    }
    #pragma unroll
    for (int o=16;o;o>>=1) acc += __shfl_xor_sync(0xFFFFFFFFu, acc, o);
    if (lane == 0) g_base[gid] = acc + bias[col];
}

__device__ __forceinline__ void tile64x64(
    const float* __restrict__ A, const float* __restrict__ B, int ldb,
    float (&acc)[4][4])
{
    __shared__ float As[32][65];
    __shared__ float Bs[32][65];
    const int tid = threadIdx.x;
    const int r  = tid >> 2;
    const int kq = (tid & 3) << 3;
    const int tx = tid & 15;
    const int ty = tid >> 4;
    for (int k0 = 0; k0 < 1024; k0 += 32) {
        float4 a0 = *(const float4*)(A + (size_t)r*1024 + k0 + kq);
        float4 a1 = *(const float4*)(A + (size_t)r*1024 + k0 + kq + 4);
        float4 b0 = *(const float4*)(B + (size_t)r*ldb  + k0 + kq);
        float4 b1 = *(const float4*)(B + (size_t)r*ldb  + k0 + kq + 4);
        __syncthreads();
        As[kq+0][r]=a0.x; As[kq+1][r]=a0.y; As[kq+2][r]=a0.z; As[kq+3][r]=a0.w;
        As[kq+4][r]=a1.x; As[kq+5][r]=a1.y; As[kq+6][r]=a1.z; As[kq+7][r]=a1.w;
        Bs[kq+0][r]=b0.x; Bs[kq+1][r]=b0.y; Bs[kq+2][r]=b0.z; Bs[kq+3][r]=b0.w;
        Bs[kq+4][r]=b1.x; Bs[kq+5][r]=b1.y; Bs[kq+6][r]=b1.z; Bs[kq+7][r]=b1.w;
        __syncthreads();
        #pragma unroll
        for (int kk=0;kk<32;kk++) {
            float a[4], b[4];
            #pragma unroll
            for (int i=0;i<4;i++) a[i] = As[kk][ty*4+i];
            #pragma unroll
            for (int j=0;j<4;j++) b[j] = Bs[kk][tx*4+j];
            #pragma unroll
            for (int i=0;i<4;i++)
                #pragma unroll
                for (int j=0;j<4;j++) acc[i][j] += a[i]*b[j];
        }
    }
}

__global__ __launch_bounds__(256) void zr_gemm(
    const float* __restrict__ mem, const float* __restrict__ Wz,
    const float* __restrict__ Wr)
{
    int g = blockIdx.y;
    int ct = blockIdx.x;
    const float* W = (g ? Wr : Wz) + (size_t)(ct*64)*2048 + 1024;
    float acc[4][4];
    #pragma unroll
    for (int i=0;i<4;i++)
        #pragma unroll
        for (int j=0;j<4;j++) acc[i][j]=0.f;
    tile64x64(mem, W, 2048, acc);
    const int tx = threadIdx.x & 15, ty = threadIdx.x >> 4;
    #pragma unroll
    for (int i=0;i<4;i++) {
        int row = ty*4+i;
        #pragma unroll
        for (int j=0;j<4;j++) {
            int col = ct*64 + tx*4+j;
            float v = acc[i][j] + g_base[g*4096 + (row>>4)*1024 + col];
            float sg = 1.f/(1.f + __expf(-v));
            if (g == 0) g_z[row*1024+col] = sg;
            else        g_rm[row*1024+col] = sg * mem[(size_t)row*1024+col];
        }
    }
}

__global__ __launch_bounds__(256) void c_gemm(
    const float* __restrict__ mem, const float* __restrict__ Wc,
    float* __restrict__ newmem)
{
    int ct = blockIdx.x;
    const float* W = Wc + (size_t)(ct*64)*2048 + 1024;
    float acc[4][4];
    #pragma unroll
    for (int i=0;i<4;i++)
        #pragma unroll
        for (int j=0;j<4;j++) acc[i][j]=0.f;
    tile64x64(g_rm, W, 2048, acc);
    const int tx = threadIdx.x & 15, ty = threadIdx.x >> 4;
    #pragma unroll
    for (int i=0;i<4;i++) {
        int row = ty*4+i;
        #pragma unroll
        for (int j=0;j<4;j++) {
            int col = ct*64 + tx*4+j;
            float v = acc[i][j] + g_base[2*4096 + (row>>4)*1024 + col];
            float c = tanhf(v);
            float z = g_z[row*1024+col];
            newmem[(size_t)row*1024+col] = (1.f - z)*mem[(size_t)row*1024+col] + z*c;
        }
    }
}

__global__ __launch_bounds__(256) void kv_gemm(
    const float* __restrict__ newmem, const float* __restrict__ mk,
    const float* __restrict__ mv)
{
    int which = blockIdx.y;
    int ct = blockIdx.x;
    const float* W = (which ? mv : mk) + (size_t)(ct*64)*1024;
    float acc[4][4];
    #pragma unroll
    for (int i=0;i<4;i++)
        #pragma unroll
        for (int j=0;j<4;j++) acc[i][j]=0.f;
    tile64x64(newmem, W, 1024, acc);
    float* out = which ? g_V : g_K;
    const int tx = threadIdx.x & 15, ty = threadIdx.x >> 4;
    #pragma unroll
    for (int i=0;i<4;i++) {
        int row = ty*4+i;
        #pragma unroll
        for (int j=0;j<4;j++) {
            int col = ct*64 + tx*4+j;
            out[(size_t)row*1024+col] = acc[i][j];
        }
    }
}

// ---------------- host launcher -------------------------------------------------
extern "C" void kernel_launch(void* const* d_in, const int* in_sizes, int n_in,
                              void* d_out, int out_size)
{
    const float* x          = (const float*)d_in[0];
    const float* memory     = (const float*)d_in[1];
    const float* ln1_g      = (const float*)d_in[2];
    const float* ln1_b      = (const float*)d_in[3];
    const float* ln2_g      = (const float*)d_in[4];
    const float* ln2_b      = (const float*)d_in[5];
    const float* ln3_g      = (const float*)d_in[6];
    const float* ln3_b      = (const float*)d_in[7];
    const float* in_proj_w  = (const float*)d_in[8];
    const float* in_proj_b  = (const float*)d_in[9];
    const float* attn_out_w = (const float*)d_in[10];
    const float* attn_out_b = (const float*)d_in[11];
    const float* Wz_w       = (const float*)d_in[12];
    const float* Wz_b       = (const float*)d_in[13];
    const float* Wr_w       = (const float*)d_in[14];
    const float* Wr_b       = (const float*)d_in[15];
    const float* Wc_w       = (const float*)d_in[16];
    const float* Wc_b       = (const float*)d_in[17];
    const float* mq_w       = (const float*)d_in[18];
    const float* mk_w       = (const float*)d_in[19];
    const float* mv_w       = (const float*)d_in[20];
    const float* mo_w       = (const float*)d_in[21];
    const float* W1         = (const float*)d_in[22];
    const float* b1         = (const float*)d_in[23];
    const float* W2         = (const float*)d_in[24];
    const float* b2         = (const float*)d_in[25];

    float* xo = (float*)d_out;
    float* newmem = xo + (size_t)ROWS*D;

    float *p_h, *p_qkv, *p_ao, *p_ffn, *p_K, *p_V, *p_w, *p_mh;
    cudaGetSymbolAddress((void**)&p_h,    g_h);
    cudaGetSymbolAddress((void**)&p_qkv,  g_qkv);
    cudaGetSymbolAddress((void**)&p_ao,   g_ao);
    cudaGetSymbolAddress((void**)&p_ffn,  g_ffn);
    cudaGetSymbolAddress((void**)&p_K,    g_K);
    cudaGetSymbolAddress((void**)&p_V,    g_V);
    cudaGetSymbolAddress((void**)&p_w,    g_w);
    cudaGetSymbolAddress((void**)&p_mh,   g_meanh);

    // Secondary stream + events, created once on the first (non-captured)
    // correctness call. If creation fails we fall back to fully serial
    // execution on the launch stream (still correct, just no overlap).
    static cudaStream_t s2 = nullptr;
    static cudaEvent_t evStart = nullptr, evCvt = nullptr, evFork = nullptr, evMem = nullptr;
    static bool tried = false, ok = false;
    if (!tried) {
        tried = true;
        ok = (cudaStreamCreateWithFlags(&s2, cudaStreamNonBlocking) == cudaSuccess) &&
             (cudaEventCreateWithFlags(&evStart, cudaEventDisableTiming) == cudaSuccess) &&
             (cudaEventCreateWithFlags(&evCvt,   cudaEventDisableTiming) == cudaSuccess) &&
             (cudaEventCreateWithFlags(&evFork,  cudaEventDisableTiming) == cudaSuccess) &&
             (cudaEventCreateWithFlags(&evMem,   cudaEventDisableTiming) == cudaSuccess);
    }
    cudaStream_t sb = ok ? s2 : (cudaStream_t)0;   // branch stream

    cudaFuncSetAttribute(self_attn_kernel,  cudaFuncAttributeMaxDynamicSharedMemorySize, 131072);
    cudaFuncSetAttribute(cross_attn_kernel, cudaFuncAttributeMaxDynamicSharedMemorySize, 131072);
    const int GSM = SMEM_FLOATS * 4;
    cudaFuncSetAttribute(gemm_tf32<0,1,0,0>, cudaFuncAttributeMaxDynamicSharedMemorySize, GSM);
    cudaFuncSetAttribute(gemm_tf32<0,1,1,0>, cudaFuncAttributeMaxDynamicSharedMemorySize, GSM);
    cudaFuncSetAttribute(gemm_tf32<0,0,0,0>, cudaFuncAttributeMaxDynamicSharedMemorySize, GSM);
    cudaFuncSetAttribute(gemm_tf32<0,0,1,0>, cudaFuncAttributeMaxDynamicSharedMemorySize, GSM);
    cudaFuncSetAttribute(gemm_tf32<1,1,0,1>, cudaFuncAttributeMaxDynamicSharedMemorySize, GSM);

    // fork: weight conversions on sb, overlapping LN1 on stream 0
    if (ok) { cudaEventRecord(evStart, 0); cudaStreamWaitEvent(sb, evStart, 0); }
    cvt_tf32_kernel<<<3072, 256, 0, sb>>>(in_proj_w,  p_w + OFF_INP,  3*1024*1024/4);
    cvt_tf32_kernel<<<1024, 256, 0, sb>>>(attn_out_w, p_w + OFF_AOUT, 1024*1024/4);
    cvt_tf32_kernel<<<1024, 256, 0, sb>>>(mq_w,       p_w + OFF_MQ,   1024*1024/4);
    cvt_tf32_kernel<<<1024, 256, 0, sb>>>(mo_w,       p_w + OFF_MO,   1024*1024/4);
    cvt_tf32_kernel<<<4096, 256, 0, sb>>>(W1,         p_w + OFF_W1,   4*1024*1024/4);
    cvt_tf32_kernel<<<4096, 256, 0, sb>>>(W2,         p_w + OFF_W2,   4*1024*1024/4);
    if (ok) cudaEventRecord(evCvt, sb);

    // h = LN1(x) directly from input
    ln_kernel<<<ROWS, 256>>>(x, ln1_g, ln1_b, p_h);
    if (ok) cudaStreamWaitEvent(0, evCvt, 0);

    // qkv = h @ in_proj^T + b
    gemm_tf32<0,1,0,0><<<dim3(3*D/128, ROWS/128), 256, GSM>>>(p_h, p_w + OFF_INP, in_proj_b, nullptr, p_qkv, ROWS, 3*D, D);

    // self-attention
    self_attn_kernel<<<BATCH*NHEADS, 1024, 131072>>>(p_qkv, p_ao);

    // x1 = x + ao @ attn_out^T + b
    gemm_tf32<0,1,1,0><<<dim3(D/128, ROWS/128), 256, GSM>>>(p_ao, p_w + OFF_AOUT, attn_out_b, x, xo, ROWS, D, D);

    // ---- fork memory path onto sb ----
    if (ok) { cudaEventRecord(evFork, 0); cudaStreamWaitEvent(sb, evFork, 0); }
    mean_kernel<<<dim3(BATCH, 8), 256, 0, sb>>>(xo, p_mh);
    base_gemv<<<1536, 256, 0, sb>>>(Wz_w, Wr_w, Wc_w, Wz_b, Wr_b, Wc_b);
    zr_gemm<<<dim3(16, 2), 256, 0, sb>>>(memory, Wz_w, Wr_w);
    c_gemm<<<16, 256, 0, sb>>>(memory, Wc_w, newmem);
    kv_gemm<<<dim3(16, 2), 256, 0, sb>>>(newmem, mk_w, mv_w);
    if (ok) cudaEventRecord(evMem, sb);

    // ---- main path: LN2 + Q projection ----
    ln_kernel<<<ROWS, 256>>>(xo, ln2_g, ln2_b, p_h);
    gemm_tf32<0,0,0,0><<<dim3(D/128, ROWS/128), 256, GSM>>>(p_h, p_w + OFF_MQ, nullptr, nullptr, p_qkv, ROWS, D, D);

    // join, then cross-attention
    if (ok) cudaStreamWaitEvent(0, evMem, 0);
    cross_attn_kernel<<<BATCH*4, 256, 131072>>>(p_qkv, p_K, p_V, p_ao);
    gemm_tf32<0,0,1,0><<<dim3(D/128, ROWS/128), 256, GSM>>>(p_ao, p_w + OFF_MO, nullptr, xo, xo, ROWS, D, D);

    // FFN
    ln_kernel<<<ROWS, 256>>>(xo, ln3_g, ln3_b, p_h);
    gemm_tf32<1,1,0,1><<<dim3(4*D/128, ROWS/128), 256, GSM>>>(p_h, p_w + OFF_W1, b1, nullptr, p_ffn, ROWS, 4*D, D);
    gemm_tf32<0,1,1,0><<<dim3(D/128, ROWS/128), 256, GSM>>>(p_ffn, p_w + OFF_W2, b2, xo, xo, ROWS, D, 4*D);
}

// round 7
// speedup vs baseline: 3.1182x; 1.0754x over previous
#include <cuda_runtime.h>
#include <math.h>
#include <stdint.h>

#define D 1024
#define T_SEQ 1024
#define BATCH 4
#define NMEM 16
#define NHEADS 64
#define HD 16
#define ROWS (BATCH*T_SEQ)   // 4096

// ---------------- scratch (device globals; no runtime allocation) ----------------
__device__ float g_h[ROWS*D];            // LN outputs (tf32-rounded)
__device__ float g_qkv[ROWS*3*D];
__device__ float g_ao[ROWS*D];           // self-attention output (tf32-rounded)
__device__ float g_ffn[ROWS*4*D];        // FFN hidden (tf32-rounded)
__device__ float g_meanh[BATCH*D];
__device__ float g_base[3*BATCH*D];      // meanh @ W[:, :1024]^T + bias, per gate
__device__ float g_zpre[BATCH*NMEM*D];   // memory @ Wz[:,1024:]^T (raw)
__device__ float g_rpre[BATCH*NMEM*D];   // memory @ Wr[:,1024:]^T (raw)
__device__ float g_z[BATCH*NMEM*D];      // sigmoid(zpre+base)
__device__ float g_rm[BATCH*NMEM*D];     // sigmoid(rpre+base) * memory
__device__ float g_K[BATCH*NMEM*D];      // folded K' = newmem @ Wk'^T
__device__ float g_V[BATCH*NMEM*D];      // folded V' = newmem @ Wv'^T
__device__ float g_wk[1024*1024];        // Wk' = mq^T @ mk
__device__ float g_wv[1024*1024];        // Wv' = mo @ mv
__device__ float g_w[16*1024*1024];      // tf32-rounded weight copies / transposes

#define OFF_INP   0
#define OFF_AOUT  (3*1024*1024)
#define OFF_MQT   (4*1024*1024)
#define OFF_MO    (5*1024*1024)
#define OFF_W1    (6*1024*1024)
#define OFF_W2    (10*1024*1024)
#define OFF_MKT   (14*1024*1024)
#define OFF_MVT   (15*1024*1024)

__device__ __forceinline__ float to_tf32(float v) {
    uint32_t r;
    asm("cvt.rna.tf32.f32 %0, %1;" : "=r"(r) : "f"(v));
    return __uint_as_float(r);
}

// ---------------- utility kernels ----------------
__global__ void cvt_tf32_kernel(const float* __restrict__ src, float* __restrict__ dst, int n4) {
    int i = blockIdx.x*blockDim.x + threadIdx.x;
    if (i < n4) {
        float4 v = ((const float4*)src)[i];
        v.x = to_tf32(v.x); v.y = to_tf32(v.y); v.z = to_tf32(v.z); v.w = to_tf32(v.w);
        ((float4*)dst)[i] = v;
    }
}

// transpose 1024x1024 with tf32 rounding: dst[i][j] = tf32(src[j][i])
__global__ __launch_bounds__(256) void transpose_tf32(
    const float* __restrict__ src, float* __restrict__ dst)
{
    __shared__ float tile[32][33];
    int x = blockIdx.x*32 + threadIdx.x;
    int y0 = blockIdx.y*32 + threadIdx.y;
    #pragma unroll
    for (int i=0;i<32;i+=8)
        tile[threadIdx.y+i][threadIdx.x] = src[(size_t)(y0+i)*1024 + x];
    __syncthreads();
    int x2 = blockIdx.y*32 + threadIdx.x;
    int y2 = blockIdx.x*32 + threadIdx.y;
    #pragma unroll
    for (int i=0;i<32;i+=8)
        dst[(size_t)(y2+i)*1024 + x2] = to_tf32(tile[threadIdx.x][threadIdx.y+i]);
}

__global__ __launch_bounds__(256) void ln_kernel(
    const float* __restrict__ x, const float* __restrict__ g,
    const float* __restrict__ b, float* __restrict__ y)
{
    __shared__ float s1[256], s2[256];
    int row = blockIdx.x;
    const float4* xr = (const float4*)(x + (size_t)row*D);
    float4 v = xr[threadIdx.x];
    float sum = v.x+v.y+v.z+v.w;
    float sq  = v.x*v.x + v.y*v.y + v.z*v.z + v.w*v.w;
    s1[threadIdx.x]=sum; s2[threadIdx.x]=sq;
    __syncthreads();
    for (int off=128; off; off>>=1) {
        if (threadIdx.x < off) {
            s1[threadIdx.x]+=s1[threadIdx.x+off];
            s2[threadIdx.x]+=s2[threadIdx.x+off];
        }
        __syncthreads();
    }
    float mean = s1[0]*(1.0f/D);
    float var  = s2[0]*(1.0f/D) - mean*mean;
    float rstd = rsqrtf(var + 1e-5f);
    int c = threadIdx.x*4;
    float4 gg = *(const float4*)(g+c);
    float4 bb = *(const float4*)(b+c);
    float4 o;
    o.x = to_tf32((v.x-mean)*rstd*gg.x + bb.x);
    o.y = to_tf32((v.y-mean)*rstd*gg.y + bb.y);
    o.z = to_tf32((v.z-mean)*rstd*gg.z + bb.z);
    o.w = to_tf32((v.w-mean)*rstd*gg.w + bb.w);
    ((float4*)(y + (size_t)row*D))[threadIdx.x] = o;
}

// ---------------- tf32 tensor-core GEMM: C(M,N) = A(M,K) @ B(N,K)^T -------------
#define SMEM_FLOATS (4*4608)
#define A_OFFS(buf) ((buf)*4608)
#define B_OFFS(buf) (9216 + (buf)*4608)

__device__ __forceinline__ void cp16(uint32_t dst, const void* src) {
    asm volatile("cp.async.cg.shared.global [%0], [%1], 16;" :: "r"(dst), "l"(src));
}

template<int ACT, int BIASF, int RESF, int TF32OUT>
__global__ __launch_bounds__(256, 2) void gemm_tf32(
    const float* __restrict__ A, const float* __restrict__ B,
    const float* __restrict__ bias, const float* __restrict__ res,
    float* __restrict__ C, int M, int N, int K)
{
    extern __shared__ float sm[];
    const int tid = threadIdx.x;
    const int bm = blockIdx.y * 128;
    const int bn = blockIdx.x * 128;
    const int lane = tid & 31;
    const int warp = tid >> 5;
    const int wm64 = (warp & 1) * 64;
    const int wn32 = (warp >> 1) * 32;
    const int qr = lane >> 2;
    const int qc = lane & 3;

    uint32_t smem_u32 = (uint32_t)__cvta_generic_to_shared(sm);

    const int lrow = tid >> 3;
    const int lkq  = (tid & 7) * 4;

    float acc[4][4][4];
    #pragma unroll
    for (int i=0;i<4;i++)
        #pragma unroll
        for (int j=0;j<4;j++)
            #pragma unroll
            for (int e=0;e<4;e++) acc[i][j][e] = 0.f;

    const int NT = K >> 5;

    {
        const float* Ab = A + (size_t)bm*K;
        const float* Bb = B + (size_t)bn*K;
        #pragma unroll
        for (int rep=0; rep<4; rep++) {
            int row = rep*32 + lrow;
            cp16(smem_u32 + (A_OFFS(0) + row*36 + lkq)*4, Ab + (size_t)row*K + lkq);
            cp16(smem_u32 + (B_OFFS(0) + row*36 + lkq)*4, Bb + (size_t)row*K + lkq);
        }
        asm volatile("cp.async.commit_group;");
    }

    for (int t = 0; t < NT; t++) {
        if (t + 1 < NT) {
            int buf = (t+1) & 1;
            int kb = (t+1) << 5;
            const float* Ab = A + (size_t)bm*K + kb;
            const float* Bb = B + (size_t)bn*K + kb;
            #pragma unroll
            for (int rep=0; rep<4; rep++) {
                int row = rep*32 + lrow;
                cp16(smem_u32 + (A_OFFS(buf) + row*36 + lkq)*4, Ab + (size_t)row*K + lkq);
                cp16(smem_u32 + (B_OFFS(buf) + row*36 + lkq)*4, Bb + (size_t)row*K + lkq);
            }
            asm volatile("cp.async.commit_group;");
            asm volatile("cp.async.wait_group 1;");
        } else {
            asm volatile("cp.async.wait_group 0;");
        }
        __syncthreads();

        const float* sA = sm + A_OFFS(t & 1);
        const float* sB = sm + B_OFFS(t & 1);

        #pragma unroll
        for (int ks = 0; ks < 4; ks++) {
            const int k0 = ks * 8;
            uint32_t a[4][4], b[4][2];
            #pragma unroll
            for (int i=0;i<4;i++) {
                int r = wm64 + i*16 + qr;
                a[i][0] = __float_as_uint(sA[r*36 + k0 + qc]);
                a[i][1] = __float_as_uint(sA[(r+8)*36 + k0 + qc]);
                a[i][2] = __float_as_uint(sA[r*36 + k0 + qc + 4]);
                a[i][3] = __float_as_uint(sA[(r+8)*36 + k0 + qc + 4]);
            }
            #pragma unroll
            for (int j=0;j<4;j++) {
                int n = wn32 + j*8 + qr;
                b[j][0] = __float_as_uint(sB[n*36 + k0 + qc]);
                b[j][1] = __float_as_uint(sB[n*36 + k0 + qc + 4]);
            }
            #pragma unroll
            for (int i=0;i<4;i++)
                #pragma unroll
                for (int j=0;j<4;j++) {
                    asm volatile(
                        "mma.sync.aligned.m16n8k8.row.col.f32.tf32.tf32.f32 "
                        "{%0,%1,%2,%3}, {%4,%5,%6,%7}, {%8,%9}, {%0,%1,%2,%3};"
                        : "+f"(acc[i][j][0]), "+f"(acc[i][j][1]),
                          "+f"(acc[i][j][2]), "+f"(acc[i][j][3])
                        : "r"(a[i][0]), "r"(a[i][1]), "r"(a[i][2]), "r"(a[i][3]),
                          "r"(b[j][0]), "r"(b[j][1]));
                }
        }
        __syncthreads();
    }

    #pragma unroll
    for (int i=0;i<4;i++) {
        int row0 = bm + wm64 + i*16 + qr;
        #pragma unroll
        for (int j=0;j<4;j++) {
            int col0 = bn + wn32 + j*8 + qc*2;
            float v0 = acc[i][j][0], v1 = acc[i][j][1];
            float v2 = acc[i][j][2], v3 = acc[i][j][3];
            if (BIASF) {
                float b0 = bias[col0], b1 = bias[col0+1];
                v0 += b0; v1 += b1; v2 += b0; v3 += b1;
            }
            if (ACT == 1) {
                v0 = 0.5f*v0*(1.f + erff(v0*0.70710678118654752f));
                v1 = 0.5f*v1*(1.f + erff(v1*0.70710678118654752f));
                v2 = 0.5f*v2*(1.f + erff(v2*0.70710678118654752f));
                v3 = 0.5f*v3*(1.f + erff(v3*0.70710678118654752f));
            }
            if (RESF) {
                v0 += res[(size_t)row0*N + col0];
                v1 += res[(size_t)row0*N + col0 + 1];
                v2 += res[(size_t)(row0+8)*N + col0];
                v3 += res[(size_t)(row0+8)*N + col0 + 1];
            }
            if (TF32OUT) {
                v0 = to_tf32(v0); v1 = to_tf32(v1);
                v2 = to_tf32(v2); v3 = to_tf32(v3);
            }
            *(float2*)(C + (size_t)row0*N + col0)     = make_float2(v0, v1);
            *(float2*)(C + (size_t)(row0+8)*N + col0) = make_float2(v2, v3);
        }
    }
}

// ---------------- self-attention: block = (b,h), thread = query row ------------
__global__ __launch_bounds__(1024) void self_attn_kernel(
    const float* __restrict__ qkv, float* __restrict__ ao)
{
    extern __shared__ float smem[];
    float* Ks = smem;
    float* Vs = smem + T_SEQ*HD;
    int b = blockIdx.x >> 6;
    int h = blockIdx.x & 63;
    int t = threadIdx.x;
    const float* base = qkv + (size_t)b*T_SEQ*3*D;
    const float4* krow = (const float4*)(base + (size_t)t*3*D + D   + h*HD);
    const float4* vrow = (const float4*)(base + (size_t)t*3*D + 2*D + h*HD);
    #pragma unroll
    for (int i=0;i<4;i++) {
        ((float4*)(Ks + t*HD))[i] = krow[i];
        ((float4*)(Vs + t*HD))[i] = vrow[i];
    }
    float4 q0, q1, q2, q3;
    {
        const float4* qrow = (const float4*)(base + (size_t)t*3*D + h*HD);
        q0 = qrow[0]; q1 = qrow[1]; q2 = qrow[2]; q3 = qrow[3];
        q0.x*=0.25f;q0.y*=0.25f;q0.z*=0.25f;q0.w*=0.25f;
        q1.x*=0.25f;q1.y*=0.25f;q1.z*=0.25f;q1.w*=0.25f;
        q2.x*=0.25f;q2.y*=0.25f;q2.z*=0.25f;q2.w*=0.25f;
        q3.x*=0.25f;q3.y*=0.25f;q3.z*=0.25f;q3.w*=0.25f;
    }
    __syncthreads();

    float m = -1e30f, l = 0.f;
    float4 a0 = make_float4(0,0,0,0), a1 = a0, a2 = a0, a3 = a0;

    for (int j=0;j<T_SEQ;j+=2) {
        const float4* kp = (const float4*)(Ks + j*HD);
        float4 x0 = kp[0], x1 = kp[1], x2 = kp[2], x3 = kp[3];
        float s0 = q0.x*x0.x + q0.y*x0.y + q0.z*x0.z + q0.w*x0.w
                 + q1.x*x1.x + q1.y*x1.y + q1.z*x1.z + q1.w*x1.w
                 + q2.x*x2.x + q2.y*x2.y + q2.z*x2.z + q2.w*x2.w
                 + q3.x*x3.x + q3.y*x3.y + q3.z*x3.z + q3.w*x3.w;
        x0 = kp[4]; x1 = kp[5]; x2 = kp[6]; x3 = kp[7];
        float s1 = q0.x*x0.x + q0.y*x0.y + q0.z*x0.z + q0.w*x0.w
                 + q1.x*x1.x + q1.y*x1.y + q1.z*x1.z + q1.w*x1.w
                 + q2.x*x2.x + q2.y*x2.y + q2.z*x2.z + q2.w*x2.w
                 + q3.x*x3.x + q3.y*x3.y + q3.z*x3.z + q3.w*x3.w;
        float mx = fmaxf(s0, s1);
        if (mx > m) {
            float corr = __expf(m - mx);
            l *= corr;
            a0.x*=corr;a0.y*=corr;a0.z*=corr;a0.w*=corr;
            a1.x*=corr;a1.y*=corr;a1.z*=corr;a1.w*=corr;
            a2.x*=corr;a2.y*=corr;a2.z*=corr;a2.w*=corr;
            a3.x*=corr;a3.y*=corr;a3.z*=corr;a3.w*=corr;
            m = mx;
        }
        float p0 = __expf(s0 - m), p1 = __expf(s1 - m);
        l += p0 + p1;
        const float4* vp = (const float4*)(Vs + j*HD);
        x0 = vp[0]; x1 = vp[1]; x2 = vp[2]; x3 = vp[3];
        a0.x += p0*x0.x; a0.y += p0*x0.y; a0.z += p0*x0.z; a0.w += p0*x0.w;
        a1.x += p0*x1.x; a1.y += p0*x1.y; a1.z += p0*x1.z; a1.w += p0*x1.w;
        a2.x += p0*x2.x; a2.y += p0*x2.y; a2.z += p0*x2.z; a2.w += p0*x2.w;
        a3.x += p0*x3.x; a3.y += p0*x3.y; a3.z += p0*x3.z; a3.w += p0*x3.w;
        x0 = vp[4]; x1 = vp[5]; x2 = vp[6]; x3 = vp[7];
        a0.x += p1*x0.x; a0.y += p1*x0.y; a0.z += p1*x0.z; a0.w += p1*x0.w;
        a1.x += p1*x1.x; a1.y += p1*x1.y; a1.z += p1*x1.z; a1.w += p1*x1.w;
        a2.x += p1*x2.x; a2.y += p1*x2.y; a2.z += p1*x2.z; a2.w += p1*x2.w;
        a3.x += p1*x3.x; a3.y += p1*x3.y; a3.z += p1*x3.z; a3.w += p1*x3.w;
    }
    float inv = 1.f/l;
    float* orow = ao + ((size_t)b*T_SEQ + t)*D + h*HD;
    orow[0]=to_tf32(a0.x*inv); orow[1]=to_tf32(a0.y*inv); orow[2]=to_tf32(a0.z*inv); orow[3]=to_tf32(a0.w*inv);
    orow[4]=to_tf32(a1.x*inv); orow[5]=to_tf32(a1.y*inv); orow[6]=to_tf32(a1.z*inv); orow[7]=to_tf32(a1.w*inv);
    orow[8]=to_tf32(a2.x*inv); orow[9]=to_tf32(a2.y*inv); orow[10]=to_tf32(a2.z*inv); orow[11]=to_tf32(a2.w*inv);
    orow[12]=to_tf32(a3.x*inv); orow[13]=to_tf32(a3.y*inv); orow[14]=to_tf32(a3.z*inv); orow[15]=to_tf32(a3.w*inv);
}

// ---------------- cross-attention (folded): xo += softmax(h@K'^T/32) @ V' -------
__global__ __launch_bounds__(256) void cross_attn_kernel(
    const float* __restrict__ Q, const float* __restrict__ Km,
    const float* __restrict__ Vm, float* __restrict__ xo)
{
    extern __shared__ float smem[];
    float* Ks = smem;
    float* Vs = smem + NMEM*D;
    int b = blockIdx.x >> 2;
    int chunk = blockIdx.x & 3;
    for (int i=threadIdx.x; i<NMEM*D; i+=256) {
        Ks[i] = Km[(size_t)b*NMEM*D + i];
        Vs[i] = Vm[(size_t)b*NMEM*D + i];
    }
    __syncthreads();
    int t = chunk*256 + threadIdx.x;
    const float4* qrow = (const float4*)(Q + ((size_t)b*T_SEQ + t)*D);
    float s[16];
    #pragma unroll
    for (int mm=0;mm<16;mm++) s[mm]=0.f;
    for (int k4=0;k4<D/4;k4++) {
        float4 qv = qrow[k4];
        #pragma unroll
        for (int mm=0;mm<16;mm++) {
            const float* kr = Ks + mm*D + k4*4;
            s[mm] += qv.x*kr[0] + qv.y*kr[1] + qv.z*kr[2] + qv.w*kr[3];
        }
    }
    float mx = -1e30f;
    #pragma unroll
    for (int mm=0;mm<16;mm++) { s[mm] *= 0.03125f; mx = fmaxf(mx, s[mm]); }
    float sum = 0.f;
    #pragma unroll
    for (int mm=0;mm<16;mm++) { s[mm] = __expf(s[mm]-mx); sum += s[mm]; }
    float inv = 1.f/sum;
    #pragma unroll
    for (int mm=0;mm<16;mm++) s[mm] *= inv;
    float* xrow = xo + ((size_t)b*T_SEQ + t)*D;
    for (int c=0;c<D;c+=4) {
        float4 o = *(const float4*)(xrow + c);   // residual (in-place add)
        #pragma unroll
        for (int mm=0;mm<16;mm++) {
            const float* vr = Vs + mm*D + c;
            o.x += s[mm]*vr[0]; o.y += s[mm]*vr[1];
            o.z += s[mm]*vr[2]; o.w += s[mm]*vr[3];
        }
        *(float4*)(xrow + c) = o;
    }
}

// ---------------- memory path -------------------------------------------------
__global__ __launch_bounds__(256) void mean_kernel(const float* __restrict__ x,
                                                   float* __restrict__ mh) {
    __shared__ float sred[256];
    int b = blockIdx.x, cb = blockIdx.y*128;
    int c = threadIdx.x & 127, half = threadIdx.x >> 7;
    const float* p = x + (size_t)b*T_SEQ*D + (size_t)half*512*D + cb + c;
    float s = 0.f;
    #pragma unroll 4
    for (int t=0;t<512;t++) s += p[(size_t)t*D];
    sred[threadIdx.x] = s;
    __syncthreads();
    if (half == 0)
        mh[b*D + cb + c] = (sred[threadIdx.x] + sred[threadIdx.x+128]) * (1.f/T_SEQ);
}

__global__ __launch_bounds__(256) void base_gemv(
    const float* __restrict__ Wz, const float* __restrict__ Wr, const float* __restrict__ Wc,
    const float* __restrict__ bz, const float* __restrict__ br, const float* __restrict__ bc)
{
    int gid = blockIdx.x*8 + (threadIdx.x >> 5);
    int lane = threadIdx.x & 31;
    int g = gid >> 12;
    int rem = gid & 4095;
    int b = rem >> 10;
    int col = rem & 1023;
    const float* W    = (g==0) ? Wz : ((g==1) ? Wr : Wc);
    const float* bias = (g==0) ? bz : ((g==1) ? br : bc);
    const float* wrow = W + (size_t)col*2048;
    const float* mrow = g_meanh + b*D;
    float acc = 0.f;
    #pragma unroll
    for (int k0=0;k0<1024;k0+=128) {
        float4 w = *(const float4*)(wrow + k0 + lane*4);
        float4 m = *(const float4*)(mrow + k0 + lane*4);
        acc += w.x*m.x + w.y*m.y + w.z*m.z + w.w*m.w;
    }
    #pragma unroll
    for (int o=16;o;o>>=1) acc += __shfl_xor_sync(0xFFFFFFFFu, acc, o);
    if (lane == 0) g_base[gid] = acc + bias[col];
}

__device__ __forceinline__ void tile64x64(
    const float* __restrict__ A, const float* __restrict__ B, int ldb,
    float (&acc)[4][4])
{
    __shared__ float As[32][65];
    __shared__ float Bs[32][65];
    const int tid = threadIdx.x;
    const int r  = tid >> 2;
    const int kq = (tid & 3) << 3;
    const int tx = tid & 15;
    const int ty = tid >> 4;
    for (int k0 = 0; k0 < 1024; k0 += 32) {
        float4 a0 = *(const float4*)(A + (size_t)r*1024 + k0 + kq);
        float4 a1 = *(const float4*)(A + (size_t)r*1024 + k0 + kq + 4);
        float4 b0 = *(const float4*)(B + (size_t)r*ldb  + k0 + kq);
        float4 b1 = *(const float4*)(B + (size_t)r*ldb  + k0 + kq + 4);
        __syncthreads();
        As[kq+0][r]=a0.x; As[kq+1][r]=a0.y; As[kq+2][r]=a0.z; As[kq+3][r]=a0.w;
        As[kq+4][r]=a1.x; As[kq+5][r]=a1.y; As[kq+6][r]=a1.z; As[kq+7][r]=a1.w;
        Bs[kq+0][r]=b0.x; Bs[kq+1][r]=b0.y; Bs[kq+2][r]=b0.z; Bs[kq+3][r]=b0.w;
        Bs[kq+4][r]=b1.x; Bs[kq+5][r]=b1.y; Bs[kq+6][r]=b1.z; Bs[kq+7][r]=b1.w;
        __syncthreads();
        #pragma unroll
        for (int kk=0;kk<32;kk++) {
            float a[4], b[4];
            #pragma unroll
            for (int i=0;i<4;i++) a[i] = As[kk][ty*4+i];
            #pragma unroll
            for (int j=0;j<4;j++) b[j] = Bs[kk][tx*4+j];
            #pragma unroll
            for (int i=0;i<4;i++)
                #pragma unroll
                for (int j=0;j<4;j++) acc[i][j] += a[i]*b[j];
        }
    }
}

// raw pre-activations from memory-half of Wz/Wr (no mean dependence)
__global__ __launch_bounds__(256) void zr_pre(
    const float* __restrict__ mem, const float* __restrict__ Wz,
    const float* __restrict__ Wr)
{
    int g = blockIdx.y;
    int ct = blockIdx.x;
    const float* W = (g ? Wr : Wz) + (size_t)(ct*64)*2048 + 1024;
    float acc[4][4];
    #pragma unroll
    for (int i=0;i<4;i++)
        #pragma unroll
        for (int j=0;j<4;j++) acc[i][j]=0.f;
    tile64x64(mem, W, 2048, acc);
    float* out = g ? g_rpre : g_zpre;
    const int tx = threadIdx.x & 15, ty = threadIdx.x >> 4;
    #pragma unroll
    for (int i=0;i<4;i++) {
        int row = ty*4+i;
        #pragma unroll
        for (int j=0;j<4;j++) out[row*1024 + ct*64 + tx*4+j] = acc[i][j];
    }
}

// z = sigmoid(zpre+base_z); rm = sigmoid(rpre+base_r)*memory
__global__ void combine_kernel(const float* __restrict__ mem) {
    int idx = blockIdx.x*blockDim.x + threadIdx.x;   // 0..65535
    int row = idx >> 10, col = idx & 1023, b = row >> 4;
    float z = 1.f/(1.f + __expf(-(g_zpre[idx] + g_base[0*4096 + b*1024 + col])));
    float r = 1.f/(1.f + __expf(-(g_rpre[idx] + g_base[1*4096 + b*1024 + col])));
    g_z[idx] = z;
    g_rm[idx] = r * mem[idx];
}

__global__ __launch_bounds__(256) void c_gemm(
    const float* __restrict__ mem, const float* __restrict__ Wc,
    float* __restrict__ newmem)
{
    int ct = blockIdx.x;
    const float* W = Wc + (size_t)(ct*64)*2048 + 1024;
    float acc[4][4];
    #pragma unroll
    for (int i=0;i<4;i++)
        #pragma unroll
        for (int j=0;j<4;j++) acc[i][j]=0.f;
    tile64x64(g_rm, W, 2048, acc);
    const int tx = threadIdx.x & 15, ty = threadIdx.x >> 4;
    #pragma unroll
    for (int i=0;i<4;i++) {
        int row = ty*4+i;
        #pragma unroll
        for (int j=0;j<4;j++) {
            int col = ct*64 + tx*4+j;
            float v = acc[i][j] + g_base[2*4096 + (row>>4)*1024 + col];
            float c = tanhf(v);
            float z = g_z[row*1024+col];
            newmem[(size_t)row*1024+col] = (1.f - z)*mem[(size_t)row*1024+col] + z*c;
        }
    }
}

// K' = newmem @ Wk'^T ; V' = newmem @ Wv'^T
__global__ __launch_bounds__(256) void kv2_gemm(const float* __restrict__ newmem)
{
    int which = blockIdx.y;
    int ct = blockIdx.x;
    const float* W = (which ? g_wv : g_wk) + (size_t)(ct*64)*1024;
    float acc[4][4];
    #pragma unroll
    for (int i=0;i<4;i++)
        #pragma unroll
        for (int j=0;j<4;j++) acc[i][j]=0.f;
    tile64x64(newmem, W, 1024, acc);
    float* out = which ? g_V : g_K;
    const int tx = threadIdx.x & 15, ty = threadIdx.x >> 4;
    #pragma unroll
    for (int i=0;i<4;i++) {
        int row = ty*4+i;
        #pragma unroll
        for (int j=0;j<4;j++) {
            int col = ct*64 + tx*4+j;
            out[(size_t)row*1024+col] = acc[i][j];
        }
    }
}

// ---------------- host launcher -------------------------------------------------
extern "C" void kernel_launch(void* const* d_in, const int* in_sizes, int n_in,
                              void* d_out, int out_size)
{
    const float* x          = (const float*)d_in[0];
    const float* memory     = (const float*)d_in[1];
    const float* ln1_g      = (const float*)d_in[2];
    const float* ln1_b      = (const float*)d_in[3];
    const float* ln2_g      = (const float*)d_in[4];
    const float* ln2_b      = (const float*)d_in[5];
    const float* ln3_g      = (const float*)d_in[6];
    const float* ln3_b      = (const float*)d_in[7];
    const float* in_proj_w  = (const float*)d_in[8];
    const float* in_proj_b  = (const float*)d_in[9];
    const float* attn_out_w = (const float*)d_in[10];
    const float* attn_out_b = (const float*)d_in[11];
    const float* Wz_w       = (const float*)d_in[12];
    const float* Wz_b       = (const float*)d_in[13];
    const float* Wr_w       = (const float*)d_in[14];
    const float* Wr_b       = (const float*)d_in[15];
    const float* Wc_w       = (const float*)d_in[16];
    const float* Wc_b       = (const float*)d_in[17];
    const float* mq_w       = (const float*)d_in[18];
    const float* mk_w       = (const float*)d_in[19];
    const float* mv_w       = (const float*)d_in[20];
    const float* mo_w       = (const float*)d_in[21];
    const float* W1         = (const float*)d_in[22];
    const float* b1         = (const float*)d_in[23];
    const float* W2         = (const float*)d_in[24];
    const float* b2         = (const float*)d_in[25];

    float* xo = (float*)d_out;
    float* newmem = xo + (size_t)ROWS*D;

    float *p_h, *p_qkv, *p_ao, *p_ffn, *p_K, *p_V, *p_w, *p_mh, *p_wk, *p_wv;
    cudaGetSymbolAddress((void**)&p_h,    g_h);
    cudaGetSymbolAddress((void**)&p_qkv,  g_qkv);
    cudaGetSymbolAddress((void**)&p_ao,   g_ao);
    cudaGetSymbolAddress((void**)&p_ffn,  g_ffn);
    cudaGetSymbolAddress((void**)&p_K,    g_K);
    cudaGetSymbolAddress((void**)&p_V,    g_V);
    cudaGetSymbolAddress((void**)&p_w,    g_w);
    cudaGetSymbolAddress((void**)&p_mh,   g_meanh);
    cudaGetSymbolAddress((void**)&p_wk,   g_wk);
    cudaGetSymbolAddress((void**)&p_wv,   g_wv);

    static cudaStream_t s2 = nullptr;
    static cudaEvent_t evStart = nullptr, evCvt = nullptr, evFork = nullptr, evMem = nullptr;
    static bool tried = false, ok = false;
    if (!tried) {
        tried = true;
        ok = (cudaStreamCreateWithFlags(&s2, cudaStreamNonBlocking) == cudaSuccess) &&
             (cudaEventCreateWithFlags(&evStart, cudaEventDisableTiming) == cudaSuccess) &&
             (cudaEventCreateWithFlags(&evCvt,   cudaEventDisableTiming) == cudaSuccess) &&
             (cudaEventCreateWithFlags(&evFork,  cudaEventDisableTiming) == cudaSuccess) &&
             (cudaEventCreateWithFlags(&evMem,   cudaEventDisableTiming) == cudaSuccess);
    }
    cudaStream_t sb = ok ? s2 : (cudaStream_t)0;

    cudaFuncSetAttribute(self_attn_kernel,  cudaFuncAttributeMaxDynamicSharedMemorySize, 131072);
    cudaFuncSetAttribute(cross_attn_kernel, cudaFuncAttributeMaxDynamicSharedMemorySize, 131072);
    const int GSM = SMEM_FLOATS * 4;
    cudaFuncSetAttribute(gemm_tf32<0,1,0,0>, cudaFuncAttributeMaxDynamicSharedMemorySize, GSM);
    cudaFuncSetAttribute(gemm_tf32<0,1,1,0>, cudaFuncAttributeMaxDynamicSharedMemorySize, GSM);
    cudaFuncSetAttribute(gemm_tf32<0,0,0,0>, cudaFuncAttributeMaxDynamicSharedMemorySize, GSM);
    cudaFuncSetAttribute(gemm_tf32<1,1,0,1>, cudaFuncAttributeMaxDynamicSharedMemorySize, GSM);

    // ---- early hidden phase on sb ----
    if (ok) { cudaEventRecord(evStart, 0); cudaStreamWaitEvent(sb, evStart, 0); }
    // weight conversions needed by main-path gemms
    cvt_tf32_kernel<<<3072, 256, 0, sb>>>(in_proj_w,  p_w + OFF_INP,  3*1024*1024/4);
    cvt_tf32_kernel<<<1024, 256, 0, sb>>>(attn_out_w, p_w + OFF_AOUT, 1024*1024/4);
    cvt_tf32_kernel<<<4096, 256, 0, sb>>>(W1,         p_w + OFF_W1,   4*1024*1024/4);
    cvt_tf32_kernel<<<4096, 256, 0, sb>>>(W2,         p_w + OFF_W2,   4*1024*1024/4);
    if (ok) cudaEventRecord(evCvt, sb);
    // folded-weight prep (only needed by memory path / cross-attn)
    cvt_tf32_kernel<<<1024, 256, 0, sb>>>(mo_w, p_w + OFF_MO, 1024*1024/4);
    transpose_tf32<<<dim3(32,32), dim3(32,8), 0, sb>>>(mq_w, p_w + OFF_MQT);
    transpose_tf32<<<dim3(32,32), dim3(32,8), 0, sb>>>(mk_w, p_w + OFF_MKT);
    transpose_tf32<<<dim3(32,32), dim3(32,8), 0, sb>>>(mv_w, p_w + OFF_MVT);
    // Wk' = mq^T @ mk ; Wv' = mo @ mv   (1024x1024x1024 tf32 gemms)
    gemm_tf32<0,0,0,0><<<dim3(8,8), 256, GSM, sb>>>(p_w + OFF_MQT, p_w + OFF_MKT, nullptr, nullptr, p_wk, 1024, 1024, 1024);
    gemm_tf32<0,0,0,0><<<dim3(8,8), 256, GSM, sb>>>(p_w + OFF_MO,  p_w + OFF_MVT, nullptr, nullptr, p_wv, 1024, 1024, 1024);
    // memory-only z/r pre-activations
    zr_pre<<<dim3(16,2), 256, 0, sb>>>(memory, Wz_w, Wr_w);

    // ---- main path ----
    ln_kernel<<<ROWS, 256>>>(x, ln1_g, ln1_b, p_h);
    if (ok) cudaStreamWaitEvent(0, evCvt, 0);

    gemm_tf32<0,1,0,0><<<dim3(3*D/128, ROWS/128), 256, GSM>>>(p_h, p_w + OFF_INP, in_proj_b, nullptr, p_qkv, ROWS, 3*D, D);
    self_attn_kernel<<<BATCH*NHEADS, 1024, 131072>>>(p_qkv, p_ao);
    gemm_tf32<0,1,1,0><<<dim3(D/128, ROWS/128), 256, GSM>>>(p_ao, p_w + OFF_AOUT, attn_out_b, x, xo, ROWS, D, D);

    // ---- fork memory path onto sb ----
    if (ok) { cudaEventRecord(evFork, 0); cudaStreamWaitEvent(sb, evFork, 0); }
    mean_kernel<<<dim3(BATCH, 8), 256, 0, sb>>>(xo, p_mh);
    base_gemv<<<1536, 256, 0, sb>>>(Wz_w, Wr_w, Wc_w, Wz_b, Wr_b, Wc_b);
    combine_kernel<<<BATCH*NMEM*D/256, 256, 0, sb>>>(memory);
    c_gemm<<<16, 256, 0, sb>>>(memory, Wc_w, newmem);
    kv2_gemm<<<dim3(16, 2), 256, 0, sb>>>(newmem);
    if (ok) cudaEventRecord(evMem, sb);

    // ---- main path: LN2, then folded cross-attention (in-place residual) ----
    ln_kernel<<<ROWS, 256>>>(xo, ln2_g, ln2_b, p_h);
    if (ok) cudaStreamWaitEvent(0, evMem, 0);
    cross_attn_kernel<<<BATCH*4, 256, 131072>>>(p_h, p_K, p_V, xo);

    // FFN
    ln_kernel<<<ROWS, 256>>>(xo, ln3_g, ln3_b, p_h);
    gemm_tf32<1,1,0,1><<<dim3(4*D/128, ROWS/128), 256, GSM>>>(p_h, p_w + OFF_W1, b1, nullptr, p_ffn, ROWS, 4*D, D);
    gemm_tf32<0,1,1,0><<<dim3(D/128, ROWS/128), 256, GSM>>>(p_ffn, p_w + OFF_W2, b2, xo, xo, ROWS, D, 4*D);
}

// round 9
// speedup vs baseline: 3.6848x; 1.1817x over previous
#include <cuda_runtime.h>
#include <math.h>
#include <stdint.h>

#define D 1024
#define T_SEQ 1024
#define BATCH 4
#define NMEM 16
#define NHEADS 64
#define HD 16
#define ROWS (BATCH*T_SEQ)   // 4096

// ---------------- scratch (device globals; no runtime allocation) ----------------
__device__ float g_h[ROWS*D];            // LN outputs (tf32-rounded)
__device__ float g_qkv[ROWS*3*D];
__device__ float g_ao[ROWS*D];           // self-attention output (tf32-rounded)
__device__ float g_ffn[ROWS*4*D];        // FFN hidden (tf32-rounded)
__device__ float g_meanh[BATCH*D];
__device__ float g_base[3*BATCH*D];      // meanh @ W[:, :1024]^T + bias, per gate
__device__ float g_zpre[BATCH*NMEM*D];   // memory @ Wz[:,1024:]^T (raw)
__device__ float g_rpre[BATCH*NMEM*D];   // memory @ Wr[:,1024:]^T (raw)
__device__ float g_z[BATCH*NMEM*D];      // sigmoid(zpre+base)
__device__ float g_rm[BATCH*NMEM*D];     // sigmoid(rpre+base) * memory
__device__ float g_K[BATCH*NMEM*D];      // folded K' = newmem @ Wk'^T
__device__ float g_V[BATCH*NMEM*D];      // folded V' = newmem @ Wv'^T
__device__ float g_wk[1024*1024];        // Wk' = mq^T @ mk
__device__ float g_wv[1024*1024];        // Wv' = mo @ mv
__device__ float g_w[16*1024*1024];      // tf32-rounded weight copies / transposes

#define OFF_INP   0
#define OFF_AOUT  (3*1024*1024)
#define OFF_MQT   (4*1024*1024)
#define OFF_MO    (5*1024*1024)
#define OFF_W1    (6*1024*1024)
#define OFF_W2    (10*1024*1024)
#define OFF_MKT   (14*1024*1024)
#define OFF_MVT   (15*1024*1024)

__device__ __forceinline__ float to_tf32(float v) {
    uint32_t r;
    asm("cvt.rna.tf32.f32 %0, %1;" : "=r"(r) : "f"(v));
    return __uint_as_float(r);
}

// ---------------- utility kernels ----------------
__global__ void cvt_tf32_kernel(const float* __restrict__ src, float* __restrict__ dst, int n4) {
    int i = blockIdx.x*blockDim.x + threadIdx.x;
    if (i < n4) {
        float4 v = ((const float4*)src)[i];
        v.x = to_tf32(v.x); v.y = to_tf32(v.y); v.z = to_tf32(v.z); v.w = to_tf32(v.w);
        ((float4*)dst)[i] = v;
    }
}

// transpose 1024x1024 with tf32 rounding: dst[i][j] = tf32(src[j][i])
__global__ __launch_bounds__(256) void transpose_tf32(
    const float* __restrict__ src, float* __restrict__ dst)
{
    __shared__ float tile[32][33];
    int x = blockIdx.x*32 + threadIdx.x;
    int y0 = blockIdx.y*32 + threadIdx.y;
    #pragma unroll
    for (int i=0;i<32;i+=8)
        tile[threadIdx.y+i][threadIdx.x] = src[(size_t)(y0+i)*1024 + x];
    __syncthreads();
    int x2 = blockIdx.y*32 + threadIdx.x;
    int y2 = blockIdx.x*32 + threadIdx.y;
    #pragma unroll
    for (int i=0;i<32;i+=8)
        dst[(size_t)(y2+i)*1024 + x2] = to_tf32(tile[threadIdx.x][threadIdx.y+i]);
}

__global__ __launch_bounds__(256) void ln_kernel(
    const float* __restrict__ x, const float* __restrict__ g,
    const float* __restrict__ b, float* __restrict__ y)
{
    __shared__ float s1[256], s2[256];
    int row = blockIdx.x;
    const float4* xr = (const float4*)(x + (size_t)row*D);
    float4 v = xr[threadIdx.x];
    float sum = v.x+v.y+v.z+v.w;
    float sq  = v.x*v.x + v.y*v.y + v.z*v.z + v.w*v.w;
    s1[threadIdx.x]=sum; s2[threadIdx.x]=sq;
    __syncthreads();
    for (int off=128; off; off>>=1) {
        if (threadIdx.x < off) {
            s1[threadIdx.x]+=s1[threadIdx.x+off];
            s2[threadIdx.x]+=s2[threadIdx.x+off];
        }
        __syncthreads();
    }
    float mean = s1[0]*(1.0f/D);
    float var  = s2[0]*(1.0f/D) - mean*mean;
    float rstd = rsqrtf(var + 1e-5f);
    int c = threadIdx.x*4;
    float4 gg = *(const float4*)(g+c);
    float4 bb = *(const float4*)(b+c);
    float4 o;
    o.x = to_tf32((v.x-mean)*rstd*gg.x + bb.x);
    o.y = to_tf32((v.y-mean)*rstd*gg.y + bb.y);
    o.z = to_tf32((v.z-mean)*rstd*gg.z + bb.z);
    o.w = to_tf32((v.w-mean)*rstd*gg.w + bb.w);
    ((float4*)(y + (size_t)row*D))[threadIdx.x] = o;
}

// ---------------- tf32 tensor-core GEMM: C(M,N) = A(M,K) @ B(N,K)^T -------------
#define SMEM_FLOATS (4*4608)
#define A_OFFS(buf) ((buf)*4608)
#define B_OFFS(buf) (9216 + (buf)*4608)

__device__ __forceinline__ void cp16(uint32_t dst, const void* src) {
    asm volatile("cp.async.cg.shared.global [%0], [%1], 16;" :: "r"(dst), "l"(src));
}

template<int ACT, int BIASF, int RESF, int TF32OUT>
__global__ __launch_bounds__(256, 2) void gemm_tf32(
    const float* __restrict__ A, const float* __restrict__ B,
    const float* __restrict__ bias, const float* __restrict__ res,
    float* __restrict__ C, int M, int N, int K)
{
    extern __shared__ float sm[];
    const int tid = threadIdx.x;
    const int bm = blockIdx.y * 128;
    const int bn = blockIdx.x * 128;
    const int lane = tid & 31;
    const int warp = tid >> 5;
    const int wm64 = (warp & 1) * 64;
    const int wn32 = (warp >> 1) * 32;
    const int qr = lane >> 2;
    const int qc = lane & 3;

    uint32_t smem_u32 = (uint32_t)__cvta_generic_to_shared(sm);

    const int lrow = tid >> 3;
    const int lkq  = (tid & 7) * 4;

    float acc[4][4][4];
    #pragma unroll
    for (int i=0;i<4;i++)
        #pragma unroll
        for (int j=0;j<4;j++)
            #pragma unroll
            for (int e=0;e<4;e++) acc[i][j][e] = 0.f;

    const int NT = K >> 5;

    {
        const float* Ab = A + (size_t)bm*K;
        const float* Bb = B + (size_t)bn*K;
        #pragma unroll
        for (int rep=0; rep<4; rep++) {
            int row = rep*32 + lrow;
            cp16(smem_u32 + (A_OFFS(0) + row*36 + lkq)*4, Ab + (size_t)row*K + lkq);
            cp16(smem_u32 + (B_OFFS(0) + row*36 + lkq)*4, Bb + (size_t)row*K + lkq);
        }
        asm volatile("cp.async.commit_group;");
    }

    for (int t = 0; t < NT; t++) {
        if (t + 1 < NT) {
            int buf = (t+1) & 1;
            int kb = (t+1) << 5;
            const float* Ab = A + (size_t)bm*K + kb;
            const float* Bb = B + (size_t)bn*K + kb;
            #pragma unroll
            for (int rep=0; rep<4; rep++) {
                int row = rep*32 + lrow;
                cp16(smem_u32 + (A_OFFS(buf) + row*36 + lkq)*4, Ab + (size_t)row*K + lkq);
                cp16(smem_u32 + (B_OFFS(buf) + row*36 + lkq)*4, Bb + (size_t)row*K + lkq);
            }
            asm volatile("cp.async.commit_group;");
            asm volatile("cp.async.wait_group 1;");
        } else {
            asm volatile("cp.async.wait_group 0;");
        }
        __syncthreads();

        const float* sA = sm + A_OFFS(t & 1);
        const float* sB = sm + B_OFFS(t & 1);

        #pragma unroll
        for (int ks = 0; ks < 4; ks++) {
            const int k0 = ks * 8;
            uint32_t a[4][4], b[4][2];
            #pragma unroll
            for (int i=0;i<4;i++) {
                int r = wm64 + i*16 + qr;
                a[i][0] = __float_as_uint(sA[r*36 + k0 + qc]);
                a[i][1] = __float_as_uint(sA[(r+8)*36 + k0 + qc]);
                a[i][2] = __float_as_uint(sA[r*36 + k0 + qc + 4]);
                a[i][3] = __float_as_uint(sA[(r+8)*36 + k0 + qc + 4]);
            }
            #pragma unroll
            for (int j=0;j<4;j++) {
                int n = wn32 + j*8 + qr;
                b[j][0] = __float_as_uint(sB[n*36 + k0 + qc]);
                b[j][1] = __float_as_uint(sB[n*36 + k0 + qc + 4]);
            }
            #pragma unroll
            for (int i=0;i<4;i++)
                #pragma unroll
                for (int j=0;j<4;j++) {
                    asm volatile(
                        "mma.sync.aligned.m16n8k8.row.col.f32.tf32.tf32.f32 "
                        "{%0,%1,%2,%3}, {%4,%5,%6,%7}, {%8,%9}, {%0,%1,%2,%3};"
                        : "+f"(acc[i][j][0]), "+f"(acc[i][j][1]),
                          "+f"(acc[i][j][2]), "+f"(acc[i][j][3])
                        : "r"(a[i][0]), "r"(a[i][1]), "r"(a[i][2]), "r"(a[i][3]),
                          "r"(b[j][0]), "r"(b[j][1]));
                }
        }
        __syncthreads();
    }

    #pragma unroll
    for (int i=0;i<4;i++) {
        int row0 = bm + wm64 + i*16 + qr;
        #pragma unroll
        for (int j=0;j<4;j++) {
            int col0 = bn + wn32 + j*8 + qc*2;
            float v0 = acc[i][j][0], v1 = acc[i][j][1];
            float v2 = acc[i][j][2], v3 = acc[i][j][3];
            if (BIASF) {
                float b0 = bias[col0], b1 = bias[col0+1];
                v0 += b0; v1 += b1; v2 += b0; v3 += b1;
            }
            if (ACT == 1) {
                v0 = 0.5f*v0*(1.f + erff(v0*0.70710678118654752f));
                v1 = 0.5f*v1*(1.f + erff(v1*0.70710678118654752f));
                v2 = 0.5f*v2*(1.f + erff(v2*0.70710678118654752f));
                v3 = 0.5f*v3*(1.f + erff(v3*0.70710678118654752f));
            }
            if (RESF) {
                v0 += res[(size_t)row0*N + col0];
                v1 += res[(size_t)row0*N + col0 + 1];
                v2 += res[(size_t)(row0+8)*N + col0];
                v3 += res[(size_t)(row0+8)*N + col0 + 1];
            }
            if (TF32OUT) {
                v0 = to_tf32(v0); v1 = to_tf32(v1);
                v2 = to_tf32(v2); v3 = to_tf32(v3);
            }
            *(float2*)(C + (size_t)row0*N + col0)     = make_float2(v0, v1);
            *(float2*)(C + (size_t)(row0+8)*N + col0) = make_float2(v2, v3);
        }
    }
}

// ---------------- tensor-core flash self-attention ------------------------------
// block = (b*64+h, qtile of 256 queries), 256 threads (8 warps), warp owns 32 q.
// Full K/V head resident in smem (tf32), keys chunked by 64 for S registers.
#define KS_STRIDE 20
#define VS_STRIDE 24
#define PS_STRIDE 68
#define FLASH_SMEM ((1024*KS_STRIDE + 1024*VS_STRIDE + 8*16*PS_STRIDE)*4)

#define MMA_TF32(acc, a, b0, b1) \
    asm volatile( \
        "mma.sync.aligned.m16n8k8.row.col.f32.tf32.tf32.f32 " \
        "{%0,%1,%2,%3}, {%4,%5,%6,%7}, {%8,%9}, {%0,%1,%2,%3};" \
        : "+f"((acc)[0]), "+f"((acc)[1]), "+f"((acc)[2]), "+f"((acc)[3]) \
        : "r"((a)[0]), "r"((a)[1]), "r"((a)[2]), "r"((a)[3]), \
          "r"(b0), "r"(b1))

__global__ __launch_bounds__(256) void flash_attn_kernel(
    const float* __restrict__ qkv, float* __restrict__ ao)
{
    extern __shared__ float smem[];
    float* Ks = smem;                               // [1024][KS_STRIDE]
    float* Vs = smem + 1024*KS_STRIDE;              // [1024][VS_STRIDE]
    float* Ps = Vs + 1024*VS_STRIDE + (threadIdx.x >> 5)*16*PS_STRIDE; // per-warp

    const int b = blockIdx.x >> 6;
    const int h = blockIdx.x & 63;
    const int qt = blockIdx.y;
    const int tid = threadIdx.x;
    const int lane = tid & 31;
    const int warp = tid >> 5;
    const int qr = lane >> 2;      // 0..7
    const int qc = lane & 3;       // 0..3

    const float* base = qkv + (size_t)b*T_SEQ*3*D + h*HD;

    // stage K/V (tf32-rounded)
    for (int r = tid; r < T_SEQ; r += 256) {
        const float4* kr = (const float4*)(base + (size_t)r*3*D + D);
        const float4* vr = (const float4*)(base + (size_t)r*3*D + 2*D);
        #pragma unroll
        for (int i=0;i<4;i++) {
            float4 kv = kr[i], vv = vr[i];
            kv.x=to_tf32(kv.x); kv.y=to_tf32(kv.y); kv.z=to_tf32(kv.z); kv.w=to_tf32(kv.w);
            vv.x=to_tf32(vv.x); vv.y=to_tf32(vv.y); vv.z=to_tf32(vv.z); vv.w=to_tf32(vv.w);
            *(float4*)(Ks + r*KS_STRIDE + i*4) = kv;
            *(float4*)(Vs + r*VS_STRIDE + i*4) = vv;
        }
    }

    // load Q fragments (scale folded, tf32-rounded)
    const int q0 = qt*256 + warp*32;
    uint32_t aQ[2][2][4];
    #pragma unroll
    for (int mt=0; mt<2; mt++)
        #pragma unroll
        for (int ks=0; ks<2; ks++) {
            int r0 = q0 + mt*16 + qr;
            int c0 = ks*8 + qc;
            aQ[mt][ks][0] = __float_as_uint(to_tf32(0.25f*base[(size_t)r0*3*D + c0]));
            aQ[mt][ks][1] = __float_as_uint(to_tf32(0.25f*base[(size_t)(r0+8)*3*D + c0]));
            aQ[mt][ks][2] = __float_as_uint(to_tf32(0.25f*base[(size_t)r0*3*D + c0+4]));
            aQ[mt][ks][3] = __float_as_uint(to_tf32(0.25f*base[(size_t)(r0+8)*3*D + c0+4]));
        }
    __syncthreads();

    float mstate[2][2], lstate[2][2], oacc[2][2][4];
    #pragma unroll
    for (int mt=0; mt<2; mt++) {
        mstate[mt][0] = -1e30f; mstate[mt][1] = -1e30f;
        lstate[mt][0] = 0.f;    lstate[mt][1] = 0.f;
        #pragma unroll
        for (int nt=0; nt<2; nt++)
            #pragma unroll
            for (int e=0; e<4; e++) oacc[mt][nt][e] = 0.f;
    }

    for (int nc = 0; nc < 16; nc++) {
        const int kb = nc*64;
        #pragma unroll
        for (int mt=0; mt<2; mt++) {
            // --- S = Q @ K^T over this 64-key chunk ---
            float sacc[8][4];
            #pragma unroll
            for (int nt=0; nt<8; nt++)
                #pragma unroll
                for (int e=0; e<4; e++) sacc[nt][e] = 0.f;
            #pragma unroll
            for (int nt=0; nt<8; nt++) {
                const int key = kb + nt*8 + qr;
                #pragma unroll
                for (int ks=0; ks<2; ks++) {
                    uint32_t b0 = __float_as_uint(Ks[key*KS_STRIDE + ks*8 + qc]);
                    uint32_t b1 = __float_as_uint(Ks[key*KS_STRIDE + ks*8 + qc + 4]);
                    MMA_TF32(sacc[nt], aQ[mt][ks], b0, b1);
                }
            }
            // --- online softmax ---
            float r0max = -1e30f, r1max = -1e30f;
            #pragma unroll
            for (int nt=0; nt<8; nt++) {
                r0max = fmaxf(r0max, fmaxf(sacc[nt][0], sacc[nt][1]));
                r1max = fmaxf(r1max, fmaxf(sacc[nt][2], sacc[nt][3]));
            }
            r0max = fmaxf(r0max, __shfl_xor_sync(0xFFFFFFFFu, r0max, 1));
            r0max = fmaxf(r0max, __shfl_xor_sync(0xFFFFFFFFu, r0max, 2));
            r1max = fmaxf(r1max, __shfl_xor_sync(0xFFFFFFFFu, r1max, 1));
            r1max = fmaxf(r1max, __shfl_xor_sync(0xFFFFFFFFu, r1max, 2));
            float mnew0 = fmaxf(mstate[mt][0], r0max);
            float mnew1 = fmaxf(mstate[mt][1], r1max);
            float corr0 = __expf(mstate[mt][0] - mnew0);
            float corr1 = __expf(mstate[mt][1] - mnew1);
            mstate[mt][0] = mnew0; mstate[mt][1] = mnew1;

            float rs0 = 0.f, rs1 = 0.f;
            #pragma unroll
            for (int nt=0; nt<8; nt++) {
                float p0 = __expf(sacc[nt][0] - mnew0);
                float p1 = __expf(sacc[nt][1] - mnew0);
                float p2 = __expf(sacc[nt][2] - mnew1);
                float p3 = __expf(sacc[nt][3] - mnew1);
                rs0 += p0 + p1; rs1 += p2 + p3;
                *(float2*)(Ps + qr*PS_STRIDE + nt*8 + 2*qc)     = make_float2(to_tf32(p0), to_tf32(p1));
                *(float2*)(Ps + (qr+8)*PS_STRIDE + nt*8 + 2*qc) = make_float2(to_tf32(p2), to_tf32(p3));
            }
            rs0 += __shfl_xor_sync(0xFFFFFFFFu, rs0, 1);
            rs0 += __shfl_xor_sync(0xFFFFFFFFu, rs0, 2);
            rs1 += __shfl_xor_sync(0xFFFFFFFFu, rs1, 1);
            rs1 += __shfl_xor_sync(0xFFFFFFFFu, rs1, 2);
            lstate[mt][0] = lstate[mt][0]*corr0 + rs0;
            lstate[mt][1] = lstate[mt][1]*corr1 + rs1;
            #pragma unroll
            for (int nt=0; nt<2; nt++) {
                oacc[mt][nt][0] *= corr0; oacc[mt][nt][1] *= corr0;
                oacc[mt][nt][2] *= corr1; oacc[mt][nt][3] *= corr1;
            }
            __syncwarp();
            // --- O += P @ V ---
            #pragma unroll
            for (int ks=0; ks<8; ks++) {
                uint32_t a[4];
                a[0] = __float_as_uint(Ps[qr*PS_STRIDE + ks*8 + qc]);
                a[1] = __float_as_uint(Ps[(qr+8)*PS_STRIDE + ks*8 + qc]);
                a[2] = __float_as_uint(Ps[qr*PS_STRIDE + ks*8 + qc + 4]);
                a[3] = __float_as_uint(Ps[(qr+8)*PS_STRIDE + ks*8 + qc + 4]);
                #pragma unroll
                for (int nt=0; nt<2; nt++) {
                    uint32_t b0 = __float_as_uint(Vs[(kb + ks*8 + qc)*VS_STRIDE + nt*8 + qr]);
                    uint32_t b1 = __float_as_uint(Vs[(kb + ks*8 + qc + 4)*VS_STRIDE + nt*8 + qr]);
                    MMA_TF32(oacc[mt][nt], a, b0, b1);
                }
            }
            __syncwarp();
        }
    }

    // epilogue: normalize and write (tf32-rounded; feeds tf32 GEMM)
    #pragma unroll
    for (int mt=0; mt<2; mt++) {
        float inv0 = 1.f/lstate[mt][0];
        float inv1 = 1.f/lstate[mt][1];
        int row0 = q0 + mt*16 + qr;
        #pragma unroll
        for (int nt=0; nt<2; nt++) {
            int col = h*HD + nt*8 + 2*qc;
            float* o0 = ao + ((size_t)b*T_SEQ + row0)*D + col;
            float* o1 = ao + ((size_t)b*T_SEQ + row0 + 8)*D + col;
            *(float2*)o0 = make_float2(to_tf32(oacc[mt][nt][0]*inv0), to_tf32(oacc[mt][nt][1]*inv0));
            *(float2*)o1 = make_float2(to_tf32(oacc[mt][nt][2]*inv1), to_tf32(oacc[mt][nt][3]*inv1));
        }
    }
}

// ---------------- cross-attention (folded): xo += softmax(h@K'^T/32) @ V' -------
__global__ __launch_bounds__(256) void cross_attn_kernel(
    const float* __restrict__ Q, const float* __restrict__ Km,
    const float* __restrict__ Vm, float* __restrict__ xo)
{
    extern __shared__ float smem[];
    float* Ks = smem;
    float* Vs = smem + NMEM*D;
    int b = blockIdx.x >> 2;
    int chunk = blockIdx.x & 3;
    for (int i=threadIdx.x; i<NMEM*D; i+=256) {
        Ks[i] = Km[(size_t)b*NMEM*D + i];
        Vs[i] = Vm[(size_t)b*NMEM*D + i];
    }
    __syncthreads();
    int t = chunk*256 + threadIdx.x;
    const float4* qrow = (const float4*)(Q + ((size_t)b*T_SEQ + t)*D);
    float s[16];
    #pragma unroll
    for (int mm=0;mm<16;mm++) s[mm]=0.f;
    for (int k4=0;k4<D/4;k4++) {
        float4 qv = qrow[k4];
        #pragma unroll
        for (int mm=0;mm<16;mm++) {
            const float* kr = Ks + mm*D + k4*4;
            s[mm] += qv.x*kr[0] + qv.y*kr[1] + qv.z*kr[2] + qv.w*kr[3];
        }
    }
    float mx = -1e30f;
    #pragma unroll
    for (int mm=0;mm<16;mm++) { s[mm] *= 0.03125f; mx = fmaxf(mx, s[mm]); }
    float sum = 0.f;
    #pragma unroll
    for (int mm=0;mm<16;mm++) { s[mm] = __expf(s[mm]-mx); sum += s[mm]; }
    float inv = 1.f/sum;
    #pragma unroll
    for (int mm=0;mm<16;mm++) s[mm] *= inv;
    float* xrow = xo + ((size_t)b*T_SEQ + t)*D;
    for (int c=0;c<D;c+=4) {
        float4 o = *(const float4*)(xrow + c);
        #pragma unroll
        for (int mm=0;mm<16;mm++) {
            const float* vr = Vs + mm*D + c;
            o.x += s[mm]*vr[0]; o.y += s[mm]*vr[1];
            o.z += s[mm]*vr[2]; o.w += s[mm]*vr[3];
        }
        *(float4*)(xrow + c) = o;
    }
}

// ---------------- memory path -------------------------------------------------
__global__ __launch_bounds__(256) void mean_kernel(const float* __restrict__ x,
                                                   float* __restrict__ mh) {
    __shared__ float sred[256];
    int b = blockIdx.x, cb = blockIdx.y*128;
    int c = threadIdx.x & 127, half = threadIdx.x >> 7;
    const float* p = x + (size_t)b*T_SEQ*D + (size_t)half*512*D + cb + c;
    float s = 0.f;
    #pragma unroll 4
    for (int t=0;t<512;t++) s += p[(size_t)t*D];
    sred[threadIdx.x] = s;
    __syncthreads();
    if (half == 0)
        mh[b*D + cb + c] = (sred[threadIdx.x] + sred[threadIdx.x+128]) * (1.f/T_SEQ);
}

__global__ __launch_bounds__(256) void base_gemv(
    const float* __restrict__ Wz, const float* __restrict__ Wr, const float* __restrict__ Wc,
    const float* __restrict__ bz, const float* __restrict__ br, const float* __restrict__ bc)
{
    int gid = blockIdx.x*8 + (threadIdx.x >> 5);
    int lane = threadIdx.x & 31;
    int g = gid >> 12;
    int rem = gid & 4095;
    int b = rem >> 10;
    int col = rem & 1023;
    const float* W    = (g==0) ? Wz : ((g==1) ? Wr : Wc);
    const float* bias = (g==0) ? bz : ((g==1) ? br : bc);
    const float* wrow = W + (size_t)col*2048;
    const float* mrow = g_meanh + b*D;
    float acc = 0.f;
    #pragma unroll
    for (int k0=0;k0<1024;k0+=128) {
        float4 w = *(const float4*)(wrow + k0 + lane*4);
        float4 m = *(const float4*)(mrow + k0 + lane*4);
        acc += w.x*m.x + w.y*m.y + w.z*m.z + w.w*m.w;
    }
    #pragma unroll
    for (int o=16;o;o>>=1) acc += __shfl_xor_sync(0xFFFFFFFFu, acc, o);
    if (lane == 0) g_base[gid] = acc + bias[col];
}

__device__ __forceinline__ void tile64x64(
    const float* __restrict__ A, const float* __restrict__ B, int ldb,
    float (&acc)[4][4])
{
    __shared__ float As[32][65];
    __shared__ float Bs[32][65];
    const int tid = threadIdx.x;
    const int r  = tid >> 2;
    const int kq = (tid & 3) << 3;
    const int tx = tid & 15;
    const int ty = tid >> 4;
    for (int k0 = 0; k0 < 1024; k0 += 32) {
        float4 a0 = *(const float4*)(A + (size_t)r*1024 + k0 + kq);
        float4 a1 = *(const float4*)(A + (size_t)r*1024 + k0 + kq + 4);
        float4 b0 = *(const float4*)(B + (size_t)r*ldb  + k0 + kq);
        float4 b1 = *(const float4*)(B + (size_t)r*ldb  + k0 + kq + 4);
        __syncthreads();
        As[kq+0][r]=a0.x; As[kq+1][r]=a0.y; As[kq+2][r]=a0.z; As[kq+3][r]=a0.w;
        As[kq+4][r]=a1.x; As[kq+5][r]=a1.y; As[kq+6][r]=a1.z; As[kq+7][r]=a1.w;
        Bs[kq+0][r]=b0.x; Bs[kq+1][r]=b0.y; Bs[kq+2][r]=b0.z; Bs[kq+3][r]=b0.w;
        Bs[kq+4][r]=b1.x; Bs[kq+5][r]=b1.y; Bs[kq+6][r]=b1.z; Bs[kq+7][r]=b1.w;
        __syncthreads();
        #pragma unroll
        for (int kk=0;kk<32;kk++) {
            float a[4], b[4];
            #pragma unroll
            for (int i=0;i<4;i++) a[i] = As[kk][ty*4+i];
            #pragma unroll
            for (int j=0;j<4;j++) b[j] = Bs[kk][tx*4+j];
            #pragma unroll
            for (int i=0;i<4;i++)
                #pragma unroll
                for (int j=0;j<4;j++) acc[i][j] += a[i]*b[j];
        }
    }
}

// raw pre-activations from memory-half of Wz/Wr (no mean dependence)
__global__ __launch_bounds__(256) void zr_pre(
    const float* __restrict__ mem, const float* __restrict__ Wz,
    const float* __restrict__ Wr)
{
    int g = blockIdx.y;
    int ct = blockIdx.x;
    const float* W = (g ? Wr : Wz) + (size_t)(ct*64)*2048 + 1024;
    float acc[4][4];
    #pragma unroll
    for (int i=0;i<4;i++)
        #pragma unroll
        for (int j=0;j<4;j++) acc[i][j]=0.f;
    tile64x64(mem, W, 2048, acc);
    float* out = g ? g_rpre : g_zpre;
    const int tx = threadIdx.x & 15, ty = threadIdx.x >> 4;
    #pragma unroll
    for (int i=0;i<4;i++) {
        int row = ty*4+i;
        #pragma unroll
        for (int j=0;j<4;j++) out[row*1024 + ct*64 + tx*4+j] = acc[i][j];
    }
}

// z = sigmoid(zpre+base_z); rm = sigmoid(rpre+base_r)*memory
__global__ void combine_kernel(const float* __restrict__ mem) {
    int idx = blockIdx.x*blockDim.x + threadIdx.x;   // 0..65535
    int row = idx >> 10, col = idx & 1023, b = row >> 4;
    float z = 1.f/(1.f + __expf(-(g_zpre[idx] + g_base[0*4096 + b*1024 + col])));
    float r = 1.f/(1.f + __expf(-(g_rpre[idx] + g_base[1*4096 + b*1024 + col])));
    g_z[idx] = z;
    g_rm[idx] = r * mem[idx];
}

__global__ __launch_bounds__(256) void c_gemm(
    const float* __restrict__ mem, const float* __restrict__ Wc,
    float* __restrict__ newmem)
{
    int ct = blockIdx.x;
    const float* W = Wc + (size_t)(ct*64)*2048 + 1024;
    float acc[4][4];
    #pragma unroll
    for (int i=0;i<4;i++)
        #pragma unroll
        for (int j=0;j<4;j++) acc[i][j]=0.f;
    tile64x64(g_rm, W, 2048, acc);
    const int tx = threadIdx.x & 15, ty = threadIdx.x >> 4;
    #pragma unroll
    for (int i=0;i<4;i++) {
        int row = ty*4+i;
        #pragma unroll
        for (int j=0;j<4;j++) {
            int col = ct*64 + tx*4+j;
            float v = acc[i][j] + g_base[2*4096 + (row>>4)*1024 + col];
            float c = tanhf(v);
            float z = g_z[row*1024+col];
            newmem[(size_t)row*1024+col] = (1.f - z)*mem[(size_t)row*1024+col] + z*c;
        }
    }
}

// K' = newmem @ Wk'^T ; V' = newmem @ Wv'^T
__global__ __launch_bounds__(256) void kv2_gemm(const float* __restrict__ newmem)
{
    int which = blockIdx.y;
    int ct = blockIdx.x;
    const float* W = (which ? g_wv : g_wk) + (size_t)(ct*64)*1024;
    float acc[4][4];
    #pragma unroll
    for (int i=0;i<4;i++)
        #pragma unroll
        for (int j=0;j<4;j++) acc[i][j]=0.f;
    tile64x64(newmem, W, 1024, acc);
    float* out = which ? g_V : g_K;
    const int tx = threadIdx.x & 15, ty = threadIdx.x >> 4;
    #pragma unroll
    for (int i=0;i<4;i++) {
        int row = ty*4+i;
        #pragma unroll
        for (int j=0;j<4;j++) {
            int col = ct*64 + tx*4+j;
            out[(size_t)row*1024+col] = acc[i][j];
        }
    }
}

// ---------------- host launcher -------------------------------------------------
extern "C" void kernel_launch(void* const* d_in, const int* in_sizes, int n_in,
                              void* d_out, int out_size)
{
    const float* x          = (const float*)d_in[0];
    const float* memory     = (const float*)d_in[1];
    const float* ln1_g      = (const float*)d_in[2];
    const float* ln1_b      = (const float*)d_in[3];
    const float* ln2_g      = (const float*)d_in[4];
    const float* ln2_b      = (const float*)d_in[5];
    const float* ln3_g      = (const float*)d_in[6];
    const float* ln3_b      = (const float*)d_in[7];
    const float* in_proj_w  = (const float*)d_in[8];
    const float* in_proj_b  = (const float*)d_in[9];
    const float* attn_out_w = (const float*)d_in[10];
    const float* attn_out_b = (const float*)d_in[11];
    const float* Wz_w       = (const float*)d_in[12];
    const float* Wz_b       = (const float*)d_in[13];
    const float* Wr_w       = (const float*)d_in[14];
    const float* Wr_b       = (const float*)d_in[15];
    const float* Wc_w       = (const float*)d_in[16];
    const float* Wc_b       = (const float*)d_in[17];
    const float* mq_w       = (const float*)d_in[18];
    const float* mk_w       = (const float*)d_in[19];
    const float* mv_w       = (const float*)d_in[20];
    const float* mo_w       = (const float*)d_in[21];
    const float* W1         = (const float*)d_in[22];
    const float* b1         = (const float*)d_in[23];
    const float* W2         = (const float*)d_in[24];
    const float* b2         = (const float*)d_in[25];

    float* xo = (float*)d_out;
    float* newmem = xo + (size_t)ROWS*D;

    float *p_h, *p_qkv, *p_ao, *p_ffn, *p_K, *p_V, *p_w, *p_mh, *p_wk, *p_wv;
    cudaGetSymbolAddress((void**)&p_h,    g_h);
    cudaGetSymbolAddress((void**)&p_qkv,  g_qkv);
    cudaGetSymbolAddress((void**)&p_ao,   g_ao);
    cudaGetSymbolAddress((void**)&p_ffn,  g_ffn);
    cudaGetSymbolAddress((void**)&p_K,    g_K);
    cudaGetSymbolAddress((void**)&p_V,    g_V);
    cudaGetSymbolAddress((void**)&p_w,    g_w);
    cudaGetSymbolAddress((void**)&p_mh,   g_meanh);
    cudaGetSymbolAddress((void**)&p_wk,   g_wk);
    cudaGetSymbolAddress((void**)&p_wv,   g_wv);

    static cudaStream_t s2 = nullptr;
    static cudaEvent_t evStart = nullptr, evCvt = nullptr, evFork = nullptr, evMem = nullptr;
    static bool tried = false, ok = false;
    if (!tried) {
        tried = true;
        ok = (cudaStreamCreateWithFlags(&s2, cudaStreamNonBlocking) == cudaSuccess) &&
             (cudaEventCreateWithFlags(&evStart, cudaEventDisableTiming) == cudaSuccess) &&
             (cudaEventCreateWithFlags(&evCvt,   cudaEventDisableTiming) == cudaSuccess) &&
             (cudaEventCreateWithFlags(&evFork,  cudaEventDisableTiming) == cudaSuccess) &&
             (cudaEventCreateWithFlags(&evMem,   cudaEventDisableTiming) == cudaSuccess);
    }
    cudaStream_t sb = ok ? s2 : (cudaStream_t)0;

    cudaFuncSetAttribute(flash_attn_kernel, cudaFuncAttributeMaxDynamicSharedMemorySize, FLASH_SMEM);
    cudaFuncSetAttribute(cross_attn_kernel, cudaFuncAttributeMaxDynamicSharedMemorySize, 131072);
    const int GSM = SMEM_FLOATS * 4;
    cudaFuncSetAttribute(gemm_tf32<0,1,0,0>, cudaFuncAttributeMaxDynamicSharedMemorySize, GSM);
    cudaFuncSetAttribute(gemm_tf32<0,1,1,0>, cudaFuncAttributeMaxDynamicSharedMemorySize, GSM);
    cudaFuncSetAttribute(gemm_tf32<0,0,0,0>, cudaFuncAttributeMaxDynamicSharedMemorySize, GSM);
    cudaFuncSetAttribute(gemm_tf32<1,1,0,1>, cudaFuncAttributeMaxDynamicSharedMemorySize, GSM);

    // ---- early hidden phase on sb ----
    if (ok) { cudaEventRecord(evStart, 0); cudaStreamWaitEvent(sb, evStart, 0); }
    cvt_tf32_kernel<<<3072, 256, 0, sb>>>(in_proj_w,  p_w + OFF_INP,  3*1024*1024/4);
    cvt_tf32_kernel<<<1024, 256, 0, sb>>>(attn_out_w, p_w + OFF_AOUT, 1024*1024/4);
    cvt_tf32_kernel<<<4096, 256, 0, sb>>>(W1,         p_w + OFF_W1,   4*1024*1024/4);
    cvt_tf32_kernel<<<4096, 256, 0, sb>>>(W2,         p_w + OFF_W2,   4*1024*1024/4);
    if (ok) cudaEventRecord(evCvt, sb);
    cvt_tf32_kernel<<<1024, 256, 0, sb>>>(mo_w, p_w + OFF_MO, 1024*1024/4);
    transpose_tf32<<<dim3(32,32), dim3(32,8), 0, sb>>>(mq_w, p_w + OFF_MQT);
    transpose_tf32<<<dim3(32,32), dim3(32,8), 0, sb>>>(mk_w, p_w + OFF_MKT);
    transpose_tf32<<<dim3(32,32), dim3(32,8), 0, sb>>>(mv_w, p_w + OFF_MVT);
    gemm_tf32<0,0,0,0><<<dim3(8,8), 256, GSM, sb>>>(p_w + OFF_MQT, p_w + OFF_MKT, nullptr, nullptr, p_wk, 1024, 1024, 1024);
    gemm_tf32<0,0,0,0><<<dim3(8,8), 256, GSM, sb>>>(p_w + OFF_MO,  p_w + OFF_MVT, nullptr, nullptr, p_wv, 1024, 1024, 1024);
    zr_pre<<<dim3(16,2), 256, 0, sb>>>(memory, Wz_w, Wr_w);

    // ---- main path ----
    ln_kernel<<<ROWS, 256>>>(x, ln1_g, ln1_b, p_h);
    if (ok) cudaStreamWaitEvent(0, evCvt, 0);

    gemm_tf32<0,1,0,0><<<dim3(3*D/128, ROWS/128), 256, GSM>>>(p_h, p_w + OFF_INP, in_proj_b, nullptr, p_qkv, ROWS, 3*D, D);
    flash_attn_kernel<<<dim3(BATCH*NHEADS, 4), 256, FLASH_SMEM>>>(p_qkv, p_ao);
    gemm_tf32<0,1,1,0><<<dim3(D/128, ROWS/128), 256, GSM>>>(p_ao, p_w + OFF_AOUT, attn_out_b, x, xo, ROWS, D, D);

    // ---- fork memory path onto sb ----
    if (ok) { cudaEventRecord(evFork, 0); cudaStreamWaitEvent(sb, evFork, 0); }
    mean_kernel<<<dim3(BATCH, 8), 256, 0, sb>>>(xo, p_mh);
    base_gemv<<<1536, 256, 0, sb>>>(Wz_w, Wr_w, Wc_w, Wz_b, Wr_b, Wc_b);
    combine_kernel<<<BATCH*NMEM*D/256, 256, 0, sb>>>(memory);
    c_gemm<<<16, 256, 0, sb>>>(memory, Wc_w, newmem);
    kv2_gemm<<<dim3(16, 2), 256, 0, sb>>>(newmem);
    if (ok) cudaEventRecord(evMem, sb);

    // ---- main path: LN2, then folded cross-attention (in-place residual) ----
    ln_kernel<<<ROWS, 256>>>(xo, ln2_g, ln2_b, p_h);
    if (ok) cudaStreamWaitEvent(0, evMem, 0);
    cross_attn_kernel<<<BATCH*4, 256, 131072>>>(p_h, p_K, p_V, xo);

    // FFN
    ln_kernel<<<ROWS, 256>>>(xo, ln3_g, ln3_b, p_h);
    gemm_tf32<1,1,0,1><<<dim3(4*D/128, ROWS/128), 256, GSM>>>(p_h, p_w + OFF_W1, b1, nullptr, p_ffn, ROWS, 4*D, D);
    gemm_tf32<0,1,1,0><<<dim3(D/128, ROWS/128), 256, GSM>>>(p_ffn, p_w + OFF_W2, b2, xo, xo, ROWS, D, 4*D);
}

// round 11
// speedup vs baseline: 4.5371x; 1.2313x over previous
#include <cuda_runtime.h>
#include <cuda_fp16.h>
#include <math.h>
#include <stdint.h>

#define D 1024
#define T_SEQ 1024
#define BATCH 4
#define NMEM 16
#define NHEADS 64
#define HD 16
#define ROWS (BATCH*T_SEQ)   // 4096

// ---------------- scratch (device globals; no runtime allocation) ----------------
__device__ float g_h[ROWS*D];            // LN2 output (float, feeds cross-attn)
__device__ __half h_h[ROWS*D];           // LN1/LN3 outputs (fp16, feeds fp16 GEMMs)
__device__ float g_qkv[ROWS*3*D];
__device__ __half h_ao[ROWS*D];          // self-attention output (fp16)
__device__ __half h_ffn[ROWS*4*D];       // FFN hidden (fp16)
__device__ float g_meanh[BATCH*D];
__device__ float g_base[3*BATCH*D];
__device__ float g_zpre[BATCH*NMEM*D];
__device__ float g_rpre[BATCH*NMEM*D];
__device__ float g_z[BATCH*NMEM*D];
__device__ float g_rm[BATCH*NMEM*D];
__device__ float g_K[BATCH*NMEM*D];
__device__ float g_V[BATCH*NMEM*D];
__device__ float g_wk[1024*1024];        // Wk' = mq^T @ mk
__device__ float g_wv[1024*1024];        // Wv' = mo @ mv
__device__ float g_w[8*1024*1024];       // float scratch for fold path
__device__ __half h_w[12*1024*1024];     // fp16 weight copies

// float scratch offsets (fold path)
#define OFF_MQT   0
#define OFF_MO    (1*1024*1024)
#define OFF_MKT   (2*1024*1024)
#define OFF_MVT   (3*1024*1024)
// fp16 weight offsets
#define HOFF_INP  0
#define HOFF_AOUT (3*1024*1024)
#define HOFF_W1   (4*1024*1024)
#define HOFF_W2   (8*1024*1024)

__device__ __forceinline__ float to_tf32(float v) {
    uint32_t r;
    asm("cvt.rna.tf32.f32 %0, %1;" : "=r"(r) : "f"(v));
    return __uint_as_float(r);
}

// ---------------- utility kernels ----------------
__global__ void cvt_tf32_kernel(const float* __restrict__ src, float* __restrict__ dst, int n4) {
    int i = blockIdx.x*blockDim.x + threadIdx.x;
    if (i < n4) {
        float4 v = ((const float4*)src)[i];
        v.x = to_tf32(v.x); v.y = to_tf32(v.y); v.z = to_tf32(v.z); v.w = to_tf32(v.w);
        ((float4*)dst)[i] = v;
    }
}

__global__ void cvt_fp16_kernel(const float* __restrict__ src, __half* __restrict__ dst, int n4) {
    int i = blockIdx.x*blockDim.x + threadIdx.x;
    if (i < n4) {
        float4 v = ((const float4*)src)[i];
        half2 lo = __floats2half2_rn(v.x, v.y);
        half2 hi = __floats2half2_rn(v.z, v.w);
        ((half2*)dst)[2*i]   = lo;
        ((half2*)dst)[2*i+1] = hi;
    }
}

__global__ __launch_bounds__(256) void transpose_tf32(
    const float* __restrict__ src, float* __restrict__ dst)
{
    __shared__ float tile[32][33];
    int x = blockIdx.x*32 + threadIdx.x;
    int y0 = blockIdx.y*32 + threadIdx.y;
    #pragma unroll
    for (int i=0;i<32;i+=8)
        tile[threadIdx.y+i][threadIdx.x] = src[(size_t)(y0+i)*1024 + x];
    __syncthreads();
    int x2 = blockIdx.y*32 + threadIdx.x;
    int y2 = blockIdx.x*32 + threadIdx.y;
    #pragma unroll
    for (int i=0;i<32;i+=8)
        dst[(size_t)(y2+i)*1024 + x2] = to_tf32(tile[threadIdx.x][threadIdx.y+i]);
}

// LayerNorm -> float output (LN2, feeds scalar cross-attn)
__global__ __launch_bounds__(256) void ln_kernel(
    const float* __restrict__ x, const float* __restrict__ g,
    const float* __restrict__ b, float* __restrict__ y)
{
    __shared__ float s1[256], s2[256];
    int row = blockIdx.x;
    const float4* xr = (const float4*)(x + (size_t)row*D);
    float4 v = xr[threadIdx.x];
    float sum = v.x+v.y+v.z+v.w;
    float sq  = v.x*v.x + v.y*v.y + v.z*v.z + v.w*v.w;
    s1[threadIdx.x]=sum; s2[threadIdx.x]=sq;
    __syncthreads();
    for (int off=128; off; off>>=1) {
        if (threadIdx.x < off) {
            s1[threadIdx.x]+=s1[threadIdx.x+off];
            s2[threadIdx.x]+=s2[threadIdx.x+off];
        }
        __syncthreads();
    }
    float mean = s1[0]*(1.0f/D);
    float var  = s2[0]*(1.0f/D) - mean*mean;
    float rstd = rsqrtf(var + 1e-5f);
    int c = threadIdx.x*4;
    float4 gg = *(const float4*)(g+c);
    float4 bb = *(const float4*)(b+c);
    float4 o;
    o.x = (v.x-mean)*rstd*gg.x + bb.x;
    o.y = (v.y-mean)*rstd*gg.y + bb.y;
    o.z = (v.z-mean)*rstd*gg.z + bb.z;
    o.w = (v.w-mean)*rstd*gg.w + bb.w;
    ((float4*)(y + (size_t)row*D))[threadIdx.x] = o;
}

// LayerNorm -> fp16 output (LN1/LN3, feeds fp16 GEMMs)
__global__ __launch_bounds__(256) void ln_kernel_h(
    const float* __restrict__ x, const float* __restrict__ g,
    const float* __restrict__ b, __half* __restrict__ y)
{
    __shared__ float s1[256], s2[256];
    int row = blockIdx.x;
    const float4* xr = (const float4*)(x + (size_t)row*D);
    float4 v = xr[threadIdx.x];
    float sum = v.x+v.y+v.z+v.w;
    float sq  = v.x*v.x + v.y*v.y + v.z*v.z + v.w*v.w;
    s1[threadIdx.x]=sum; s2[threadIdx.x]=sq;
    __syncthreads();
    for (int off=128; off; off>>=1) {
        if (threadIdx.x < off) {
            s1[threadIdx.x]+=s1[threadIdx.x+off];
            s2[threadIdx.x]+=s2[threadIdx.x+off];
        }
        __syncthreads();
    }
    float mean = s1[0]*(1.0f/D);
    float var  = s2[0]*(1.0f/D) - mean*mean;
    float rstd = rsqrtf(var + 1e-5f);
    int c = threadIdx.x*4;
    float4 gg = *(const float4*)(g+c);
    float4 bb = *(const float4*)(b+c);
    half2 lo = __floats2half2_rn((v.x-mean)*rstd*gg.x + bb.x, (v.y-mean)*rstd*gg.y + bb.y);
    half2 hi = __floats2half2_rn((v.z-mean)*rstd*gg.z + bb.z, (v.w-mean)*rstd*gg.w + bb.w);
    half2* yr = (half2*)(y + (size_t)row*D);
    yr[threadIdx.x*2]   = lo;
    yr[threadIdx.x*2+1] = hi;
}

__device__ __forceinline__ void cp16(uint32_t dst, const void* src) {
    asm volatile("cp.async.cg.shared.global [%0], [%1], 16;" :: "r"(dst), "l"(src));
}

// ---------------- fp16 tensor-core GEMM: C(M,N) = A(M,K) @ B(N,K)^T -------------
// m16n8k16 HMMA, fp32 accum. 128x128 tile, BK=32, 2-stage cp.async.
// smem rows of 40 halves (80B stride: 16B-aligned, conflict-free frag loads).
#define HA_OFF(buf) ((buf)*10240)
#define HB_OFF(buf) (5120 + (buf)*10240)
#define HSMEM_BYTES (20480*2)

template<int ACT, int BIASF, int RESF, int OUTHALF>
__global__ __launch_bounds__(256, 2) void gemm_fp16(
    const __half* __restrict__ A, const __half* __restrict__ B,
    const float* __restrict__ bias, const float* __restrict__ res,
    void* __restrict__ Cv, int M, int N, int K)
{
    extern __shared__ __half hsm[];
    float* Cf = (float*)Cv;
    __half* Ch = (__half*)Cv;
    const int tid = threadIdx.x;
    const int bm = blockIdx.y * 128;
    const int bn = blockIdx.x * 128;
    const int lane = tid & 31;
    const int warp = tid >> 5;
    const int wm64 = (warp & 1) * 64;
    const int wn32 = (warp >> 1) * 32;
    const int qr = lane >> 2;
    const int qc = lane & 3;
    uint32_t smem_u32 = (uint32_t)__cvta_generic_to_shared(hsm);

    float acc[4][4][4];
    #pragma unroll
    for (int i=0;i<4;i++)
        #pragma unroll
        for (int j=0;j<4;j++)
            #pragma unroll
            for (int e=0;e<4;e++) acc[i][j][e] = 0.f;

    const int NT = K >> 5;

    // prologue
    {
        const __half* Ab = A + (size_t)bm*K;
        const __half* Bb = B + (size_t)bn*K;
        #pragma unroll
        for (int rep=0; rep<2; rep++) {
            int idx = rep*256 + tid;
            int row = idx >> 2, seg = idx & 3;
            cp16(smem_u32 + (HA_OFF(0) + row*40 + seg*8)*2, Ab + (size_t)row*K + seg*8);
            cp16(smem_u32 + (HB_OFF(0) + row*40 + seg*8)*2, Bb + (size_t)row*K + seg*8);
        }
        asm volatile("cp.async.commit_group;");
    }

    for (int t = 0; t < NT; t++) {
        if (t + 1 < NT) {
            int buf = (t+1) & 1;
            int kb = (t+1) << 5;
            const __half* Ab = A + (size_t)bm*K + kb;
            const __half* Bb = B + (size_t)bn*K + kb;
            #pragma unroll
            for (int rep=0; rep<2; rep++) {
                int idx = rep*256 + tid;
                int row = idx >> 2, seg = idx & 3;
                cp16(smem_u32 + (HA_OFF(buf) + row*40 + seg*8)*2, Ab + (size_t)row*K + seg*8);
                cp16(smem_u32 + (HB_OFF(buf) + row*40 + seg*8)*2, Bb + (size_t)row*K + seg*8);
            }
            asm volatile("cp.async.commit_group;");
            asm volatile("cp.async.wait_group 1;");
        } else {
            asm volatile("cp.async.wait_group 0;");
        }
        __syncthreads();

        const __half* sA = hsm + HA_OFF(t & 1);
        const __half* sB = hsm + HB_OFF(t & 1);

        #pragma unroll
        for (int ks = 0; ks < 2; ks++) {
            const int k0 = ks * 16;
            uint32_t a[4][4], b[4][2];
            #pragma unroll
            for (int i=0;i<4;i++) {
                int r = wm64 + i*16 + qr;
                a[i][0] = *(const uint32_t*)(sA + r*40 + k0 + 2*qc);
                a[i][1] = *(const uint32_t*)(sA + (r+8)*40 + k0 + 2*qc);
                a[i][2] = *(const uint32_t*)(sA + r*40 + k0 + 2*qc + 8);
                a[i][3] = *(const uint32_t*)(sA + (r+8)*40 + k0 + 2*qc + 8);
            }
            #pragma unroll
            for (int j=0;j<4;j++) {
                int n = wn32 + j*8 + qr;
                b[j][0] = *(const uint32_t*)(sB + n*40 + k0 + 2*qc);
                b[j][1] = *(const uint32_t*)(sB + n*40 + k0 + 2*qc + 8);
            }
            #pragma unroll
            for (int i=0;i<4;i++)
                #pragma unroll
                for (int j=0;j<4;j++) {
                    asm volatile(
                        "mma.sync.aligned.m16n8k16.row.col.f32.f16.f16.f32 "
                        "{%0,%1,%2,%3}, {%4,%5,%6,%7}, {%8,%9}, {%0,%1,%2,%3};"
                        : "+f"(acc[i][j][0]), "+f"(acc[i][j][1]),
                          "+f"(acc[i][j][2]), "+f"(acc[i][j][3])
                        : "r"(a[i][0]), "r"(a[i][1]), "r"(a[i][2]), "r"(a[i][3]),
                          "r"(b[j][0]), "r"(b[j][1]));
                }
        }
        __syncthreads();
    }

    #pragma unroll
    for (int i=0;i<4;i++) {
        int row0 = bm + wm64 + i*16 + qr;
        #pragma unroll
        for (int j=0;j<4;j++) {
            int col0 = bn + wn32 + j*8 + qc*2;
            float v0 = acc[i][j][0], v1 = acc[i][j][1];
            float v2 = acc[i][j][2], v3 = acc[i][j][3];
            if (BIASF) {
                float b0 = bias[col0], b1 = bias[col0+1];
                v0 += b0; v1 += b1; v2 += b0; v3 += b1;
            }
            if (ACT == 1) {
                v0 = 0.5f*v0*(1.f + erff(v0*0.70710678118654752f));
                v1 = 0.5f*v1*(1.f + erff(v1*0.70710678118654752f));
                v2 = 0.5f*v2*(1.f + erff(v2*0.70710678118654752f));
                v3 = 0.5f*v3*(1.f + erff(v3*0.70710678118654752f));
            }
            if (RESF) {
                v0 += res[(size_t)row0*N + col0];
                v1 += res[(size_t)row0*N + col0 + 1];
                v2 += res[(size_t)(row0+8)*N + col0];
                v3 += res[(size_t)(row0+8)*N + col0 + 1];
            }
            if (OUTHALF) {
                *(half2*)(Ch + (size_t)row0*N + col0)     = __floats2half2_rn(v0, v1);
                *(half2*)(Ch + (size_t)(row0+8)*N + col0) = __floats2half2_rn(v2, v3);
            } else {
                *(float2*)(Cf + (size_t)row0*N + col0)     = make_float2(v0, v1);
                *(float2*)(Cf + (size_t)(row0+8)*N + col0) = make_float2(v2, v3);
            }
        }
    }
}

// ---------------- legacy mma.sync tf32 GEMM (hidden weight-fold GEMMs) ----------
#define SMEM_FLOATS (4*4608)
#define A_OFFS(buf) ((buf)*4608)
#define B_OFFS(buf) (9216 + (buf)*4608)

template<int ACT, int BIASF, int RESF, int TF32OUT>
__global__ __launch_bounds__(256, 2) void gemm_tf32(
    const float* __restrict__ A, const float* __restrict__ B,
    const float* __restrict__ bias, const float* __restrict__ res,
    float* __restrict__ C, int M, int N, int K)
{
    extern __shared__ float sm[];
    const int tid = threadIdx.x;
    const int bm = blockIdx.y * 128;
    const int bn = blockIdx.x * 128;
    const int lane = tid & 31;
    const int warp = tid >> 5;
    const int wm64 = (warp & 1) * 64;
    const int wn32 = (warp >> 1) * 32;
    const int qr = lane >> 2;
    const int qc = lane & 3;
    uint32_t smem_u32 = (uint32_t)__cvta_generic_to_shared(sm);
    const int lrow = tid >> 3;
    const int lkq  = (tid & 7) * 4;

    float acc[4][4][4];
    #pragma unroll
    for (int i=0;i<4;i++)
        #pragma unroll
        for (int j=0;j<4;j++)
            #pragma unroll
            for (int e=0;e<4;e++) acc[i][j][e] = 0.f;

    const int NT = K >> 5;
    {
        const float* Ab = A + (size_t)bm*K;
        const float* Bb = B + (size_t)bn*K;
        #pragma unroll
        for (int rep=0; rep<4; rep++) {
            int row = rep*32 + lrow;
            cp16(smem_u32 + (A_OFFS(0) + row*36 + lkq)*4, Ab + (size_t)row*K + lkq);
            cp16(smem_u32 + (B_OFFS(0) + row*36 + lkq)*4, Bb + (size_t)row*K + lkq);
        }
        asm volatile("cp.async.commit_group;");
    }
    for (int t = 0; t < NT; t++) {
        if (t + 1 < NT) {
            int buf = (t+1) & 1;
            int kb = (t+1) << 5;
            const float* Ab = A + (size_t)bm*K + kb;
            const float* Bb = B + (size_t)bn*K + kb;
            #pragma unroll
            for (int rep=0; rep<4; rep++) {
                int row = rep*32 + lrow;
                cp16(smem_u32 + (A_OFFS(buf) + row*36 + lkq)*4, Ab + (size_t)row*K + lkq);
                cp16(smem_u32 + (B_OFFS(buf) + row*36 + lkq)*4, Bb + (size_t)row*K + lkq);
            }
            asm volatile("cp.async.commit_group;");
            asm volatile("cp.async.wait_group 1;");
        } else {
            asm volatile("cp.async.wait_group 0;");
        }
        __syncthreads();
        const float* sA = sm + A_OFFS(t & 1);
        const float* sB = sm + B_OFFS(t & 1);
        #pragma unroll
        for (int ks = 0; ks < 4; ks++) {
            const int k0 = ks * 8;
            uint32_t a[4][4], b[4][2];
            #pragma unroll
            for (int i=0;i<4;i++) {
                int r = wm64 + i*16 + qr;
                a[i][0] = __float_as_uint(sA[r*36 + k0 + qc]);
                a[i][1] = __float_as_uint(sA[(r+8)*36 + k0 + qc]);
                a[i][2] = __float_as_uint(sA[r*36 + k0 + qc + 4]);
                a[i][3] = __float_as_uint(sA[(r+8)*36 + k0 + qc + 4]);
            }
            #pragma unroll
            for (int j=0;j<4;j++) {
                int n = wn32 + j*8 + qr;
                b[j][0] = __float_as_uint(sB[n*36 + k0 + qc]);
                b[j][1] = __float_as_uint(sB[n*36 + k0 + qc + 4]);
            }
            #pragma unroll
            for (int i=0;i<4;i++)
                #pragma unroll
                for (int j=0;j<4;j++) {
                    asm volatile(
                        "mma.sync.aligned.m16n8k8.row.col.f32.tf32.tf32.f32 "
                        "{%0,%1,%2,%3}, {%4,%5,%6,%7}, {%8,%9}, {%0,%1,%2,%3};"
                        : "+f"(acc[i][j][0]), "+f"(acc[i][j][1]),
                          "+f"(acc[i][j][2]), "+f"(acc[i][j][3])
                        : "r"(a[i][0]), "r"(a[i][1]), "r"(a[i][2]), "r"(a[i][3]),
                          "r"(b[j][0]), "r"(b[j][1]));
                }
        }
        __syncthreads();
    }
    #pragma unroll
    for (int i=0;i<4;i++) {
        int row0 = bm + wm64 + i*16 + qr;
        #pragma unroll
        for (int j=0;j<4;j++) {
            int col0 = bn + wn32 + j*8 + qc*2;
            float v0 = acc[i][j][0], v1 = acc[i][j][1];
            float v2 = acc[i][j][2], v3 = acc[i][j][3];
            *(float2*)(C + (size_t)row0*N + col0)     = make_float2(v0, v1);
            *(float2*)(C + (size_t)(row0+8)*N + col0) = make_float2(v2, v3);
        }
    }
}

// ---------------- tensor-core flash self-attention (tf32 mma; fp16 output) -----
#define KS_STRIDE 20
#define VS_STRIDE 24
#define PS_STRIDE 68
#define FLASH_SMEM ((1024*KS_STRIDE + 1024*VS_STRIDE + 8*16*PS_STRIDE)*4)

#define MMA_TF32(acc, a, b0, b1) \
    asm volatile( \
        "mma.sync.aligned.m16n8k8.row.col.f32.tf32.tf32.f32 " \
        "{%0,%1,%2,%3}, {%4,%5,%6,%7}, {%8,%9}, {%0,%1,%2,%3};" \
        : "+f"((acc)[0]), "+f"((acc)[1]), "+f"((acc)[2]), "+f"((acc)[3]) \
        : "r"((a)[0]), "r"((a)[1]), "r"((a)[2]), "r"((a)[3]), \
          "r"(b0), "r"(b1))

__global__ __launch_bounds__(256) void flash_attn_kernel(
    const float* __restrict__ qkv, __half* __restrict__ ao)
{
    extern __shared__ float fsm[];
    float* Ks = fsm;
    float* Vs = fsm + 1024*KS_STRIDE;
    float* Ps = Vs + 1024*VS_STRIDE + (threadIdx.x >> 5)*16*PS_STRIDE;

    const int b = blockIdx.x >> 6;
    const int h = blockIdx.x & 63;
    const int qt = blockIdx.y;
    const int tid = threadIdx.x;
    const int lane = tid & 31;
    const int warp = tid >> 5;
    const int qr = lane >> 2;
    const int qc = lane & 3;

    const float* base = qkv + (size_t)b*T_SEQ*3*D + h*HD;

    for (int r = tid; r < T_SEQ; r += 256) {
        const float4* kr = (const float4*)(base + (size_t)r*3*D + D);
        const float4* vr = (const float4*)(base + (size_t)r*3*D + 2*D);
        #pragma unroll
        for (int i=0;i<4;i++) {
            float4 kv = kr[i], vv = vr[i];
            kv.x=to_tf32(kv.x); kv.y=to_tf32(kv.y); kv.z=to_tf32(kv.z); kv.w=to_tf32(kv.w);
            vv.x=to_tf32(vv.x); vv.y=to_tf32(vv.y); vv.z=to_tf32(vv.z); vv.w=to_tf32(vv.w);
            *(float4*)(Ks + r*KS_STRIDE + i*4) = kv;
            *(float4*)(Vs + r*VS_STRIDE + i*4) = vv;
        }
    }

    const int q0 = qt*256 + warp*32;
    uint32_t aQ[2][2][4];
    #pragma unroll
    for (int mt=0; mt<2; mt++)
        #pragma unroll
        for (int ks=0; ks<2; ks++) {
            int r0 = q0 + mt*16 + qr;
            int c0 = ks*8 + qc;
            aQ[mt][ks][0] = __float_as_uint(to_tf32(0.25f*base[(size_t)r0*3*D + c0]));
            aQ[mt][ks][1] = __float_as_uint(to_tf32(0.25f*base[(size_t)(r0+8)*3*D + c0]));
            aQ[mt][ks][2] = __float_as_uint(to_tf32(0.25f*base[(size_t)r0*3*D + c0+4]));
            aQ[mt][ks][3] = __float_as_uint(to_tf32(0.25f*base[(size_t)(r0+8)*3*D + c0+4]));
        }
    __syncthreads();

    float mstate[2][2], lstate[2][2], oacc[2][2][4];
    #pragma unroll
    for (int mt=0; mt<2; mt++) {
        mstate[mt][0] = -1e30f; mstate[mt][1] = -1e30f;
        lstate[mt][0] = 0.f;    lstate[mt][1] = 0.f;
        #pragma unroll
        for (int nt=0; nt<2; nt++)
            #pragma unroll
            for (int e=0; e<4; e++) oacc[mt][nt][e] = 0.f;
    }

    for (int nc = 0; nc < 16; nc++) {
        const int kb = nc*64;
        #pragma unroll
        for (int mt=0; mt<2; mt++) {
            float sacc[8][4];
            #pragma unroll
            for (int nt=0; nt<8; nt++)
                #pragma unroll
                for (int e=0; e<4; e++) sacc[nt][e] = 0.f;
            #pragma unroll
            for (int nt=0; nt<8; nt++) {
                const int key = kb + nt*8 + qr;
                #pragma unroll
                for (int ks=0; ks<2; ks++) {
                    uint32_t b0 = __float_as_uint(Ks[key*KS_STRIDE + ks*8 + qc]);
                    uint32_t b1 = __float_as_uint(Ks[key*KS_STRIDE + ks*8 + qc + 4]);
                    MMA_TF32(sacc[nt], aQ[mt][ks], b0, b1);
                }
            }
            float r0max = -1e30f, r1max = -1e30f;
            #pragma unroll
            for (int nt=0; nt<8; nt++) {
                r0max = fmaxf(r0max, fmaxf(sacc[nt][0], sacc[nt][1]));
                r1max = fmaxf(r1max, fmaxf(sacc[nt][2], sacc[nt][3]));
            }
            r0max = fmaxf(r0max, __shfl_xor_sync(0xFFFFFFFFu, r0max, 1));
            r0max = fmaxf(r0max, __shfl_xor_sync(0xFFFFFFFFu, r0max, 2));
            r1max = fmaxf(r1max, __shfl_xor_sync(0xFFFFFFFFu, r1max, 1));
            r1max = fmaxf(r1max, __shfl_xor_sync(0xFFFFFFFFu, r1max, 2));
            float mnew0 = fmaxf(mstate[mt][0], r0max);
            float mnew1 = fmaxf(mstate[mt][1], r1max);
            float corr0 = __expf(mstate[mt][0] - mnew0);
            float corr1 = __expf(mstate[mt][1] - mnew1);
            mstate[mt][0] = mnew0; mstate[mt][1] = mnew1;

            float rs0 = 0.f, rs1 = 0.f;
            #pragma unroll
            for (int nt=0; nt<8; nt++) {
                float p0 = __expf(sacc[nt][0] - mnew0);
                float p1 = __expf(sacc[nt][1] - mnew0);
                float p2 = __expf(sacc[nt][2] - mnew1);
                float p3 = __expf(sacc[nt][3] - mnew1);
                rs0 += p0 + p1; rs1 += p2 + p3;
                *(float2*)(Ps + qr*PS_STRIDE + nt*8 + 2*qc)     = make_float2(to_tf32(p0), to_tf32(p1));
                *(float2*)(Ps + (qr+8)*PS_STRIDE + nt*8 + 2*qc) = make_float2(to_tf32(p2), to_tf32(p3));
            }
            rs0 += __shfl_xor_sync(0xFFFFFFFFu, rs0, 1);
            rs0 += __shfl_xor_sync(0xFFFFFFFFu, rs0, 2);
            rs1 += __shfl_xor_sync(0xFFFFFFFFu, rs1, 1);
            rs1 += __shfl_xor_sync(0xFFFFFFFFu, rs1, 2);
            lstate[mt][0] = lstate[mt][0]*corr0 + rs0;
            lstate[mt][1] = lstate[mt][1]*corr1 + rs1;
            #pragma unroll
            for (int nt=0; nt<2; nt++) {
                oacc[mt][nt][0] *= corr0; oacc[mt][nt][1] *= corr0;
                oacc[mt][nt][2] *= corr1; oacc[mt][nt][3] *= corr1;
            }
            __syncwarp();
            #pragma unroll
            for (int ks=0; ks<8; ks++) {
                uint32_t a[4];
                a[0] = __float_as_uint(Ps[qr*PS_STRIDE + ks*8 + qc]);
                a[1] = __float_as_uint(Ps[(qr+8)*PS_STRIDE + ks*8 + qc]);
                a[2] = __float_as_uint(Ps[qr*PS_STRIDE + ks*8 + qc + 4]);
                a[3] = __float_as_uint(Ps[(qr+8)*PS_STRIDE + ks*8 + qc + 4]);
                #pragma unroll
                for (int nt=0; nt<2; nt++) {
                    uint32_t b0 = __float_as_uint(Vs[(kb + ks*8 + qc)*VS_STRIDE + nt*8 + qr]);
                    uint32_t b1 = __float_as_uint(Vs[(kb + ks*8 + qc + 4)*VS_STRIDE + nt*8 + qr]);
                    MMA_TF32(oacc[mt][nt], a, b0, b1);
                }
            }
            __syncwarp();
        }
    }

    #pragma unroll
    for (int mt=0; mt<2; mt++) {
        float inv0 = 1.f/lstate[mt][0];
        float inv1 = 1.f/lstate[mt][1];
        int row0 = q0 + mt*16 + qr;
        #pragma unroll
        for (int nt=0; nt<2; nt++) {
            int col = h*HD + nt*8 + 2*qc;
            __half* o0 = ao + ((size_t)b*T_SEQ + row0)*D + col;
            __half* o1 = ao + ((size_t)b*T_SEQ + row0 + 8)*D + col;
            *(half2*)o0 = __floats2half2_rn(oacc[mt][nt][0]*inv0, oacc[mt][nt][1]*inv0);
            *(half2*)o1 = __floats2half2_rn(oacc[mt][nt][2]*inv1, oacc[mt][nt][3]*inv1);
        }
    }
}

// ---------------- cross-attention (folded): xo += softmax(h@K'^T/32) @ V' -------
__global__ __launch_bounds__(256) void cross_attn_kernel(
    const float* __restrict__ Q, const float* __restrict__ Km,
    const float* __restrict__ Vm, float* __restrict__ xo)
{
    extern __shared__ float csm[];
    float* Ks = csm;
    float* Vs = csm + NMEM*D;
    int b = blockIdx.x >> 2;
    int chunk = blockIdx.x & 3;
    for (int i=threadIdx.x; i<NMEM*D; i+=256) {
        Ks[i] = Km[(size_t)b*NMEM*D + i];
        Vs[i] = Vm[(size_t)b*NMEM*D + i];
    }
    __syncthreads();
    int t = chunk*256 + threadIdx.x;
    const float4* qrow = (const float4*)(Q + ((size_t)b*T_SEQ + t)*D);
    float s[16];
    #pragma unroll
    for (int mm=0;mm<16;mm++) s[mm]=0.f;
    for (int k4=0;k4<D/4;k4++) {
        float4 qv = qrow[k4];
        #pragma unroll
        for (int mm=0;mm<16;mm++) {
            const float* kr = Ks + mm*D + k4*4;
            s[mm] += qv.x*kr[0] + qv.y*kr[1] + qv.z*kr[2] + qv.w*kr[3];
        }
    }
    float mx = -1e30f;
    #pragma unroll
    for (int mm=0;mm<16;mm++) { s[mm] *= 0.03125f; mx = fmaxf(mx, s[mm]); }
    float sum = 0.f;
    #pragma unroll
    for (int mm=0;mm<16;mm++) { s[mm] = __expf(s[mm]-mx); sum += s[mm]; }
    float inv = 1.f/sum;
    #pragma unroll
    for (int mm=0;mm<16;mm++) s[mm] *= inv;
    float* xrow = xo + ((size_t)b*T_SEQ + t)*D;
    for (int c=0;c<D;c+=4) {
        float4 o = *(const float4*)(xrow + c);
        #pragma unroll
        for (int mm=0;mm<16;mm++) {
            const float* vr = Vs + mm*D + c;
            o.x += s[mm]*vr[0]; o.y += s[mm]*vr[1];
            o.z += s[mm]*vr[2]; o.w += s[mm]*vr[3];
        }
        *(float4*)(xrow + c) = o;
    }
}

// ---------------- memory path -------------------------------------------------
__global__ __launch_bounds__(256) void mean_kernel(const float* __restrict__ x,
                                                   float* __restrict__ mh) {
    __shared__ float sred[256];
    int b = blockIdx.x, cb = blockIdx.y*128;
    int c = threadIdx.x & 127, half = threadIdx.x >> 7;
    const float* p = x + (size_t)b*T_SEQ*D + (size_t)half*512*D + cb + c;
    float s = 0.f;
    #pragma unroll 4
    for (int t=0;t<512;t++) s += p[(size_t)t*D];
    sred[threadIdx.x] = s;
    __syncthreads();
    if (half == 0)
        mh[b*D + cb + c] = (sred[threadIdx.x] + sred[threadIdx.x+128]) * (1.f/T_SEQ);
}

__global__ __launch_bounds__(256) void base_gemv(
    const float* __restrict__ Wz, const float* __restrict__ Wr, const float* __restrict__ Wc,
    const float* __restrict__ bz, const float* __restrict__ br, const float* __restrict__ bc)
{
    int gid = blockIdx.x*8 + (threadIdx.x >> 5);
    int lane = threadIdx.x & 31;
    int g = gid >> 12;
    int rem = gid & 4095;
    int b = rem >> 10;
    int col = rem & 1023;
    const float* W    = (g==0) ? Wz : ((g==1) ? Wr : Wc);
    const float* bias = (g==0) ? bz : ((g==1) ? br : bc);
    const float* wrow = W + (size_t)col*2048;
    const float* mrow = g_meanh + b*D;
    float acc = 0.f;
    #pragma unroll
    for (int k0=0;k0<1024;k0+=128) {
        float4 w = *(const float4*)(wrow + k0 + lane*4);
        float4 m = *(const float4*)(mrow + k0 + lane*4);
        acc += w.x*m.x + w.y*m.y + w.z*m.z + w.w*m.w;
    }
    #pragma unroll
    for (int o=16;o;o>>=1) acc += __shfl_xor_sync(0xFFFFFFFFu, acc, o);
    if (lane == 0) g_base[gid] = acc + bias[col];
}

__device__ __forceinline__ void tile64x64(
    const float* __restrict__ A, const float* __restrict__ B, int ldb,
    float (&acc)[4][4])
{
    __shared__ float As[32][65];
    __shared__ float Bs[32][65];
    const int tid = threadIdx.x;
    const int r  = tid >> 2;
    const int kq = (tid & 3) << 3;
    const int tx = tid & 15;
    const int ty = tid >> 4;
    for (int k0 = 0; k0 < 1024; k0 += 32) {
        float4 a0 = *(const float4*)(A + (size_t)r*1024 + k0 + kq);
        float4 a1 = *(const float4*)(A + (size_t)r*1024 + k0 + kq + 4);
        float4 b0 = *(const float4*)(B + (size_t)r*ldb  + k0 + kq);
        float4 b1 = *(const float4*)(B + (size_t)r*ldb  + k0 + kq + 4);
        __syncthreads();
        As[kq+0][r]=a0.x; As[kq+1][r]=a0.y; As[kq+2][r]=a0.z; As[kq+3][r]=a0.w;
        As[kq+4][r]=a1.x; As[kq+5][r]=a1.y; As[kq+6][r]=a1.z; As[kq+7][r]=a1.w;
        Bs[kq+0][r]=b0.x; Bs[kq+1][r]=b0.y; Bs[kq+2][r]=b0.z; Bs[kq+3][r]=b0.w;
        Bs[kq+4][r]=b1.x; Bs[kq+5][r]=b1.y; Bs[kq+6][r]=b1.z; Bs[kq+7][r]=b1.w;
        __syncthreads();
        #pragma unroll
        for (int kk=0;kk<32;kk++) {
            float a[4], b[4];
            #pragma unroll
            for (int i=0;i<4;i++) a[i] = As[kk][ty*4+i];
            #pragma unroll
            for (int j=0;j<4;j++) b[j] = Bs[kk][tx*4+j];
            #pragma unroll
            for (int i=0;i<4;i++)
                #pragma unroll
                for (int j=0;j<4;j++) acc[i][j] += a[i]*b[j];
        }
    }
}

__global__ __launch_bounds__(256) void zr_pre(
    const float* __restrict__ mem, const float* __restrict__ Wz,
    const float* __restrict__ Wr)
{
    int g = blockIdx.y;
    int ct = blockIdx.x;
    const float* W = (g ? Wr : Wz) + (size_t)(ct*64)*2048 + 1024;
    float acc[4][4];
    #pragma unroll
    for (int i=0;i<4;i++)
        #pragma unroll
        for (int j=0;j<4;j++) acc[i][j]=0.f;
    tile64x64(mem, W, 2048, acc);
    float* out = g ? g_rpre : g_zpre;
    const int tx = threadIdx.x & 15, ty = threadIdx.x >> 4;
    #pragma unroll
    for (int i=0;i<4;i++) {
        int row = ty*4+i;
        #pragma unroll
        for (int j=0;j<4;j++) out[row*1024 + ct*64 + tx*4+j] = acc[i][j];
    }
}

__global__ void combine_kernel(const float* __restrict__ mem) {
    int idx = blockIdx.x*blockDim.x + threadIdx.x;
    int row = idx >> 10, col = idx & 1023, b = row >> 4;
    float z = 1.f/(1.f + __expf(-(g_zpre[idx] + g_base[0*4096 + b*1024 + col])));
    float r = 1.f/(1.f + __expf(-(g_rpre[idx] + g_base[1*4096 + b*1024 + col])));
    g_z[idx] = z;
    g_rm[idx] = r * mem[idx];
}

__global__ __launch_bounds__(256) void c_gemm(
    const float* __restrict__ mem, const float* __restrict__ Wc,
    float* __restrict__ newmem)
{
    int ct = blockIdx.x;
    const float* W = Wc + (size_t)(ct*64)*2048 + 1024;
    float acc[4][4];
    #pragma unroll
    for (int i=0;i<4;i++)
        #pragma unroll
        for (int j=0;j<4;j++) acc[i][j]=0.f;
    tile64x64(g_rm, W, 2048, acc);
    const int tx = threadIdx.x & 15, ty = threadIdx.x >> 4;
    #pragma unroll
    for (int i=0;i<4;i++) {
        int row = ty*4+i;
        #pragma unroll
        for (int j=0;j<4;j++) {
            int col = ct*64 + tx*4+j;
            float v = acc[i][j] + g_base[2*4096 + (row>>4)*1024 + col];
            float c = tanhf(v);
            float z = g_z[row*1024+col];
            newmem[(size_t)row*1024+col] = (1.f - z)*mem[(size_t)row*1024+col] + z*c;
        }
    }
}

__global__ __launch_bounds__(256) void kv2_gemm(const float* __restrict__ newmem)
{
    int which = blockIdx.y;
    int ct = blockIdx.x;
    const float* W = (which ? g_wv : g_wk) + (size_t)(ct*64)*1024;
    float acc[4][4];
    #pragma unroll
    for (int i=0;i<4;i++)
        #pragma unroll
        for (int j=0;j<4;j++) acc[i][j]=0.f;
    tile64x64(newmem, W, 1024, acc);
    float* out = which ? g_V : g_K;
    const int tx = threadIdx.x & 15, ty = threadIdx.x >> 4;
    #pragma unroll
    for (int i=0;i<4;i++) {
        int row = ty*4+i;
        #pragma unroll
        for (int j=0;j<4;j++) {
            int col = ct*64 + tx*4+j;
            out[(size_t)row*1024+col] = acc[i][j];
        }
    }
}

// ---------------- host launcher -------------------------------------------------
extern "C" void kernel_launch(void* const* d_in, const int* in_sizes, int n_in,
                              void* d_out, int out_size)
{
    const float* x          = (const float*)d_in[0];
    const float* memory     = (const float*)d_in[1];
    const float* ln1_g      = (const float*)d_in[2];
    const float* ln1_b      = (const float*)d_in[3];
    const float* ln2_g      = (const float*)d_in[4];
    const float* ln2_b      = (const float*)d_in[5];
    const float* ln3_g      = (const float*)d_in[6];
    const float* ln3_b      = (const float*)d_in[7];
    const float* in_proj_w  = (const float*)d_in[8];
    const float* in_proj_b  = (const float*)d_in[9];
    const float* attn_out_w = (const float*)d_in[10];
    const float* attn_out_b = (const float*)d_in[11];
    const float* Wz_w       = (const float*)d_in[12];
    const float* Wz_b       = (const float*)d_in[13];
    const float* Wr_w       = (const float*)d_in[14];
    const float* Wr_b       = (const float*)d_in[15];
    const float* Wc_w       = (const float*)d_in[16];
    const float* Wc_b       = (const float*)d_in[17];
    const float* mq_w       = (const float*)d_in[18];
    const float* mk_w       = (const float*)d_in[19];
    const float* mv_w       = (const float*)d_in[20];
    const float* mo_w       = (const float*)d_in[21];
    const float* W1         = (const float*)d_in[22];
    const float* b1         = (const float*)d_in[23];
    const float* W2         = (const float*)d_in[24];
    const float* b2         = (const float*)d_in[25];

    float* xo = (float*)d_out;
    float* newmem = xo + (size_t)ROWS*D;

    float *p_h, *p_qkv, *p_K, *p_V, *p_w, *p_mh, *p_wk, *p_wv;
    __half *p_hh, *p_hao, *p_hffn, *p_hw;
    cudaGetSymbolAddress((void**)&p_h,    g_h);
    cudaGetSymbolAddress((void**)&p_qkv,  g_qkv);
    cudaGetSymbolAddress((void**)&p_K,    g_K);
    cudaGetSymbolAddress((void**)&p_V,    g_V);
    cudaGetSymbolAddress((void**)&p_w,    g_w);
    cudaGetSymbolAddress((void**)&p_mh,   g_meanh);
    cudaGetSymbolAddress((void**)&p_wk,   g_wk);
    cudaGetSymbolAddress((void**)&p_wv,   g_wv);
    cudaGetSymbolAddress((void**)&p_hh,   h_h);
    cudaGetSymbolAddress((void**)&p_hao,  h_ao);
    cudaGetSymbolAddress((void**)&p_hffn, h_ffn);
    cudaGetSymbolAddress((void**)&p_hw,   h_w);

    static cudaStream_t s2 = nullptr;
    static cudaEvent_t evStart = nullptr, evCvt = nullptr, evFork = nullptr, evMem = nullptr;
    static bool tried = false, ok = false;
    if (!tried) {
        tried = true;
        ok = (cudaStreamCreateWithFlags(&s2, cudaStreamNonBlocking) == cudaSuccess) &&
             (cudaEventCreateWithFlags(&evStart, cudaEventDisableTiming) == cudaSuccess) &&
             (cudaEventCreateWithFlags(&evCvt,   cudaEventDisableTiming) == cudaSuccess) &&
             (cudaEventCreateWithFlags(&evFork,  cudaEventDisableTiming) == cudaSuccess) &&
             (cudaEventCreateWithFlags(&evMem,   cudaEventDisableTiming) == cudaSuccess);
    }
    cudaStream_t sb = ok ? s2 : (cudaStream_t)0;

    cudaFuncSetAttribute(flash_attn_kernel, cudaFuncAttributeMaxDynamicSharedMemorySize, FLASH_SMEM);
    cudaFuncSetAttribute(cross_attn_kernel, cudaFuncAttributeMaxDynamicSharedMemorySize, 131072);
    const int GSM = SMEM_FLOATS * 4;
    cudaFuncSetAttribute(gemm_tf32<0,0,0,0>, cudaFuncAttributeMaxDynamicSharedMemorySize, GSM);

    // ---- early hidden phase on sb ----
    if (ok) { cudaEventRecord(evStart, 0); cudaStreamWaitEvent(sb, evStart, 0); }
    cvt_fp16_kernel<<<3072, 256, 0, sb>>>(in_proj_w,  p_hw + HOFF_INP,  3*1024*1024/4);
    cvt_fp16_kernel<<<1024, 256, 0, sb>>>(attn_out_w, p_hw + HOFF_AOUT, 1024*1024/4);
    cvt_fp16_kernel<<<4096, 256, 0, sb>>>(W1,         p_hw + HOFF_W1,   4*1024*1024/4);
    cvt_fp16_kernel<<<4096, 256, 0, sb>>>(W2,         p_hw + HOFF_W2,   4*1024*1024/4);
    if (ok) cudaEventRecord(evCvt, sb);
    cvt_tf32_kernel<<<1024, 256, 0, sb>>>(mo_w, p_w + OFF_MO, 1024*1024/4);
    transpose_tf32<<<dim3(32,32), dim3(32,8), 0, sb>>>(mq_w, p_w + OFF_MQT);
    transpose_tf32<<<dim3(32,32), dim3(32,8), 0, sb>>>(mk_w, p_w + OFF_MKT);
    transpose_tf32<<<dim3(32,32), dim3(32,8), 0, sb>>>(mv_w, p_w + OFF_MVT);
    gemm_tf32<0,0,0,0><<<dim3(8,8), 256, GSM, sb>>>(p_w + OFF_MQT, p_w + OFF_MKT, nullptr, nullptr, p_wk, 1024, 1024, 1024);
    gemm_tf32<0,0,0,0><<<dim3(8,8), 256, GSM, sb>>>(p_w + OFF_MO,  p_w + OFF_MVT, nullptr, nullptr, p_wv, 1024, 1024, 1024);
    zr_pre<<<dim3(16,2), 256, 0, sb>>>(memory, Wz_w, Wr_w);

    // ---- main path ----
    ln_kernel_h<<<ROWS, 256>>>(x, ln1_g, ln1_b, p_hh);
    if (ok) cudaStreamWaitEvent(0, evCvt, 0);

    gemm_fp16<0,1,0,0><<<dim3(3*D/128, ROWS/128), 256, HSMEM_BYTES>>>(p_hh, p_hw + HOFF_INP, in_proj_b, nullptr, p_qkv, ROWS, 3*D, D);
    flash_attn_kernel<<<dim3(BATCH*NHEADS, 4), 256, FLASH_SMEM>>>(p_qkv, p_hao);
    gemm_fp16<0,1,1,0><<<dim3(D/128, ROWS/128), 256, HSMEM_BYTES>>>(p_hao, p_hw + HOFF_AOUT, attn_out_b, x, xo, ROWS, D, D);

    // ---- fork memory path onto sb ----
    if (ok) { cudaEventRecord(evFork, 0); cudaStreamWaitEvent(sb, evFork, 0); }
    mean_kernel<<<dim3(BATCH, 8), 256, 0, sb>>>(xo, p_mh);
    base_gemv<<<1536, 256, 0, sb>>>(Wz_w, Wr_w, Wc_w, Wz_b, Wr_b, Wc_b);
    combine_kernel<<<BATCH*NMEM*D/256, 256, 0, sb>>>(memory);
    c_gemm<<<16, 256, 0, sb>>>(memory, Wc_w, newmem);
    kv2_gemm<<<dim3(16, 2), 256, 0, sb>>>(newmem);
    if (ok) cudaEventRecord(evMem, sb);

    // ---- main path: LN2 (float), then folded cross-attention ----
    ln_kernel<<<ROWS, 256>>>(xo, ln2_g, ln2_b, p_h);
    if (ok) cudaStreamWaitEvent(0, evMem, 0);
    cross_attn_kernel<<<BATCH*4, 256, 131072>>>(p_h, p_K, p_V, xo);

    // FFN
    ln_kernel_h<<<ROWS, 256>>>(xo, ln3_g, ln3_b, p_hh);
    gemm_fp16<1,1,0,1><<<dim3(4*D/128, ROWS/128), 256, HSMEM_BYTES>>>(p_hh, p_hw + HOFF_W1, b1, nullptr, p_hffn, ROWS, 4*D, D);
    gemm_fp16<0,1,1,0><<<dim3(D/128, ROWS/128), 256, HSMEM_BYTES>>>(p_hffn, p_hw + HOFF_W2, b2, xo, xo, ROWS, D, 4*D);
}

// round 12
// speedup vs baseline: 4.9250x; 1.0855x over previous
#include <cuda_runtime.h>
#include <cuda_fp16.h>
#include <math.h>
#include <stdint.h>

#define D 1024
#define T_SEQ 1024
#define BATCH 4
#define NMEM 16
#define NHEADS 64
#define HD 16
#define ROWS (BATCH*T_SEQ)   // 4096

// ---------------- scratch (device globals; no runtime allocation) ----------------
__device__ float g_h[ROWS*D];            // LN2 output (float, feeds cross-attn)
__device__ __half h_h[ROWS*D];           // LN1/LN3 outputs (fp16, feeds fp16 GEMMs)
__device__ __half h_qkv[ROWS*3*D];       // QKV (fp16)
__device__ __half h_ao[ROWS*D];          // self-attention output (fp16)
__device__ __half h_ffn[ROWS*4*D];       // FFN hidden (fp16)
__device__ float g_meanh[BATCH*D];
__device__ float g_base[3*BATCH*D];
__device__ float g_zpre[BATCH*NMEM*D];
__device__ float g_rpre[BATCH*NMEM*D];
__device__ float g_z[BATCH*NMEM*D];
__device__ float g_rm[BATCH*NMEM*D];
__device__ float g_K[BATCH*NMEM*D];
__device__ float g_V[BATCH*NMEM*D];
__device__ float g_wk[1024*1024];        // Wk' = mq^T @ mk
__device__ float g_wv[1024*1024];        // Wv' = mo @ mv
__device__ float g_w[8*1024*1024];       // float scratch for fold path
__device__ __half h_w[12*1024*1024];     // fp16 weight copies

// float scratch offsets (fold path)
#define OFF_MQT   0
#define OFF_MO    (1*1024*1024)
#define OFF_MKT   (2*1024*1024)
#define OFF_MVT   (3*1024*1024)
// fp16 weight offsets
#define HOFF_INP  0
#define HOFF_AOUT (3*1024*1024)
#define HOFF_W1   (4*1024*1024)
#define HOFF_W2   (8*1024*1024)

__device__ __forceinline__ float to_tf32(float v) {
    uint32_t r;
    asm("cvt.rna.tf32.f32 %0, %1;" : "=r"(r) : "f"(v));
    return __uint_as_float(r);
}

// ---------------- utility kernels ----------------
__global__ void cvt_tf32_kernel(const float* __restrict__ src, float* __restrict__ dst, int n4) {
    int i = blockIdx.x*blockDim.x + threadIdx.x;
    if (i < n4) {
        float4 v = ((const float4*)src)[i];
        v.x = to_tf32(v.x); v.y = to_tf32(v.y); v.z = to_tf32(v.z); v.w = to_tf32(v.w);
        ((float4*)dst)[i] = v;
    }
}

__global__ void cvt_fp16_kernel(const float* __restrict__ src, __half* __restrict__ dst, int n4) {
    int i = blockIdx.x*blockDim.x + threadIdx.x;
    if (i < n4) {
        float4 v = ((const float4*)src)[i];
        half2 lo = __floats2half2_rn(v.x, v.y);
        half2 hi = __floats2half2_rn(v.z, v.w);
        ((half2*)dst)[2*i]   = lo;
        ((half2*)dst)[2*i+1] = hi;
    }
}

__global__ __launch_bounds__(256) void transpose_tf32(
    const float* __restrict__ src, float* __restrict__ dst)
{
    __shared__ float tile[32][33];
    int x = blockIdx.x*32 + threadIdx.x;
    int y0 = blockIdx.y*32 + threadIdx.y;
    #pragma unroll
    for (int i=0;i<32;i+=8)
        tile[threadIdx.y+i][threadIdx.x] = src[(size_t)(y0+i)*1024 + x];
    __syncthreads();
    int x2 = blockIdx.y*32 + threadIdx.x;
    int y2 = blockIdx.x*32 + threadIdx.y;
    #pragma unroll
    for (int i=0;i<32;i+=8)
        dst[(size_t)(y2+i)*1024 + x2] = to_tf32(tile[threadIdx.x][threadIdx.y+i]);
}

// LayerNorm -> float output (LN2, feeds scalar cross-attn)
__global__ __launch_bounds__(256) void ln_kernel(
    const float* __restrict__ x, const float* __restrict__ g,
    const float* __restrict__ b, float* __restrict__ y)
{
    __shared__ float s1[256], s2[256];
    int row = blockIdx.x;
    const float4* xr = (const float4*)(x + (size_t)row*D);
    float4 v = xr[threadIdx.x];
    float sum = v.x+v.y+v.z+v.w;
    float sq  = v.x*v.x + v.y*v.y + v.z*v.z + v.w*v.w;
    s1[threadIdx.x]=sum; s2[threadIdx.x]=sq;
    __syncthreads();
    for (int off=128; off; off>>=1) {
        if (threadIdx.x < off) {
            s1[threadIdx.x]+=s1[threadIdx.x+off];
            s2[threadIdx.x]+=s2[threadIdx.x+off];
        }
        __syncthreads();
    }
    float mean = s1[0]*(1.0f/D);
    float var  = s2[0]*(1.0f/D) - mean*mean;
    float rstd = rsqrtf(var + 1e-5f);
    int c = threadIdx.x*4;
    float4 gg = *(const float4*)(g+c);
    float4 bb = *(const float4*)(b+c);
    float4 o;
    o.x = (v.x-mean)*rstd*gg.x + bb.x;
    o.y = (v.y-mean)*rstd*gg.y + bb.y;
    o.z = (v.z-mean)*rstd*gg.z + bb.z;
    o.w = (v.w-mean)*rstd*gg.w + bb.w;
    ((float4*)(y + (size_t)row*D))[threadIdx.x] = o;
}

// LayerNorm -> fp16 output (LN1/LN3, feeds fp16 GEMMs)
__global__ __launch_bounds__(256) void ln_kernel_h(
    const float* __restrict__ x, const float* __restrict__ g,
    const float* __restrict__ b, __half* __restrict__ y)
{
    __shared__ float s1[256], s2[256];
    int row = blockIdx.x;
    const float4* xr = (const float4*)(x + (size_t)row*D);
    float4 v = xr[threadIdx.x];
    float sum = v.x+v.y+v.z+v.w;
    float sq  = v.x*v.x + v.y*v.y + v.z*v.z + v.w*v.w;
    s1[threadIdx.x]=sum; s2[threadIdx.x]=sq;
    __syncthreads();
    for (int off=128; off; off>>=1) {
        if (threadIdx.x < off) {
            s1[threadIdx.x]+=s1[threadIdx.x+off];
            s2[threadIdx.x]+=s2[threadIdx.x+off];
        }
        __syncthreads();
    }
    float mean = s1[0]*(1.0f/D);
    float var  = s2[0]*(1.0f/D) - mean*mean;
    float rstd = rsqrtf(var + 1e-5f);
    int c = threadIdx.x*4;
    float4 gg = *(const float4*)(g+c);
    float4 bb = *(const float4*)(b+c);
    half2 lo = __floats2half2_rn((v.x-mean)*rstd*gg.x + bb.x, (v.y-mean)*rstd*gg.y + bb.y);
    half2 hi = __floats2half2_rn((v.z-mean)*rstd*gg.z + bb.z, (v.w-mean)*rstd*gg.w + bb.w);
    half2* yr = (half2*)(y + (size_t)row*D);
    yr[threadIdx.x*2]   = lo;
    yr[threadIdx.x*2+1] = hi;
}

__device__ __forceinline__ void cp16(uint32_t dst, const void* src) {
    asm volatile("cp.async.cg.shared.global [%0], [%1], 16;" :: "r"(dst), "l"(src));
}

// ---------------- fp16 tensor-core GEMM: C(M,N) = A(M,K) @ B(N,K)^T -------------
#define HA_OFF(buf) ((buf)*10240)
#define HB_OFF(buf) (5120 + (buf)*10240)
#define HSMEM_BYTES (20480*2)

template<int ACT, int BIASF, int RESF, int OUTHALF>
__global__ __launch_bounds__(256, 2) void gemm_fp16(
    const __half* __restrict__ A, const __half* __restrict__ B,
    const float* __restrict__ bias, const float* __restrict__ res,
    void* __restrict__ Cv, int M, int N, int K)
{
    extern __shared__ __half hsm[];
    float* Cf = (float*)Cv;
    __half* Ch = (__half*)Cv;
    const int tid = threadIdx.x;
    const int bm = blockIdx.y * 128;
    const int bn = blockIdx.x * 128;
    const int lane = tid & 31;
    const int warp = tid >> 5;
    const int wm64 = (warp & 1) * 64;
    const int wn32 = (warp >> 1) * 32;
    const int qr = lane >> 2;
    const int qc = lane & 3;
    uint32_t smem_u32 = (uint32_t)__cvta_generic_to_shared(hsm);

    float acc[4][4][4];
    #pragma unroll
    for (int i=0;i<4;i++)
        #pragma unroll
        for (int j=0;j<4;j++)
            #pragma unroll
            for (int e=0;e<4;e++) acc[i][j][e] = 0.f;

    const int NT = K >> 5;

    {
        const __half* Ab = A + (size_t)bm*K;
        const __half* Bb = B + (size_t)bn*K;
        #pragma unroll
        for (int rep=0; rep<2; rep++) {
            int idx = rep*256 + tid;
            int row = idx >> 2, seg = idx & 3;
            cp16(smem_u32 + (HA_OFF(0) + row*40 + seg*8)*2, Ab + (size_t)row*K + seg*8);
            cp16(smem_u32 + (HB_OFF(0) + row*40 + seg*8)*2, Bb + (size_t)row*K + seg*8);
        }
        asm volatile("cp.async.commit_group;");
    }

    for (int t = 0; t < NT; t++) {
        if (t + 1 < NT) {
            int buf = (t+1) & 1;
            int kb = (t+1) << 5;
            const __half* Ab = A + (size_t)bm*K + kb;
            const __half* Bb = B + (size_t)bn*K + kb;
            #pragma unroll
            for (int rep=0; rep<2; rep++) {
                int idx = rep*256 + tid;
                int row = idx >> 2, seg = idx & 3;
                cp16(smem_u32 + (HA_OFF(buf) + row*40 + seg*8)*2, Ab + (size_t)row*K + seg*8);
                cp16(smem_u32 + (HB_OFF(buf) + row*40 + seg*8)*2, Bb + (size_t)row*K + seg*8);
            }
            asm volatile("cp.async.commit_group;");
            asm volatile("cp.async.wait_group 1;");
        } else {
            asm volatile("cp.async.wait_group 0;");
        }
        __syncthreads();

        const __half* sA = hsm + HA_OFF(t & 1);
        const __half* sB = hsm + HB_OFF(t & 1);

        #pragma unroll
        for (int ks = 0; ks < 2; ks++) {
            const int k0 = ks * 16;
            uint32_t a[4][4], b[4][2];
            #pragma unroll
            for (int i=0;i<4;i++) {
                int r = wm64 + i*16 + qr;
                a[i][0] = *(const uint32_t*)(sA + r*40 + k0 + 2*qc);
                a[i][1] = *(const uint32_t*)(sA + (r+8)*40 + k0 + 2*qc);
                a[i][2] = *(const uint32_t*)(sA + r*40 + k0 + 2*qc + 8);
                a[i][3] = *(const uint32_t*)(sA + (r+8)*40 + k0 + 2*qc + 8);
            }
            #pragma unroll
            for (int j=0;j<4;j++) {
                int n = wn32 + j*8 + qr;
                b[j][0] = *(const uint32_t*)(sB + n*40 + k0 + 2*qc);
                b[j][1] = *(const uint32_t*)(sB + n*40 + k0 + 2*qc + 8);
            }
            #pragma unroll
            for (int i=0;i<4;i++)
                #pragma unroll
                for (int j=0;j<4;j++) {
                    asm volatile(
                        "mma.sync.aligned.m16n8k16.row.col.f32.f16.f16.f32 "
                        "{%0,%1,%2,%3}, {%4,%5,%6,%7}, {%8,%9}, {%0,%1,%2,%3};"
                        : "+f"(acc[i][j][0]), "+f"(acc[i][j][1]),
                          "+f"(acc[i][j][2]), "+f"(acc[i][j][3])
                        : "r"(a[i][0]), "r"(a[i][1]), "r"(a[i][2]), "r"(a[i][3]),
                          "r"(b[j][0]), "r"(b[j][1]));
                }
        }
        __syncthreads();
    }

    #pragma unroll
    for (int i=0;i<4;i++) {
        int row0 = bm + wm64 + i*16 + qr;
        #pragma unroll
        for (int j=0;j<4;j++) {
            int col0 = bn + wn32 + j*8 + qc*2;
            float v0 = acc[i][j][0], v1 = acc[i][j][1];
            float v2 = acc[i][j][2], v3 = acc[i][j][3];
            if (BIASF) {
                float b0 = bias[col0], b1 = bias[col0+1];
                v0 += b0; v1 += b1; v2 += b0; v3 += b1;
            }
            if (ACT == 1) {
                v0 = 0.5f*v0*(1.f + erff(v0*0.70710678118654752f));
                v1 = 0.5f*v1*(1.f + erff(v1*0.70710678118654752f));
                v2 = 0.5f*v2*(1.f + erff(v2*0.70710678118654752f));
                v3 = 0.5f*v3*(1.f + erff(v3*0.70710678118654752f));
            }
            if (RESF) {
                v0 += res[(size_t)row0*N + col0];
                v1 += res[(size_t)row0*N + col0 + 1];
                v2 += res[(size_t)(row0+8)*N + col0];
                v3 += res[(size_t)(row0+8)*N + col0 + 1];
            }
            if (OUTHALF) {
                *(half2*)(Ch + (size_t)row0*N + col0)     = __floats2half2_rn(v0, v1);
                *(half2*)(Ch + (size_t)(row0+8)*N + col0) = __floats2half2_rn(v2, v3);
            } else {
                *(float2*)(Cf + (size_t)row0*N + col0)     = make_float2(v0, v1);
                *(float2*)(Cf + (size_t)(row0+8)*N + col0) = make_float2(v2, v3);
            }
        }
    }
}

// ---------------- legacy mma.sync tf32 GEMM (hidden weight-fold GEMMs) ----------
#define SMEM_FLOATS (4*4608)
#define A_OFFS(buf) ((buf)*4608)
#define B_OFFS(buf) (9216 + (buf)*4608)

template<int ACT, int BIASF, int RESF, int TF32OUT>
__global__ __launch_bounds__(256, 2) void gemm_tf32(
    const float* __restrict__ A, const float* __restrict__ B,
    const float* __restrict__ bias, const float* __restrict__ res,
    float* __restrict__ C, int M, int N, int K)
{
    extern __shared__ float sm[];
    const int tid = threadIdx.x;
    const int bm = blockIdx.y * 128;
    const int bn = blockIdx.x * 128;
    const int lane = tid & 31;
    const int warp = tid >> 5;
    const int wm64 = (warp & 1) * 64;
    const int wn32 = (warp >> 1) * 32;
    const int qr = lane >> 2;
    const int qc = lane & 3;
    uint32_t smem_u32 = (uint32_t)__cvta_generic_to_shared(sm);
    const int lrow = tid >> 3;
    const int lkq  = (tid & 7) * 4;

    float acc[4][4][4];
    #pragma unroll
    for (int i=0;i<4;i++)
        #pragma unroll
        for (int j=0;j<4;j++)
            #pragma unroll
            for (int e=0;e<4;e++) acc[i][j][e] = 0.f;

    const int NT = K >> 5;
    {
        const float* Ab = A + (size_t)bm*K;
        const float* Bb = B + (size_t)bn*K;
        #pragma unroll
        for (int rep=0; rep<4; rep++) {
            int row = rep*32 + lrow;
            cp16(smem_u32 + (A_OFFS(0) + row*36 + lkq)*4, Ab + (size_t)row*K + lkq);
            cp16(smem_u32 + (B_OFFS(0) + row*36 + lkq)*4, Bb + (size_t)row*K + lkq);
        }
        asm volatile("cp.async.commit_group;");
    }
    for (int t = 0; t < NT; t++) {
        if (t + 1 < NT) {
            int buf = (t+1) & 1;
            int kb = (t+1) << 5;
            const float* Ab = A + (size_t)bm*K + kb;
            const float* Bb = B + (size_t)bn*K + kb;
            #pragma unroll
            for (int rep=0; rep<4; rep++) {
                int row = rep*32 + lrow;
                cp16(smem_u32 + (A_OFFS(buf) + row*36 + lkq)*4, Ab + (size_t)row*K + lkq);
                cp16(smem_u32 + (B_OFFS(buf) + row*36 + lkq)*4, Bb + (size_t)row*K + lkq);
            }
            asm volatile("cp.async.commit_group;");
            asm volatile("cp.async.wait_group 1;");
        } else {
            asm volatile("cp.async.wait_group 0;");
        }
        __syncthreads();
        const float* sA = sm + A_OFFS(t & 1);
        const float* sB = sm + B_OFFS(t & 1);
        #pragma unroll
        for (int ks = 0; ks < 4; ks++) {
            const int k0 = ks * 8;
            uint32_t a[4][4], b[4][2];
            #pragma unroll
            for (int i=0;i<4;i++) {
                int r = wm64 + i*16 + qr;
                a[i][0] = __float_as_uint(sA[r*36 + k0 + qc]);
                a[i][1] = __float_as_uint(sA[(r+8)*36 + k0 + qc]);
                a[i][2] = __float_as_uint(sA[r*36 + k0 + qc + 4]);
                a[i][3] = __float_as_uint(sA[(r+8)*36 + k0 + qc + 4]);
            }
            #pragma unroll
            for (int j=0;j<4;j++) {
                int n = wn32 + j*8 + qr;
                b[j][0] = __float_as_uint(sB[n*36 + k0 + qc]);
                b[j][1] = __float_as_uint(sB[n*36 + k0 + qc + 4]);
            }
            #pragma unroll
            for (int i=0;i<4;i++)
                #pragma unroll
                for (int j=0;j<4;j++) {
                    asm volatile(
                        "mma.sync.aligned.m16n8k8.row.col.f32.tf32.tf32.f32 "
                        "{%0,%1,%2,%3}, {%4,%5,%6,%7}, {%8,%9}, {%0,%1,%2,%3};"
                        : "+f"(acc[i][j][0]), "+f"(acc[i][j][1]),
                          "+f"(acc[i][j][2]), "+f"(acc[i][j][3])
                        : "r"(a[i][0]), "r"(a[i][1]), "r"(a[i][2]), "r"(a[i][3]),
                          "r"(b[j][0]), "r"(b[j][1]));
                }
        }
        __syncthreads();
    }
    #pragma unroll
    for (int i=0;i<4;i++) {
        int row0 = bm + wm64 + i*16 + qr;
        #pragma unroll
        for (int j=0;j<4;j++) {
            int col0 = bn + wn32 + j*8 + qc*2;
            float v0 = acc[i][j][0], v1 = acc[i][j][1];
            float v2 = acc[i][j][2], v3 = acc[i][j][3];
            *(float2*)(C + (size_t)row0*N + col0)     = make_float2(v0, v1);
            *(float2*)(C + (size_t)(row0+8)*N + col0) = make_float2(v2, v3);
        }
    }
}

// ---------------- fp16 tensor-core flash self-attention -------------------------
// block = (b*64+h, qtile of 256), 256 threads. K smem [key][24], V smem TRANSPOSED
// [dim][1032], P per-warp [16][72]. HD=16 = one k16 MMA per S tile.
#define KSH 24
#define VSH 1032
#define PSH 72
#define FLASH_SMEM ((1024*KSH + 16*VSH + 8*16*PSH)*2)

#define MMA_F16(acc, a, b0, b1) \
    asm volatile( \
        "mma.sync.aligned.m16n8k16.row.col.f32.f16.f16.f32 " \
        "{%0,%1,%2,%3}, {%4,%5,%6,%7}, {%8,%9}, {%0,%1,%2,%3};" \
        : "+f"((acc)[0]), "+f"((acc)[1]), "+f"((acc)[2]), "+f"((acc)[3]) \
        : "r"((a)[0]), "r"((a)[1]), "r"((a)[2]), "r"((a)[3]), \
          "r"(b0), "r"(b1))

__global__ __launch_bounds__(256) void flash_attn_kernel(
    const __half* __restrict__ qkv, __half* __restrict__ ao)
{
    extern __shared__ __half fsm[];
    __half* Ks = fsm;                          // [1024][KSH]
    __half* Vs = fsm + 1024*KSH;               // [16][VSH]  (transposed: dim-major)
    __half* Ps = Vs + 16*VSH + (threadIdx.x >> 5)*16*PSH;

    const int b = blockIdx.x >> 6;
    const int h = blockIdx.x & 63;
    const int qt = blockIdx.y;
    const int tid = threadIdx.x;
    const int lane = tid & 31;
    const int warp = tid >> 5;
    const int qr = lane >> 2;      // 0..7
    const int qc = lane & 3;       // 0..3

    const __half* base = qkv + (size_t)b*T_SEQ*3*D + h*HD;

    // stage K (row-major) and V (transposed)
    for (int r = tid; r < T_SEQ; r += 256) {
        const uint32_t* kr = (const uint32_t*)(base + (size_t)r*3*D + D);
        #pragma unroll
        for (int i=0;i<8;i++) *(uint32_t*)(Ks + r*KSH + i*2) = kr[i];
        const __half* vr = base + (size_t)r*3*D + 2*D;
        #pragma unroll
        for (int d=0; d<16; d++) Vs[d*VSH + r] = vr[d];
    }

    // Q fragments: scale folded (0.25 = HD^-0.5)
    const int q0 = qt*256 + warp*32;
    const half2 qs = __floats2half2_rn(0.25f, 0.25f);
    uint32_t aQ[2][4];
    #pragma unroll
    for (int mt=0; mt<2; mt++) {
        int r0 = q0 + mt*16 + qr;
        half2 v0 = __hmul2(*(const half2*)(base + (size_t)r0*3*D + 2*qc), qs);
        half2 v1 = __hmul2(*(const half2*)(base + (size_t)(r0+8)*3*D + 2*qc), qs);
        half2 v2 = __hmul2(*(const half2*)(base + (size_t)r0*3*D + 2*qc + 8), qs);
        half2 v3 = __hmul2(*(const half2*)(base + (size_t)(r0+8)*3*D + 2*qc + 8), qs);
        aQ[mt][0] = *(uint32_t*)&v0; aQ[mt][1] = *(uint32_t*)&v1;
        aQ[mt][2] = *(uint32_t*)&v2; aQ[mt][3] = *(uint32_t*)&v3;
    }
    __syncthreads();

    float mstate[2][2], lstate[2][2], oacc[2][2][4];
    #pragma unroll
    for (int mt=0; mt<2; mt++) {
        mstate[mt][0] = -1e30f; mstate[mt][1] = -1e30f;
        lstate[mt][0] = 0.f;    lstate[mt][1] = 0.f;
        #pragma unroll
        for (int nt=0; nt<2; nt++)
            #pragma unroll
            for (int e=0; e<4; e++) oacc[mt][nt][e] = 0.f;
    }

    for (int nc = 0; nc < 16; nc++) {
        const int kb = nc*64;
        #pragma unroll
        for (int mt=0; mt<2; mt++) {
            // --- S = Q @ K^T (one k16 MMA per 16x8 tile) ---
            float sacc[8][4];
            #pragma unroll
            for (int nt=0; nt<8; nt++) {
                sacc[nt][0]=0.f; sacc[nt][1]=0.f; sacc[nt][2]=0.f; sacc[nt][3]=0.f;
                const int key = kb + nt*8 + qr;
                uint32_t b0 = *(const uint32_t*)(Ks + key*KSH + 2*qc);
                uint32_t b1 = *(const uint32_t*)(Ks + key*KSH + 2*qc + 8);
                MMA_F16(sacc[nt], aQ[mt], b0, b1);
            }
            // --- online softmax ---
            float r0max = -1e30f, r1max = -1e30f;
            #pragma unroll
            for (int nt=0; nt<8; nt++) {
                r0max = fmaxf(r0max, fmaxf(sacc[nt][0], sacc[nt][1]));
                r1max = fmaxf(r1max, fmaxf(sacc[nt][2], sacc[nt][3]));
            }
            r0max = fmaxf(r0max, __shfl_xor_sync(0xFFFFFFFFu, r0max, 1));
            r0max = fmaxf(r0max, __shfl_xor_sync(0xFFFFFFFFu, r0max, 2));
            r1max = fmaxf(r1max, __shfl_xor_sync(0xFFFFFFFFu, r1max, 1));
            r1max = fmaxf(r1max, __shfl_xor_sync(0xFFFFFFFFu, r1max, 2));
            float mnew0 = fmaxf(mstate[mt][0], r0max);
            float mnew1 = fmaxf(mstate[mt][1], r1max);
            float corr0 = __expf(mstate[mt][0] - mnew0);
            float corr1 = __expf(mstate[mt][1] - mnew1);
            mstate[mt][0] = mnew0; mstate[mt][1] = mnew1;

            float rs0 = 0.f, rs1 = 0.f;
            #pragma unroll
            for (int nt=0; nt<8; nt++) {
                float p0 = __expf(sacc[nt][0] - mnew0);
                float p1 = __expf(sacc[nt][1] - mnew0);
                float p2 = __expf(sacc[nt][2] - mnew1);
                float p3 = __expf(sacc[nt][3] - mnew1);
                rs0 += p0 + p1; rs1 += p2 + p3;
                *(half2*)(Ps + qr*PSH + nt*8 + 2*qc)     = __floats2half2_rn(p0, p1);
                *(half2*)(Ps + (qr+8)*PSH + nt*8 + 2*qc) = __floats2half2_rn(p2, p3);
            }
            rs0 += __shfl_xor_sync(0xFFFFFFFFu, rs0, 1);
            rs0 += __shfl_xor_sync(0xFFFFFFFFu, rs0, 2);
            rs1 += __shfl_xor_sync(0xFFFFFFFFu, rs1, 1);
            rs1 += __shfl_xor_sync(0xFFFFFFFFu, rs1, 2);
            lstate[mt][0] = lstate[mt][0]*corr0 + rs0;
            lstate[mt][1] = lstate[mt][1]*corr1 + rs1;
            #pragma unroll
            for (int nt=0; nt<2; nt++) {
                oacc[mt][nt][0] *= corr0; oacc[mt][nt][1] *= corr0;
                oacc[mt][nt][2] *= corr1; oacc[mt][nt][3] *= corr1;
            }
            __syncwarp();
            // --- O += P @ V  (A = P[16x64], B = V^T slices) ---
            #pragma unroll
            for (int ks=0; ks<4; ks++) {
                uint32_t a[4];
                a[0] = *(const uint32_t*)(Ps + qr*PSH + ks*16 + 2*qc);
                a[1] = *(const uint32_t*)(Ps + (qr+8)*PSH + ks*16 + 2*qc);
                a[2] = *(const uint32_t*)(Ps + qr*PSH + ks*16 + 2*qc + 8);
                a[3] = *(const uint32_t*)(Ps + (qr+8)*PSH + ks*16 + 2*qc + 8);
                #pragma unroll
                for (int nt=0; nt<2; nt++) {
                    const __half* vb = Vs + (nt*8+qr)*VSH + kb + ks*16;
                    uint32_t b0 = *(const uint32_t*)(vb + 2*qc);
                    uint32_t b1 = *(const uint32_t*)(vb + 2*qc + 8);
                    MMA_F16(oacc[mt][nt], a, b0, b1);
                }
            }
            __syncwarp();
        }
    }

    // epilogue: normalize, write fp16
    #pragma unroll
    for (int mt=0; mt<2; mt++) {
        float inv0 = 1.f/lstate[mt][0];
        float inv1 = 1.f/lstate[mt][1];
        int row0 = q0 + mt*16 + qr;
        #pragma unroll
        for (int nt=0; nt<2; nt++) {
            int col = h*HD + nt*8 + 2*qc;
            __half* o0 = ao + ((size_t)b*T_SEQ + row0)*D + col;
            __half* o1 = ao + ((size_t)b*T_SEQ + row0 + 8)*D + col;
            *(half2*)o0 = __floats2half2_rn(oacc[mt][nt][0]*inv0, oacc[mt][nt][1]*inv0);
            *(half2*)o1 = __floats2half2_rn(oacc[mt][nt][2]*inv1, oacc[mt][nt][3]*inv1);
        }
    }
}

// ---------------- cross-attention (folded): xo += softmax(h@K'^T/32) @ V' -------
__global__ __launch_bounds__(256) void cross_attn_kernel(
    const float* __restrict__ Q, const float* __restrict__ Km,
    const float* __restrict__ Vm, float* __restrict__ xo)
{
    extern __shared__ float csm[];
    float* Ks = csm;
    float* Vs = csm + NMEM*D;
    int b = blockIdx.x >> 2;
    int chunk = blockIdx.x & 3;
    for (int i=threadIdx.x; i<NMEM*D; i+=256) {
        Ks[i] = Km[(size_t)b*NMEM*D + i];
        Vs[i] = Vm[(size_t)b*NMEM*D + i];
    }
    __syncthreads();
    int t = chunk*256 + threadIdx.x;
    const float4* qrow = (const float4*)(Q + ((size_t)b*T_SEQ + t)*D);
    float s[16];
    #pragma unroll
    for (int mm=0;mm<16;mm++) s[mm]=0.f;
    for (int k4=0;k4<D/4;k4++) {
        float4 qv = qrow[k4];
        #pragma unroll
        for (int mm=0;mm<16;mm++) {
            const float* kr = Ks + mm*D + k4*4;
            s[mm] += qv.x*kr[0] + qv.y*kr[1] + qv.z*kr[2] + qv.w*kr[3];
        }
    }
    float mx = -1e30f;
    #pragma unroll
    for (int mm=0;mm<16;mm++) { s[mm] *= 0.03125f; mx = fmaxf(mx, s[mm]); }
    float sum = 0.f;
    #pragma unroll
    for (int mm=0;mm<16;mm++) { s[mm] = __expf(s[mm]-mx); sum += s[mm]; }
    float inv = 1.f/sum;
    #pragma unroll
    for (int mm=0;mm<16;mm++) s[mm] *= inv;
    float* xrow = xo + ((size_t)b*T_SEQ + t)*D;
    for (int c=0;c<D;c+=4) {
        float4 o = *(const float4*)(xrow + c);
        #pragma unroll
        for (int mm=0;mm<16;mm++) {
            const float* vr = Vs + mm*D + c;
            o.x += s[mm]*vr[0]; o.y += s[mm]*vr[1];
            o.z += s[mm]*vr[2]; o.w += s[mm]*vr[3];
        }
        *(float4*)(xrow + c) = o;
    }
}

// ---------------- memory path -------------------------------------------------
__global__ __launch_bounds__(256) void mean_kernel(const float* __restrict__ x,
                                                   float* __restrict__ mh) {
    __shared__ float sred[256];
    int b = blockIdx.x, cb = blockIdx.y*128;
    int c = threadIdx.x & 127, half = threadIdx.x >> 7;
    const float* p = x + (size_t)b*T_SEQ*D + (size_t)half*512*D + cb + c;
    float s = 0.f;
    #pragma unroll 4
    for (int t=0;t<512;t++) s += p[(size_t)t*D];
    sred[threadIdx.x] = s;
    __syncthreads();
    if (half == 0)
        mh[b*D + cb + c] = (sred[threadIdx.x] + sred[threadIdx.x+128]) * (1.f/T_SEQ);
}

__global__ __launch_bounds__(256) void base_gemv(
    const float* __restrict__ Wz, const float* __restrict__ Wr, const float* __restrict__ Wc,
    const float* __restrict__ bz, const float* __restrict__ br, const float* __restrict__ bc)
{
    int gid = blockIdx.x*8 + (threadIdx.x >> 5);
    int lane = threadIdx.x & 31;
    int g = gid >> 12;
    int rem = gid & 4095;
    int b = rem >> 10;
    int col = rem & 1023;
    const float* W    = (g==0) ? Wz : ((g==1) ? Wr : Wc);
    const float* bias = (g==0) ? bz : ((g==1) ? br : bc);
    const float* wrow = W + (size_t)col*2048;
    const float* mrow = g_meanh + b*D;
    float acc = 0.f;
    #pragma unroll
    for (int k0=0;k0<1024;k0+=128) {
        float4 w = *(const float4*)(wrow + k0 + lane*4);
        float4 m = *(const float4*)(mrow + k0 + lane*4);
        acc += w.x*m.x + w.y*m.y + w.z*m.z + w.w*m.w;
    }
    #pragma unroll
    for (int o=16;o;o>>=1) acc += __shfl_xor_sync(0xFFFFFFFFu, acc, o);
    if (lane == 0) g_base[gid] = acc + bias[col];
}

__device__ __forceinline__ void tile64x64(
    const float* __restrict__ A, const float* __restrict__ B, int ldb,
    float (&acc)[4][4])
{
    __shared__ float As[32][65];
    __shared__ float Bs[32][65];
    const int tid = threadIdx.x;
    const int r  = tid >> 2;
    const int kq = (tid & 3) << 3;
    const int tx = tid & 15;
    const int ty = tid >> 4;
    for (int k0 = 0; k0 < 1024; k0 += 32) {
        float4 a0 = *(const float4*)(A + (size_t)r*1024 + k0 + kq);
        float4 a1 = *(const float4*)(A + (size_t)r*1024 + k0 + kq + 4);
        float4 b0 = *(const float4*)(B + (size_t)r*ldb  + k0 + kq);
        float4 b1 = *(const float4*)(B + (size_t)r*ldb  + k0 + kq + 4);
        __syncthreads();
        As[kq+0][r]=a0.x; As[kq+1][r]=a0.y; As[kq+2][r]=a0.z; As[kq+3][r]=a0.w;
        As[kq+4][r]=a1.x; As[kq+5][r]=a1.y; As[kq+6][r]=a1.z; As[kq+7][r]=a1.w;
        Bs[kq+0][r]=b0.x; Bs[kq+1][r]=b0.y; Bs[kq+2][r]=b0.z; Bs[kq+3][r]=b0.w;
        Bs[kq+4][r]=b1.x; Bs[kq+5][r]=b1.y; Bs[kq+6][r]=b1.z; Bs[kq+7][r]=b1.w;
        __syncthreads();
        #pragma unroll
        for (int kk=0;kk<32;kk++) {
            float a[4], b[4];
            #pragma unroll
            for (int i=0;i<4;i++) a[i] = As[kk][ty*4+i];
            #pragma unroll
            for (int j=0;j<4;j++) b[j] = Bs[kk][tx*4+j];
            #pragma unroll
            for (int i=0;i<4;i++)
                #pragma unroll
                for (int j=0;j<4;j++) acc[i][j] += a[i]*b[j];
        }
    }
}

__global__ __launch_bounds__(256) void zr_pre(
    const float* __restrict__ mem, const float* __restrict__ Wz,
    const float* __restrict__ Wr)
{
    int g = blockIdx.y;
    int ct = blockIdx.x;
    const float* W = (g ? Wr : Wz) + (size_t)(ct*64)*2048 + 1024;
    float acc[4][4];
    #pragma unroll
    for (int i=0;i<4;i++)
        #pragma unroll
        for (int j=0;j<4;j++) acc[i][j]=0.f;
    tile64x64(mem, W, 2048, acc);
    float* out = g ? g_rpre : g_zpre;
    const int tx = threadIdx.x & 15, ty = threadIdx.x >> 4;
    #pragma unroll
    for (int i=0;i<4;i++) {
        int row = ty*4+i;
        #pragma unroll
        for (int j=0;j<4;j++) out[row*1024 + ct*64 + tx*4+j] = acc[i][j];
    }
}

__global__ void combine_kernel(const float* __restrict__ mem) {
    int idx = blockIdx.x*blockDim.x + threadIdx.x;
    int row = idx >> 10, col = idx & 1023, b = row >> 4;
    float z = 1.f/(1.f + __expf(-(g_zpre[idx] + g_base[0*4096 + b*1024 + col])));
    float r = 1.f/(1.f + __expf(-(g_rpre[idx] + g_base[1*4096 + b*1024 + col])));
    g_z[idx] = z;
    g_rm[idx] = r * mem[idx];
}

__global__ __launch_bounds__(256) void c_gemm(
    const float* __restrict__ mem, const float* __restrict__ Wc,
    float* __restrict__ newmem)
{
    int ct = blockIdx.x;
    const float* W = Wc + (size_t)(ct*64)*2048 + 1024;
    float acc[4][4];
    #pragma unroll
    for (int i=0;i<4;i++)
        #pragma unroll
        for (int j=0;j<4;j++) acc[i][j]=0.f;
    tile64x64(g_rm, W, 2048, acc);
    const int tx = threadIdx.x & 15, ty = threadIdx.x >> 4;
    #pragma unroll
    for (int i=0;i<4;i++) {
        int row = ty*4+i;
        #pragma unroll
        for (int j=0;j<4;j++) {
            int col = ct*64 + tx*4+j;
            float v = acc[i][j] + g_base[2*4096 + (row>>4)*1024 + col];
            float c = tanhf(v);
            float z = g_z[row*1024+col];
            newmem[(size_t)row*1024+col] = (1.f - z)*mem[(size_t)row*1024+col] + z*c;
        }
    }
}

__global__ __launch_bounds__(256) void kv2_gemm(const float* __restrict__ newmem)
{
    int which = blockIdx.y;
    int ct = blockIdx.x;
    const float* W = (which ? g_wv : g_wk) + (size_t)(ct*64)*1024;
    float acc[4][4];
    #pragma unroll
    for (int i=0;i<4;i++)
        #pragma unroll
        for (int j=0;j<4;j++) acc[i][j]=0.f;
    tile64x64(newmem, W, 1024, acc);
    float* out = which ? g_V : g_K;
    const int tx = threadIdx.x & 15, ty = threadIdx.x >> 4;
    #pragma unroll
    for (int i=0;i<4;i++) {
        int row = ty*4+i;
        #pragma unroll
        for (int j=0;j<4;j++) {
            int col = ct*64 + tx*4+j;
            out[(size_t)row*1024+col] = acc[i][j];
        }
    }
}

// ---------------- host launcher -------------------------------------------------
extern "C" void kernel_launch(void* const* d_in, const int* in_sizes, int n_in,
                              void* d_out, int out_size)
{
    const float* x          = (const float*)d_in[0];
    const float* memory     = (const float*)d_in[1];
    const float* ln1_g      = (const float*)d_in[2];
    const float* ln1_b      = (const float*)d_in[3];
    const float* ln2_g      = (const float*)d_in[4];
    const float* ln2_b      = (const float*)d_in[5];
    const float* ln3_g      = (const float*)d_in[6];
    const float* ln3_b      = (const float*)d_in[7];
    const float* in_proj_w  = (const float*)d_in[8];
    const float* in_proj_b  = (const float*)d_in[9];
    const float* attn_out_w = (const float*)d_in[10];
    const float* attn_out_b = (const float*)d_in[11];
    const float* Wz_w       = (const float*)d_in[12];
    const float* Wz_b       = (const float*)d_in[13];
    const float* Wr_w       = (const float*)d_in[14];
    const float* Wr_b       = (const float*)d_in[15];
    const float* Wc_w       = (const float*)d_in[16];
    const float* Wc_b       = (const float*)d_in[17];
    const float* mq_w       = (const float*)d_in[18];
    const float* mk_w       = (const float*)d_in[19];
    const float* mv_w       = (const float*)d_in[20];
    const float* mo_w       = (const float*)d_in[21];
    const float* W1         = (const float*)d_in[22];
    const float* b1         = (const float*)d_in[23];
    const float* W2         = (const float*)d_in[24];
    const float* b2         = (const float*)d_in[25];

    float* xo = (float*)d_out;
    float* newmem = xo + (size_t)ROWS*D;

    float *p_h, *p_K, *p_V, *p_w, *p_mh, *p_wk, *p_wv;
    __half *p_hh, *p_hqkv, *p_hao, *p_hffn, *p_hw;
    cudaGetSymbolAddress((void**)&p_h,    g_h);
    cudaGetSymbolAddress((void**)&p_K,    g_K);
    cudaGetSymbolAddress((void**)&p_V,    g_V);
    cudaGetSymbolAddress((void**)&p_w,    g_w);
    cudaGetSymbolAddress((void**)&p_mh,   g_meanh);
    cudaGetSymbolAddress((void**)&p_wk,   g_wk);
    cudaGetSymbolAddress((void**)&p_wv,   g_wv);
    cudaGetSymbolAddress((void**)&p_hh,   h_h);
    cudaGetSymbolAddress((void**)&p_hqkv, h_qkv);
    cudaGetSymbolAddress((void**)&p_hao,  h_ao);
    cudaGetSymbolAddress((void**)&p_hffn, h_ffn);
    cudaGetSymbolAddress((void**)&p_hw,   h_w);

    static cudaStream_t s2 = nullptr;
    static cudaEvent_t evStart = nullptr, evCvt = nullptr, evFork = nullptr, evMem = nullptr;
    static bool tried = false, ok = false;
    if (!tried) {
        tried = true;
        ok = (cudaStreamCreateWithFlags(&s2, cudaStreamNonBlocking) == cudaSuccess) &&
             (cudaEventCreateWithFlags(&evStart, cudaEventDisableTiming) == cudaSuccess) &&
             (cudaEventCreateWithFlags(&evCvt,   cudaEventDisableTiming) == cudaSuccess) &&
             (cudaEventCreateWithFlags(&evFork,  cudaEventDisableTiming) == cudaSuccess) &&
             (cudaEventCreateWithFlags(&evMem,   cudaEventDisableTiming) == cudaSuccess);
    }
    cudaStream_t sb = ok ? s2 : (cudaStream_t)0;

    cudaFuncSetAttribute(flash_attn_kernel, cudaFuncAttributeMaxDynamicSharedMemorySize, FLASH_SMEM);
    cudaFuncSetAttribute(cross_attn_kernel, cudaFuncAttributeMaxDynamicSharedMemorySize, 131072);
    const int GSM = SMEM_FLOATS * 4;
    cudaFuncSetAttribute(gemm_tf32<0,0,0,0>, cudaFuncAttributeMaxDynamicSharedMemorySize, GSM);

    // ---- early hidden phase on sb ----
    if (ok) { cudaEventRecord(evStart, 0); cudaStreamWaitEvent(sb, evStart, 0); }
    cvt_fp16_kernel<<<3072, 256, 0, sb>>>(in_proj_w,  p_hw + HOFF_INP,  3*1024*1024/4);
    cvt_fp16_kernel<<<1024, 256, 0, sb>>>(attn_out_w, p_hw + HOFF_AOUT, 1024*1024/4);
    cvt_fp16_kernel<<<4096, 256, 0, sb>>>(W1,         p_hw + HOFF_W1,   4*1024*1024/4);
    cvt_fp16_kernel<<<4096, 256, 0, sb>>>(W2,         p_hw + HOFF_W2,   4*1024*1024/4);
    if (ok) cudaEventRecord(evCvt, sb);
    cvt_tf32_kernel<<<1024, 256, 0, sb>>>(mo_w, p_w + OFF_MO, 1024*1024/4);
    transpose_tf32<<<dim3(32,32), dim3(32,8), 0, sb>>>(mq_w, p_w + OFF_MQT);
    transpose_tf32<<<dim3(32,32), dim3(32,8), 0, sb>>>(mk_w, p_w + OFF_MKT);
    transpose_tf32<<<dim3(32,32), dim3(32,8), 0, sb>>>(mv_w, p_w + OFF_MVT);
    gemm_tf32<0,0,0,0><<<dim3(8,8), 256, GSM, sb>>>(p_w + OFF_MQT, p_w + OFF_MKT, nullptr, nullptr, p_wk, 1024, 1024, 1024);
    gemm_tf32<0,0,0,0><<<dim3(8,8), 256, GSM, sb>>>(p_w + OFF_MO,  p_w + OFF_MVT, nullptr, nullptr, p_wv, 1024, 1024, 1024);
    zr_pre<<<dim3(16,2), 256, 0, sb>>>(memory, Wz_w, Wr_w);

    // ---- main path ----
    ln_kernel_h<<<ROWS, 256>>>(x, ln1_g, ln1_b, p_hh);
    if (ok) cudaStreamWaitEvent(0, evCvt, 0);

    gemm_fp16<0,1,0,1><<<dim3(3*D/128, ROWS/128), 256, HSMEM_BYTES>>>(p_hh, p_hw + HOFF_INP, in_proj_b, nullptr, p_hqkv, ROWS, 3*D, D);
    flash_attn_kernel<<<dim3(BATCH*NHEADS, 4), 256, FLASH_SMEM>>>(p_hqkv, p_hao);
    gemm_fp16<0,1,1,0><<<dim3(D/128, ROWS/128), 256, HSMEM_BYTES>>>(p_hao, p_hw + HOFF_AOUT, attn_out_b, x, xo, ROWS, D, D);

    // ---- fork memory path onto sb ----
    if (ok) { cudaEventRecord(evFork, 0); cudaStreamWaitEvent(sb, evFork, 0); }
    mean_kernel<<<dim3(BATCH, 8), 256, 0, sb>>>(xo, p_mh);
    base_gemv<<<1536, 256, 0, sb>>>(Wz_w, Wr_w, Wc_w, Wz_b, Wr_b, Wc_b);
    combine_kernel<<<BATCH*NMEM*D/256, 256, 0, sb>>>(memory);
    c_gemm<<<16, 256, 0, sb>>>(memory, Wc_w, newmem);
    kv2_gemm<<<dim3(16, 2), 256, 0, sb>>>(newmem);
    if (ok) cudaEventRecord(evMem, sb);

    // ---- main path: LN2 (float), then folded cross-attention ----
    ln_kernel<<<ROWS, 256>>>(xo, ln2_g, ln2_b, p_h);
    if (ok) cudaStreamWaitEvent(0, evMem, 0);
    cross_attn_kernel<<<BATCH*4, 256, 131072>>>(p_h, p_K, p_V, xo);

    // FFN
    ln_kernel_h<<<ROWS, 256>>>(xo, ln3_g, ln3_b, p_hh);
    gemm_fp16<1,1,0,1><<<dim3(4*D/128, ROWS/128), 256, HSMEM_BYTES>>>(p_hh, p_hw + HOFF_W1, b1, nullptr, p_hffn, ROWS, 4*D, D);
    gemm_fp16<0,1,1,0><<<dim3(D/128, ROWS/128), 256, HSMEM_BYTES>>>(p_hffn, p_hw + HOFF_W2, b2, xo, xo, ROWS, D, 4*D);
}

// round 13
// speedup vs baseline: 5.1586x; 1.0474x over previous
#include <cuda_runtime.h>
#include <cuda_fp16.h>
#include <math.h>
#include <stdint.h>

#define D 1024
#define T_SEQ 1024
#define BATCH 4
#define NMEM 16
#define NHEADS 64
#define HD 16
#define ROWS (BATCH*T_SEQ)   // 4096

// ---------------- scratch (device globals; no runtime allocation) ----------------
__device__ float g_h[ROWS*D];            // LN2 output (float, feeds cross-attn)
__device__ __half h_h[ROWS*D];           // LN1/LN3 outputs (fp16)
__device__ __half h_qkv[ROWS*3*D];       // QKV (fp16)
__device__ __half h_ao[ROWS*D];          // self-attention output (fp16)
__device__ __half h_ffn[ROWS*4*D];       // FFN hidden (fp16)
__device__ float g_meanh[BATCH*D];
__device__ float g_base[3*BATCH*D];
__device__ float g_zpre[BATCH*NMEM*D];
__device__ float g_rpre[BATCH*NMEM*D];
__device__ float g_z[BATCH*NMEM*D];
__device__ float g_rm[BATCH*NMEM*D];
__device__ float g_K[BATCH*NMEM*D];
__device__ float g_V[BATCH*NMEM*D];
__device__ float g_wk[1024*1024];        // Wk' = mq^T @ mk
__device__ float g_wv[1024*1024];        // Wv' = mo @ mv
__device__ float g_w[8*1024*1024];       // float scratch for fold path
__device__ __half h_w[12*1024*1024];     // fp16 weight copies

#define OFF_MQT   0
#define OFF_MO    (1*1024*1024)
#define OFF_MKT   (2*1024*1024)
#define OFF_MVT   (3*1024*1024)
#define HOFF_INP  0
#define HOFF_AOUT (3*1024*1024)
#define HOFF_W1   (4*1024*1024)
#define HOFF_W2   (8*1024*1024)

__device__ __forceinline__ float to_tf32(float v) {
    uint32_t r;
    asm("cvt.rna.tf32.f32 %0, %1;" : "=r"(r) : "f"(v));
    return __uint_as_float(r);
}

// ---------------- utility kernels ----------------
__global__ void cvt_tf32_kernel(const float* __restrict__ src, float* __restrict__ dst, int n4) {
    int i = blockIdx.x*blockDim.x + threadIdx.x;
    if (i < n4) {
        float4 v = ((const float4*)src)[i];
        v.x = to_tf32(v.x); v.y = to_tf32(v.y); v.z = to_tf32(v.z); v.w = to_tf32(v.w);
        ((float4*)dst)[i] = v;
    }
}

__global__ void cvt_fp16_kernel(const float* __restrict__ src, __half* __restrict__ dst, int n4) {
    int i = blockIdx.x*blockDim.x + threadIdx.x;
    if (i < n4) {
        float4 v = ((const float4*)src)[i];
        half2 lo = __floats2half2_rn(v.x, v.y);
        half2 hi = __floats2half2_rn(v.z, v.w);
        ((half2*)dst)[2*i]   = lo;
        ((half2*)dst)[2*i+1] = hi;
    }
}

__global__ __launch_bounds__(256) void transpose_tf32(
    const float* __restrict__ src, float* __restrict__ dst)
{
    __shared__ float tile[32][33];
    int x = blockIdx.x*32 + threadIdx.x;
    int y0 = blockIdx.y*32 + threadIdx.y;
    #pragma unroll
    for (int i=0;i<32;i+=8)
        tile[threadIdx.y+i][threadIdx.x] = src[(size_t)(y0+i)*1024 + x];
    __syncthreads();
    int x2 = blockIdx.y*32 + threadIdx.x;
    int y2 = blockIdx.x*32 + threadIdx.y;
    #pragma unroll
    for (int i=0;i<32;i+=8)
        dst[(size_t)(y2+i)*1024 + x2] = to_tf32(tile[threadIdx.x][threadIdx.y+i]);
}

__global__ __launch_bounds__(256) void ln_kernel(
    const float* __restrict__ x, const float* __restrict__ g,
    const float* __restrict__ b, float* __restrict__ y)
{
    __shared__ float s1[256], s2[256];
    int row = blockIdx.x;
    const float4* xr = (const float4*)(x + (size_t)row*D);
    float4 v = xr[threadIdx.x];
    float sum = v.x+v.y+v.z+v.w;
    float sq  = v.x*v.x + v.y*v.y + v.z*v.z + v.w*v.w;
    s1[threadIdx.x]=sum; s2[threadIdx.x]=sq;
    __syncthreads();
    for (int off=128; off; off>>=1) {
        if (threadIdx.x < off) {
            s1[threadIdx.x]+=s1[threadIdx.x+off];
            s2[threadIdx.x]+=s2[threadIdx.x+off];
        }
        __syncthreads();
    }
    float mean = s1[0]*(1.0f/D);
    float var  = s2[0]*(1.0f/D) - mean*mean;
    float rstd = rsqrtf(var + 1e-5f);
    int c = threadIdx.x*4;
    float4 gg = *(const float4*)(g+c);
    float4 bb = *(const float4*)(b+c);
    float4 o;
    o.x = (v.x-mean)*rstd*gg.x + bb.x;
    o.y = (v.y-mean)*rstd*gg.y + bb.y;
    o.z = (v.z-mean)*rstd*gg.z + bb.z;
    o.w = (v.w-mean)*rstd*gg.w + bb.w;
    ((float4*)(y + (size_t)row*D))[threadIdx.x] = o;
}

__global__ __launch_bounds__(256) void ln_kernel_h(
    const float* __restrict__ x, const float* __restrict__ g,
    const float* __restrict__ b, __half* __restrict__ y)
{
    __shared__ float s1[256], s2[256];
    int row = blockIdx.x;
    const float4* xr = (const float4*)(x + (size_t)row*D);
    float4 v = xr[threadIdx.x];
    float sum = v.x+v.y+v.z+v.w;
    float sq  = v.x*v.x + v.y*v.y + v.z*v.z + v.w*v.w;
    s1[threadIdx.x]=sum; s2[threadIdx.x]=sq;
    __syncthreads();
    for (int off=128; off; off>>=1) {
        if (threadIdx.x < off) {
            s1[threadIdx.x]+=s1[threadIdx.x+off];
            s2[threadIdx.x]+=s2[threadIdx.x+off];
        }
        __syncthreads();
    }
    float mean = s1[0]*(1.0f/D);
    float var  = s2[0]*(1.0f/D) - mean*mean;
    float rstd = rsqrtf(var + 1e-5f);
    int c = threadIdx.x*4;
    float4 gg = *(const float4*)(g+c);
    float4 bb = *(const float4*)(b+c);
    half2 lo = __floats2half2_rn((v.x-mean)*rstd*gg.x + bb.x, (v.y-mean)*rstd*gg.y + bb.y);
    half2 hi = __floats2half2_rn((v.z-mean)*rstd*gg.z + bb.z, (v.w-mean)*rstd*gg.w + bb.w);
    half2* yr = (half2*)(y + (size_t)row*D);
    yr[threadIdx.x*2]   = lo;
    yr[threadIdx.x*2+1] = hi;
}

__device__ __forceinline__ void cp16(uint32_t dst, const void* src) {
    asm volatile("cp.async.cg.shared.global [%0], [%1], 16;" :: "r"(dst), "l"(src));
}

#define LDM_X4(r0, r1, r2, r3, addr) \
    asm volatile("ldmatrix.sync.aligned.m8n8.x4.shared.b16 {%0,%1,%2,%3}, [%4];" \
        : "=r"(r0), "=r"(r1), "=r"(r2), "=r"(r3) : "r"(addr))

// ---------------- fp16 tensor-core GEMM: C(M,N) = A(M,K) @ B(N,K)^T -------------
// m16n8k16 HMMA, fp32 accum. 128x128 tile, BK=32, 4-stage cp.async, ldmatrix frags.
#define HA_OFF(buf) ((buf)*10240)
#define HB_OFF(buf) (5120 + (buf)*10240)
#define HSMEM_BYTES (4*10240*2)   // 81920 B

template<int ACT, int BIASF, int RESF, int OUTHALF>
__global__ __launch_bounds__(256, 2) void gemm_fp16(
    const __half* __restrict__ A, const __half* __restrict__ B,
    const float* __restrict__ bias, const float* __restrict__ res,
    void* __restrict__ Cv, int M, int N, int K)
{
    extern __shared__ __half hsm[];
    float* Cf = (float*)Cv;
    __half* Ch = (__half*)Cv;
    const int tid = threadIdx.x;
    const int bm = blockIdx.y * 128;
    const int bn = blockIdx.x * 128;
    const int lane = tid & 31;
    const int warp = tid >> 5;
    const int wm64 = (warp & 1) * 64;
    const int wn32 = (warp >> 1) * 32;
    const int qr = lane >> 2;
    const int qc = lane & 3;
    uint32_t smem_u32 = (uint32_t)__cvta_generic_to_shared(hsm);

    // ldmatrix per-lane row/col offsets (match scalar fragment layout)
    const int a_row = wm64 + (lane & 7) + ((lane >> 3) & 1) * 8;  // + i*16
    const int a_kk  = (lane >> 4) * 8;
    const int b_row = wn32 + (lane & 7) + ((lane >= 16) ? 8 : 0); // + jp*16
    const int b_kk  = ((lane >> 3) & 1) * 8;

    const int ld_row = tid >> 2;        // 0..63 (+64 per rep)
    const int ld_seg = (tid & 3) * 8;   // halves

    float acc[4][4][4];
    #pragma unroll
    for (int i=0;i<4;i++)
        #pragma unroll
        for (int j=0;j<4;j++)
            #pragma unroll
            for (int e=0;e<4;e++) acc[i][j][e] = 0.f;

    const int NT = K >> 5;

    // prologue: prefetch stages 0..2
    #pragma unroll
    for (int p=0; p<3; p++) {
        const __half* Ab = A + (size_t)bm*K + p*32;
        const __half* Bb = B + (size_t)bn*K + p*32;
        #pragma unroll
        for (int rep=0; rep<2; rep++) {
            int row = rep*64 + ld_row;
            cp16(smem_u32 + (HA_OFF(p) + row*40 + ld_seg)*2, Ab + (size_t)row*K + ld_seg);
            cp16(smem_u32 + (HB_OFF(p) + row*40 + ld_seg)*2, Bb + (size_t)row*K + ld_seg);
        }
        asm volatile("cp.async.commit_group;");
    }

    for (int t = 0; t < NT; t++) {
        if (t + 3 <= NT)      asm volatile("cp.async.wait_group 2;");
        else if (t + 2 == NT) asm volatile("cp.async.wait_group 1;");
        else                  asm volatile("cp.async.wait_group 0;");
        __syncthreads();

        if (t + 3 < NT) {
            int buf = (t+3) & 3;
            int kb = (t+3) << 5;
            const __half* Ab = A + (size_t)bm*K + kb;
            const __half* Bb = B + (size_t)bn*K + kb;
            #pragma unroll
            for (int rep=0; rep<2; rep++) {
                int row = rep*64 + ld_row;
                cp16(smem_u32 + (HA_OFF(buf) + row*40 + ld_seg)*2, Ab + (size_t)row*K + ld_seg);
                cp16(smem_u32 + (HB_OFF(buf) + row*40 + ld_seg)*2, Bb + (size_t)row*K + ld_seg);
            }
            asm volatile("cp.async.commit_group;");
        }

        const uint32_t abuf = HA_OFF(t & 3);
        const uint32_t bbuf = HB_OFF(t & 3);

        #pragma unroll
        for (int ks = 0; ks < 2; ks++) {
            const int k0 = ks * 16;
            uint32_t a[4][4], b[4][2];
            #pragma unroll
            for (int i=0;i<4;i++) {
                uint32_t ad = smem_u32 + (abuf + (a_row + i*16)*40 + k0 + a_kk)*2;
                LDM_X4(a[i][0], a[i][1], a[i][2], a[i][3], ad);
            }
            #pragma unroll
            for (int jp=0; jp<2; jp++) {
                uint32_t bd = smem_u32 + (bbuf + (b_row + jp*16)*40 + k0 + b_kk)*2;
                LDM_X4(b[2*jp][0], b[2*jp][1], b[2*jp+1][0], b[2*jp+1][1], bd);
            }
            #pragma unroll
            for (int i=0;i<4;i++)
                #pragma unroll
                for (int j=0;j<4;j++) {
                    asm volatile(
                        "mma.sync.aligned.m16n8k16.row.col.f32.f16.f16.f32 "
                        "{%0,%1,%2,%3}, {%4,%5,%6,%7}, {%8,%9}, {%0,%1,%2,%3};"
                        : "+f"(acc[i][j][0]), "+f"(acc[i][j][1]),
                          "+f"(acc[i][j][2]), "+f"(acc[i][j][3])
                        : "r"(a[i][0]), "r"(a[i][1]), "r"(a[i][2]), "r"(a[i][3]),
                          "r"(b[j][0]), "r"(b[j][1]));
                }
        }
        __syncthreads();
    }

    #pragma unroll
    for (int i=0;i<4;i++) {
        int row0 = bm + wm64 + i*16 + qr;
        #pragma unroll
        for (int j=0;j<4;j++) {
            int col0 = bn + wn32 + j*8 + qc*2;
            float v0 = acc[i][j][0], v1 = acc[i][j][1];
            float v2 = acc[i][j][2], v3 = acc[i][j][3];
            if (BIASF) {
                float b0 = bias[col0], b1 = bias[col0+1];
                v0 += b0; v1 += b1; v2 += b0; v3 += b1;
            }
            if (ACT == 1) {
                v0 = 0.5f*v0*(1.f + erff(v0*0.70710678118654752f));
                v1 = 0.5f*v1*(1.f + erff(v1*0.70710678118654752f));
                v2 = 0.5f*v2*(1.f + erff(v2*0.70710678118654752f));
                v3 = 0.5f*v3*(1.f + erff(v3*0.70710678118654752f));
            }
            if (RESF) {
                v0 += res[(size_t)row0*N + col0];
                v1 += res[(size_t)row0*N + col0 + 1];
                v2 += res[(size_t)(row0+8)*N + col0];
                v3 += res[(size_t)(row0+8)*N + col0 + 1];
            }
            if (OUTHALF) {
                *(half2*)(Ch + (size_t)row0*N + col0)     = __floats2half2_rn(v0, v1);
                *(half2*)(Ch + (size_t)(row0+8)*N + col0) = __floats2half2_rn(v2, v3);
            } else {
                *(float2*)(Cf + (size_t)row0*N + col0)     = make_float2(v0, v1);
                *(float2*)(Cf + (size_t)(row0+8)*N + col0) = make_float2(v2, v3);
            }
        }
    }
}

// ---------------- legacy mma.sync tf32 GEMM (hidden weight-fold GEMMs) ----------
#define SMEM_FLOATS (4*4608)
#define A_OFFS(buf) ((buf)*4608)
#define B_OFFS(buf) (9216 + (buf)*4608)

template<int ACT, int BIASF, int RESF, int TF32OUT>
__global__ __launch_bounds__(256, 2) void gemm_tf32(
    const float* __restrict__ A, const float* __restrict__ B,
    const float* __restrict__ bias, const float* __restrict__ res,
    float* __restrict__ C, int M, int N, int K)
{
    extern __shared__ float sm[];
    const int tid = threadIdx.x;
    const int bm = blockIdx.y * 128;
    const int bn = blockIdx.x * 128;
    const int lane = tid & 31;
    const int warp = tid >> 5;
    const int wm64 = (warp & 1) * 64;
    const int wn32 = (warp >> 1) * 32;
    const int qr = lane >> 2;
    const int qc = lane & 3;
    uint32_t smem_u32 = (uint32_t)__cvta_generic_to_shared(sm);
    const int lrow = tid >> 3;
    const int lkq  = (tid & 7) * 4;

    float acc[4][4][4];
    #pragma unroll
    for (int i=0;i<4;i++)
        #pragma unroll
        for (int j=0;j<4;j++)
            #pragma unroll
            for (int e=0;e<4;e++) acc[i][j][e] = 0.f;

    const int NT = K >> 5;
    {
        const float* Ab = A + (size_t)bm*K;
        const float* Bb = B + (size_t)bn*K;
        #pragma unroll
        for (int rep=0; rep<4; rep++) {
            int row = rep*32 + lrow;
            cp16(smem_u32 + (A_OFFS(0) + row*36 + lkq)*4, Ab + (size_t)row*K + lkq);
            cp16(smem_u32 + (B_OFFS(0) + row*36 + lkq)*4, Bb + (size_t)row*K + lkq);
        }
        asm volatile("cp.async.commit_group;");
    }
    for (int t = 0; t < NT; t++) {
        if (t + 1 < NT) {
            int buf = (t+1) & 1;
            int kb = (t+1) << 5;
            const float* Ab = A + (size_t)bm*K + kb;
            const float* Bb = B + (size_t)bn*K + kb;
            #pragma unroll
            for (int rep=0; rep<4; rep++) {
                int row = rep*32 + lrow;
                cp16(smem_u32 + (A_OFFS(buf) + row*36 + lkq)*4, Ab + (size_t)row*K + lkq);
                cp16(smem_u32 + (B_OFFS(buf) + row*36 + lkq)*4, Bb + (size_t)row*K + lkq);
            }
            asm volatile("cp.async.commit_group;");
            asm volatile("cp.async.wait_group 1;");
        } else {
            asm volatile("cp.async.wait_group 0;");
        }
        __syncthreads();
        const float* sA = sm + A_OFFS(t & 1);
        const float* sB = sm + B_OFFS(t & 1);
        #pragma unroll
        for (int ks = 0; ks < 4; ks++) {
            const int k0 = ks * 8;
            uint32_t a[4][4], b[4][2];
            #pragma unroll
            for (int i=0;i<4;i++) {
                int r = wm64 + i*16 + qr;
                a[i][0] = __float_as_uint(sA[r*36 + k0 + qc]);
                a[i][1] = __float_as_uint(sA[(r+8)*36 + k0 + qc]);
                a[i][2] = __float_as_uint(sA[r*36 + k0 + qc + 4]);
                a[i][3] = __float_as_uint(sA[(r+8)*36 + k0 + qc + 4]);
            }
            #pragma unroll
            for (int j=0;j<4;j++) {
                int n = wn32 + j*8 + qr;
                b[j][0] = __float_as_uint(sB[n*36 + k0 + qc]);
                b[j][1] = __float_as_uint(sB[n*36 + k0 + qc + 4]);
            }
            #pragma unroll
            for (int i=0;i<4;i++)
                #pragma unroll
                for (int j=0;j<4;j++) {
                    asm volatile(
                        "mma.sync.aligned.m16n8k8.row.col.f32.tf32.tf32.f32 "
                        "{%0,%1,%2,%3}, {%4,%5,%6,%7}, {%8,%9}, {%0,%1,%2,%3};"
                        : "+f"(acc[i][j][0]), "+f"(acc[i][j][1]),
                          "+f"(acc[i][j][2]), "+f"(acc[i][j][3])
                        : "r"(a[i][0]), "r"(a[i][1]), "r"(a[i][2]), "r"(a[i][3]),
                          "r"(b[j][0]), "r"(b[j][1]));
                }
        }
        __syncthreads();
    }
    #pragma unroll
    for (int i=0;i<4;i++) {
        int row0 = bm + wm64 + i*16 + qr;
        #pragma unroll
        for (int j=0;j<4;j++) {
            int col0 = bn + wn32 + j*8 + qc*2;
            float v0 = acc[i][j][0], v1 = acc[i][j][1];
            float v2 = acc[i][j][2], v3 = acc[i][j][3];
            *(float2*)(C + (size_t)row0*N + col0)     = make_float2(v0, v1);
            *(float2*)(C + (size_t)(row0+8)*N + col0) = make_float2(v2, v3);
        }
    }
}

// ---------------- fp16 tensor-core flash self-attention -------------------------
#define KSH 24
#define VSH 1032
#define PSH 72
#define FLASH_SMEM ((1024*KSH + 16*VSH + 8*16*PSH)*2)

#define MMA_F16(acc, a, b0, b1) \
    asm volatile( \
        "mma.sync.aligned.m16n8k16.row.col.f32.f16.f16.f32 " \
        "{%0,%1,%2,%3}, {%4,%5,%6,%7}, {%8,%9}, {%0,%1,%2,%3};" \
        : "+f"((acc)[0]), "+f"((acc)[1]), "+f"((acc)[2]), "+f"((acc)[3]) \
        : "r"((a)[0]), "r"((a)[1]), "r"((a)[2]), "r"((a)[3]), \
          "r"(b0), "r"(b1))

__global__ __launch_bounds__(256) void flash_attn_kernel(
    const __half* __restrict__ qkv, __half* __restrict__ ao)
{
    extern __shared__ __half fsm[];
    __half* Ks = fsm;
    __half* Vs = fsm + 1024*KSH;
    __half* Ps = Vs + 16*VSH + (threadIdx.x >> 5)*16*PSH;

    const int b = blockIdx.x >> 6;
    const int h = blockIdx.x & 63;
    const int qt = blockIdx.y;
    const int tid = threadIdx.x;
    const int lane = tid & 31;
    const int warp = tid >> 5;
    const int qr = lane >> 2;
    const int qc = lane & 3;

    const __half* base = qkv + (size_t)b*T_SEQ*3*D + h*HD;

    for (int r = tid; r < T_SEQ; r += 256) {
        const uint32_t* kr = (const uint32_t*)(base + (size_t)r*3*D + D);
        #pragma unroll
        for (int i=0;i<8;i++) *(uint32_t*)(Ks + r*KSH + i*2) = kr[i];
        const __half* vr = base + (size_t)r*3*D + 2*D;
        #pragma unroll
        for (int d=0; d<16; d++) Vs[d*VSH + r] = vr[d];
    }

    const int q0 = qt*256 + warp*32;
    const half2 qs = __floats2half2_rn(0.25f, 0.25f);
    uint32_t aQ[2][4];
    #pragma unroll
    for (int mt=0; mt<2; mt++) {
        int r0 = q0 + mt*16 + qr;
        half2 v0 = __hmul2(*(const half2*)(base + (size_t)r0*3*D + 2*qc), qs);
        half2 v1 = __hmul2(*(const half2*)(base + (size_t)(r0+8)*3*D + 2*qc), qs);
        half2 v2 = __hmul2(*(const half2*)(base + (size_t)r0*3*D + 2*qc + 8), qs);
        half2 v3 = __hmul2(*(const half2*)(base + (size_t)(r0+8)*3*D + 2*qc + 8), qs);
        aQ[mt][0] = *(uint32_t*)&v0; aQ[mt][1] = *(uint32_t*)&v1;
        aQ[mt][2] = *(uint32_t*)&v2; aQ[mt][3] = *(uint32_t*)&v3;
    }
    __syncthreads();

    float mstate[2][2], lstate[2][2], oacc[2][2][4];
    #pragma unroll
    for (int mt=0; mt<2; mt++) {
        mstate[mt][0] = -1e30f; mstate[mt][1] = -1e30f;
        lstate[mt][0] = 0.f;    lstate[mt][1] = 0.f;
        #pragma unroll
        for (int nt=0; nt<2; nt++)
            #pragma unroll
            for (int e=0; e<4; e++) oacc[mt][nt][e] = 0.f;
    }

    for (int nc = 0; nc < 16; nc++) {
        const int kb = nc*64;
        #pragma unroll
        for (int mt=0; mt<2; mt++) {
            float sacc[8][4];
            #pragma unroll
            for (int nt=0; nt<8; nt++) {
                sacc[nt][0]=0.f; sacc[nt][1]=0.f; sacc[nt][2]=0.f; sacc[nt][3]=0.f;
                const int key = kb + nt*8 + qr;
                uint32_t b0 = *(const uint32_t*)(Ks + key*KSH + 2*qc);
                uint32_t b1 = *(const uint32_t*)(Ks + key*KSH + 2*qc + 8);
                MMA_F16(sacc[nt], aQ[mt], b0, b1);
            }
            float r0max = -1e30f, r1max = -1e30f;
            #pragma unroll
            for (int nt=0; nt<8; nt++) {
                r0max = fmaxf(r0max, fmaxf(sacc[nt][0], sacc[nt][1]));
                r1max = fmaxf(r1max, fmaxf(sacc[nt][2], sacc[nt][3]));
            }
            r0max = fmaxf(r0max, __shfl_xor_sync(0xFFFFFFFFu, r0max, 1));
            r0max = fmaxf(r0max, __shfl_xor_sync(0xFFFFFFFFu, r0max, 2));
            r1max = fmaxf(r1max, __shfl_xor_sync(0xFFFFFFFFu, r1max, 1));
            r1max = fmaxf(r1max, __shfl_xor_sync(0xFFFFFFFFu, r1max, 2));
            float mnew0 = fmaxf(mstate[mt][0], r0max);
            float mnew1 = fmaxf(mstate[mt][1], r1max);
            float corr0 = __expf(mstate[mt][0] - mnew0);
            float corr1 = __expf(mstate[mt][1] - mnew1);
            mstate[mt][0] = mnew0; mstate[mt][1] = mnew1;

            float rs0 = 0.f, rs1 = 0.f;
            #pragma unroll
            for (int nt=0; nt<8; nt++) {
                float p0 = __expf(sacc[nt][0] - mnew0);
                float p1 = __expf(sacc[nt][1] - mnew0);
                float p2 = __expf(sacc[nt][2] - mnew1);
                float p3 = __expf(sacc[nt][3] - mnew1);
                rs0 += p0 + p1; rs1 += p2 + p3;
                *(half2*)(Ps + qr*PSH + nt*8 + 2*qc)     = __floats2half2_rn(p0, p1);
                *(half2*)(Ps + (qr+8)*PSH + nt*8 + 2*qc) = __floats2half2_rn(p2, p3);
            }
            rs0 += __shfl_xor_sync(0xFFFFFFFFu, rs0, 1);
            rs0 += __shfl_xor_sync(0xFFFFFFFFu, rs0, 2);
            rs1 += __shfl_xor_sync(0xFFFFFFFFu, rs1, 1);
            rs1 += __shfl_xor_sync(0xFFFFFFFFu, rs1, 2);
            lstate[mt][0] = lstate[mt][0]*corr0 + rs0;
            lstate[mt][1] = lstate[mt][1]*corr1 + rs1;
            #pragma unroll
            for (int nt=0; nt<2; nt++) {
                oacc[mt][nt][0] *= corr0; oacc[mt][nt][1] *= corr0;
                oacc[mt][nt][2] *= corr1; oacc[mt][nt][3] *= corr1;
            }
            __syncwarp();
            #pragma unroll
            for (int ks=0; ks<4; ks++) {
                uint32_t a[4];
                a[0] = *(const uint32_t*)(Ps + qr*PSH + ks*16 + 2*qc);
                a[1] = *(const uint32_t*)(Ps + (qr+8)*PSH + ks*16 + 2*qc);
                a[2] = *(const uint32_t*)(Ps + qr*PSH + ks*16 + 2*qc + 8);
                a[3] = *(const uint32_t*)(Ps + (qr+8)*PSH + ks*16 + 2*qc + 8);
                #pragma unroll
                for (int nt=0; nt<2; nt++) {
                    const __half* vb = Vs + (nt*8+qr)*VSH + kb + ks*16;
                    uint32_t b0 = *(const uint32_t*)(vb + 2*qc);
                    uint32_t b1 = *(const uint32_t*)(vb + 2*qc + 8);
                    MMA_F16(oacc[mt][nt], a, b0, b1);
                }
            }
            __syncwarp();
        }
    }

    #pragma unroll
    for (int mt=0; mt<2; mt++) {
        float inv0 = 1.f/lstate[mt][0];
        float inv1 = 1.f/lstate[mt][1];
        int row0 = q0 + mt*16 + qr;
        #pragma unroll
        for (int nt=0; nt<2; nt++) {
            int col = h*HD + nt*8 + 2*qc;
            __half* o0 = ao + ((size_t)b*T_SEQ + row0)*D + col;
            __half* o1 = ao + ((size_t)b*T_SEQ + row0 + 8)*D + col;
            *(half2*)o0 = __floats2half2_rn(oacc[mt][nt][0]*inv0, oacc[mt][nt][1]*inv0);
            *(half2*)o1 = __floats2half2_rn(oacc[mt][nt][2]*inv1, oacc[mt][nt][3]*inv1);
        }
    }
}

// ---------------- cross-attention (folded): xo += softmax(h@K'^T/32) @ V' -------
__global__ __launch_bounds__(256) void cross_attn_kernel(
    const float* __restrict__ Q, const float* __restrict__ Km,
    const float* __restrict__ Vm, float* __restrict__ xo)
{
    extern __shared__ float csm[];
    float* Ks = csm;
    float* Vs = csm + NMEM*D;
    int b = blockIdx.x >> 2;
    int chunk = blockIdx.x & 3;
    for (int i=threadIdx.x; i<NMEM*D; i+=256) {
        Ks[i] = Km[(size_t)b*NMEM*D + i];
        Vs[i] = Vm[(size_t)b*NMEM*D + i];
    }
    __syncthreads();
    int t = chunk*256 + threadIdx.x;
    const float4* qrow = (const float4*)(Q + ((size_t)b*T_SEQ + t)*D);
    float s[16];
    #pragma unroll
    for (int mm=0;mm<16;mm++) s[mm]=0.f;
    for (int k4=0;k4<D/4;k4++) {
        float4 qv = qrow[k4];
        #pragma unroll
        for (int mm=0;mm<16;mm++) {
            const float* kr = Ks + mm*D + k4*4;
            s[mm] += qv.x*kr[0] + qv.y*kr[1] + qv.z*kr[2] + qv.w*kr[3];
        }
    }
    float mx = -1e30f;
    #pragma unroll
    for (int mm=0;mm<16;mm++) { s[mm] *= 0.03125f; mx = fmaxf(mx, s[mm]); }
    float sum = 0.f;
    #pragma unroll
    for (int mm=0;mm<16;mm++) { s[mm] = __expf(s[mm]-mx); sum += s[mm]; }
    float inv = 1.f/sum;
    #pragma unroll
    for (int mm=0;mm<16;mm++) s[mm] *= inv;
    float* xrow = xo + ((size_t)b*T_SEQ + t)*D;
    for (int c=0;c<D;c+=4) {
        float4 o = *(const float4*)(xrow + c);
        #pragma unroll
        for (int mm=0;mm<16;mm++) {
            const float* vr = Vs + mm*D + c;
            o.x += s[mm]*vr[0]; o.y += s[mm]*vr[1];
            o.z += s[mm]*vr[2]; o.w += s[mm]*vr[3];
        }
        *(float4*)(xrow + c) = o;
    }
}

// ---------------- memory path -------------------------------------------------
__global__ __launch_bounds__(256) void mean_kernel(const float* __restrict__ x,
                                                   float* __restrict__ mh) {
    __shared__ float sred[256];
    int b = blockIdx.x, cb = blockIdx.y*128;
    int c = threadIdx.x & 127, half = threadIdx.x >> 7;
    const float* p = x + (size_t)b*T_SEQ*D + (size_t)half*512*D + cb + c;
    float s = 0.f;
    #pragma unroll 4
    for (int t=0;t<512;t++) s += p[(size_t)t*D];
    sred[threadIdx.x] = s;
    __syncthreads();
    if (half == 0)
        mh[b*D + cb + c] = (sred[threadIdx.x] + sred[threadIdx.x+128]) * (1.f/T_SEQ);
}

__global__ __launch_bounds__(256) void base_gemv(
    const float* __restrict__ Wz, const float* __restrict__ Wr, const float* __restrict__ Wc,
    const float* __restrict__ bz, const float* __restrict__ br, const float* __restrict__ bc)
{
    int gid = blockIdx.x*8 + (threadIdx.x >> 5);
    int lane = threadIdx.x & 31;
    int g = gid >> 12;
    int rem = gid & 4095;
    int b = rem >> 10;
    int col = rem & 1023;
    const float* W    = (g==0) ? Wz : ((g==1) ? Wr : Wc);
    const float* bias = (g==0) ? bz : ((g==1) ? br : bc);
    const float* wrow = W + (size_t)col*2048;
    const float* mrow = g_meanh + b*D;
    float acc = 0.f;
    #pragma unroll
    for (int k0=0;k0<1024;k0+=128) {
        float4 w = *(const float4*)(wrow + k0 + lane*4);
        float4 m = *(const float4*)(mrow + k0 + lane*4);
        acc += w.x*m.x + w.y*m.y + w.z*m.z + w.w*m.w;
    }
    #pragma unroll
    for (int o=16;o;o>>=1) acc += __shfl_xor_sync(0xFFFFFFFFu, acc, o);
    if (lane == 0) g_base[gid] = acc + bias[col];
}

__device__ __forceinline__ void tile64x64(
    const float* __restrict__ A, const float* __restrict__ B, int ldb,
    float (&acc)[4][4])
{
    __shared__ float As[32][65];
    __shared__ float Bs[32][65];
    const int tid = threadIdx.x;
    const int r  = tid >> 2;
    const int kq = (tid & 3) << 3;
    const int tx = tid & 15;
    const int ty = tid >> 4;
    for (int k0 = 0; k0 < 1024; k0 += 32) {
        float4 a0 = *(const float4*)(A + (size_t)r*1024 + k0 + kq);
        float4 a1 = *(const float4*)(A + (size_t)r*1024 + k0 + kq + 4);
        float4 b0 = *(const float4*)(B + (size_t)r*ldb  + k0 + kq);
        float4 b1 = *(const float4*)(B + (size_t)r*ldb  + k0 + kq + 4);
        __syncthreads();
        As[kq+0][r]=a0.x; As[kq+1][r]=a0.y; As[kq+2][r]=a0.z; As[kq+3][r]=a0.w;
        As[kq+4][r]=a1.x; As[kq+5][r]=a1.y; As[kq+6][r]=a1.z; As[kq+7][r]=a1.w;
        Bs[kq+0][r]=b0.x; Bs[kq+1][r]=b0.y; Bs[kq+2][r]=b0.z; Bs[kq+3][r]=b0.w;
        Bs[kq+4][r]=b1.x; Bs[kq+5][r]=b1.y; Bs[kq+6][r]=b1.z; Bs[kq+7][r]=b1.w;
        __syncthreads();
        #pragma unroll
        for (int kk=0;kk<32;kk++) {
            float a[4], b[4];
            #pragma unroll
            for (int i=0;i<4;i++) a[i] = As[kk][ty*4+i];
            #pragma unroll
            for (int j=0;j<4;j++) b[j] = Bs[kk][tx*4+j];
            #pragma unroll
            for (int i=0;i<4;i++)
                #pragma unroll
                for (int j=0;j<4;j++) acc[i][j] += a[i]*b[j];
        }
    }
}

__global__ __launch_bounds__(256) void zr_pre(
    const float* __restrict__ mem, const float* __restrict__ Wz,
    const float* __restrict__ Wr)
{
    int g = blockIdx.y;
    int ct = blockIdx.x;
    const float* W = (g ? Wr : Wz) + (size_t)(ct*64)*2048 + 1024;
    float acc[4][4];
    #pragma unroll
    for (int i=0;i<4;i++)
        #pragma unroll
        for (int j=0;j<4;j++) acc[i][j]=0.f;
    tile64x64(mem, W, 2048, acc);
    float* out = g ? g_rpre : g_zpre;
    const int tx = threadIdx.x & 15, ty = threadIdx.x >> 4;
    #pragma unroll
    for (int i=0;i<4;i++) {
        int row = ty*4+i;
        #pragma unroll
        for (int j=0;j<4;j++) out[row*1024 + ct*64 + tx*4+j] = acc[i][j];
    }
}

__global__ void combine_kernel(const float* __restrict__ mem) {
    int idx = blockIdx.x*blockDim.x + threadIdx.x;
    int row = idx >> 10, col = idx & 1023, b = row >> 4;
    float z = 1.f/(1.f + __expf(-(g_zpre[idx] + g_base[0*4096 + b*1024 + col])));
    float r = 1.f/(1.f + __expf(-(g_rpre[idx] + g_base[1*4096 + b*1024 + col])));
    g_z[idx] = z;
    g_rm[idx] = r * mem[idx];
}

__global__ __launch_bounds__(256) void c_gemm(
    const float* __restrict__ mem, const float* __restrict__ Wc,
    float* __restrict__ newmem)
{
    int ct = blockIdx.x;
    const float* W = Wc + (size_t)(ct*64)*2048 + 1024;
    float acc[4][4];
    #pragma unroll
    for (int i=0;i<4;i++)
        #pragma unroll
        for (int j=0;j<4;j++) acc[i][j]=0.f;
    tile64x64(g_rm, W, 2048, acc);
    const int tx = threadIdx.x & 15, ty = threadIdx.x >> 4;
    #pragma unroll
    for (int i=0;i<4;i++) {
        int row = ty*4+i;
        #pragma unroll
        for (int j=0;j<4;j++) {
            int col = ct*64 + tx*4+j;
            float v = acc[i][j] + g_base[2*4096 + (row>>4)*1024 + col];
            float c = tanhf(v);
            float z = g_z[row*1024+col];
            newmem[(size_t)row*1024+col] = (1.f - z)*mem[(size_t)row*1024+col] + z*c;
        }
    }
}

__global__ __launch_bounds__(256) void kv2_gemm(const float* __restrict__ newmem)
{
    int which = blockIdx.y;
    int ct = blockIdx.x;
    const float* W = (which ? g_wv : g_wk) + (size_t)(ct*64)*1024;
    float acc[4][4];
    #pragma unroll
    for (int i=0;i<4;i++)
        #pragma unroll
        for (int j=0;j<4;j++) acc[i][j]=0.f;
    tile64x64(newmem, W, 1024, acc);
    float* out = which ? g_V : g_K;
    const int tx = threadIdx.x & 15, ty = threadIdx.x >> 4;
    #pragma unroll
    for (int i=0;i<4;i++) {
        int row = ty*4+i;
        #pragma unroll
        for (int j=0;j<4;j++) {
            int col = ct*64 + tx*4+j;
            out[(size_t)row*1024+col] = acc[i][j];
        }
    }
}

// ---------------- host launcher -------------------------------------------------
extern "C" void kernel_launch(void* const* d_in, const int* in_sizes, int n_in,
                              void* d_out, int out_size)
{
    const float* x          = (const float*)d_in[0];
    const float* memory     = (const float*)d_in[1];
    const float* ln1_g      = (const float*)d_in[2];
    const float* ln1_b      = (const float*)d_in[3];
    const float* ln2_g      = (const float*)d_in[4];
    const float* ln2_b      = (const float*)d_in[5];
    const float* ln3_g      = (const float*)d_in[6];
    const float* ln3_b      = (const float*)d_in[7];
    const float* in_proj_w  = (const float*)d_in[8];
    const float* in_proj_b  = (const float*)d_in[9];
    const float* attn_out_w = (const float*)d_in[10];
    const float* attn_out_b = (const float*)d_in[11];
    const float* Wz_w       = (const float*)d_in[12];
    const float* Wz_b       = (const float*)d_in[13];
    const float* Wr_w       = (const float*)d_in[14];
    const float* Wr_b       = (const float*)d_in[15];
    const float* Wc_w       = (const float*)d_in[16];
    const float* Wc_b       = (const float*)d_in[17];
    const float* mq_w       = (const float*)d_in[18];
    const float* mk_w       = (const float*)d_in[19];
    const float* mv_w       = (const float*)d_in[20];
    const float* mo_w       = (const float*)d_in[21];
    const float* W1         = (const float*)d_in[22];
    const float* b1         = (const float*)d_in[23];
    const float* W2         = (const float*)d_in[24];
    const float* b2         = (const float*)d_in[25];

    float* xo = (float*)d_out;
    float* newmem = xo + (size_t)ROWS*D;

    float *p_h, *p_K, *p_V, *p_w, *p_mh, *p_wk, *p_wv;
    __half *p_hh, *p_hqkv, *p_hao, *p_hffn, *p_hw;
    cudaGetSymbolAddress((void**)&p_h,    g_h);
    cudaGetSymbolAddress((void**)&p_K,    g_K);
    cudaGetSymbolAddress((void**)&p_V,    g_V);
    cudaGetSymbolAddress((void**)&p_w,    g_w);
    cudaGetSymbolAddress((void**)&p_mh,   g_meanh);
    cudaGetSymbolAddress((void**)&p_wk,   g_wk);
    cudaGetSymbolAddress((void**)&p_wv,   g_wv);
    cudaGetSymbolAddress((void**)&p_hh,   h_h);
    cudaGetSymbolAddress((void**)&p_hqkv, h_qkv);
    cudaGetSymbolAddress((void**)&p_hao,  h_ao);
    cudaGetSymbolAddress((void**)&p_hffn, h_ffn);
    cudaGetSymbolAddress((void**)&p_hw,   h_w);

    static cudaStream_t s2 = nullptr;
    static cudaEvent_t evStart = nullptr, evCvt = nullptr, evFork = nullptr, evMem = nullptr;
    static bool tried = false, ok = false;
    if (!tried) {
        tried = true;
        ok = (cudaStreamCreateWithFlags(&s2, cudaStreamNonBlocking) == cudaSuccess) &&
             (cudaEventCreateWithFlags(&evStart, cudaEventDisableTiming) == cudaSuccess) &&
             (cudaEventCreateWithFlags(&evCvt,   cudaEventDisableTiming) == cudaSuccess) &&
             (cudaEventCreateWithFlags(&evFork,  cudaEventDisableTiming) == cudaSuccess) &&
             (cudaEventCreateWithFlags(&evMem,   cudaEventDisableTiming) == cudaSuccess);
    }
    cudaStream_t sb = ok ? s2 : (cudaStream_t)0;

    cudaFuncSetAttribute(flash_attn_kernel, cudaFuncAttributeMaxDynamicSharedMemorySize, FLASH_SMEM);
    cudaFuncSetAttribute(cross_attn_kernel, cudaFuncAttributeMaxDynamicSharedMemorySize, 131072);
    const int GSM = SMEM_FLOATS * 4;
    cudaFuncSetAttribute(gemm_tf32<0,0,0,0>, cudaFuncAttributeMaxDynamicSharedMemorySize, GSM);
    cudaFuncSetAttribute(gemm_fp16<0,1,0,1>, cudaFuncAttributeMaxDynamicSharedMemorySize, HSMEM_BYTES);
    cudaFuncSetAttribute(gemm_fp16<0,1,1,0>, cudaFuncAttributeMaxDynamicSharedMemorySize, HSMEM_BYTES);
    cudaFuncSetAttribute(gemm_fp16<1,1,0,1>, cudaFuncAttributeMaxDynamicSharedMemorySize, HSMEM_BYTES);

    // ---- early hidden phase on sb ----
    if (ok) { cudaEventRecord(evStart, 0); cudaStreamWaitEvent(sb, evStart, 0); }
    cvt_fp16_kernel<<<3072, 256, 0, sb>>>(in_proj_w,  p_hw + HOFF_INP,  3*1024*1024/4);
    cvt_fp16_kernel<<<1024, 256, 0, sb>>>(attn_out_w, p_hw + HOFF_AOUT, 1024*1024/4);
    cvt_fp16_kernel<<<4096, 256, 0, sb>>>(W1,         p_hw + HOFF_W1,   4*1024*1024/4);
    cvt_fp16_kernel<<<4096, 256, 0, sb>>>(W2,         p_hw + HOFF_W2,   4*1024*1024/4);
    if (ok) cudaEventRecord(evCvt, sb);
    cvt_tf32_kernel<<<1024, 256, 0, sb>>>(mo_w, p_w + OFF_MO, 1024*1024/4);
    transpose_tf32<<<dim3(32,32), dim3(32,8), 0, sb>>>(mq_w, p_w + OFF_MQT);
    transpose_tf32<<<dim3(32,32), dim3(32,8), 0, sb>>>(mk_w, p_w + OFF_MKT);
    transpose_tf32<<<dim3(32,32), dim3(32,8), 0, sb>>>(mv_w, p_w + OFF_MVT);
    gemm_tf32<0,0,0,0><<<dim3(8,8), 256, GSM, sb>>>(p_w + OFF_MQT, p_w + OFF_MKT, nullptr, nullptr, p_wk, 1024, 1024, 1024);
    gemm_tf32<0,0,0,0><<<dim3(8,8), 256, GSM, sb>>>(p_w + OFF_MO,  p_w + OFF_MVT, nullptr, nullptr, p_wv, 1024, 1024, 1024);
    zr_pre<<<dim3(16,2), 256, 0, sb>>>(memory, Wz_w, Wr_w);

    // ---- main path ----
    ln_kernel_h<<<ROWS, 256>>>(x, ln1_g, ln1_b, p_hh);
    if (ok) cudaStreamWaitEvent(0, evCvt, 0);

    gemm_fp16<0,1,0,1><<<dim3(3*D/128, ROWS/128), 256, HSMEM_BYTES>>>(p_hh, p_hw + HOFF_INP, in_proj_b, nullptr, p_hqkv, ROWS, 3*D, D);
    flash_attn_kernel<<<dim3(BATCH*NHEADS, 4), 256, FLASH_SMEM>>>(p_hqkv, p_hao);
    gemm_fp16<0,1,1,0><<<dim3(D/128, ROWS/128), 256, HSMEM_BYTES>>>(p_hao, p_hw + HOFF_AOUT, attn_out_b, x, xo, ROWS, D, D);

    // ---- fork memory path onto sb ----
    if (ok) { cudaEventRecord(evFork, 0); cudaStreamWaitEvent(sb, evFork, 0); }
    mean_kernel<<<dim3(BATCH, 8), 256, 0, sb>>>(xo, p_mh);
    base_gemv<<<1536, 256, 0, sb>>>(Wz_w, Wr_w, Wc_w, Wz_b, Wr_b, Wc_b);
    combine_kernel<<<BATCH*NMEM*D/256, 256, 0, sb>>>(memory);
    c_gemm<<<16, 256, 0, sb>>>(memory, Wc_w, newmem);
    kv2_gemm<<<dim3(16, 2), 256, 0, sb>>>(newmem);
    if (ok) cudaEventRecord(evMem, sb);

    // ---- main path: LN2 (float), then folded cross-attention ----
    ln_kernel<<<ROWS, 256>>>(xo, ln2_g, ln2_b, p_h);
    if (ok) cudaStreamWaitEvent(0, evMem, 0);
    cross_attn_kernel<<<BATCH*4, 256, 131072>>>(p_h, p_K, p_V, xo);

    // FFN
    ln_kernel_h<<<ROWS, 256>>>(xo, ln3_g, ln3_b, p_hh);
    gemm_fp16<1,1,0,1><<<dim3(4*D/128, ROWS/128), 256, HSMEM_BYTES>>>(p_hh, p_hw + HOFF_W1, b1, nullptr, p_hffn, ROWS, 4*D, D);
    gemm_fp16<0,1,1,0><<<dim3(D/128, ROWS/128), 256, HSMEM_BYTES>>>(p_hffn, p_hw + HOFF_W2, b2, xo, xo, ROWS, D, 4*D);
}